// round 1
// baseline (speedup 1.0000x reference)
#include <cuda_runtime.h>
#include <cuda_bf16.h>
#include <math.h>

// ---------------------------------------------------------------------------
// Problem constants
// ---------------------------------------------------------------------------
#define Bq   8
#define Tq   1024
#define Dq   768
#define NEq  8
#define DSq  128
#define Hq   64
#define ROWS (Bq*Tq)            // 8192
#define SROWS (Bq*Tq*NEq)       // 65536

// Output layout (concatenated, float32, reference return order)
#define POOLED_OFF  0ll
#define MEM_OFF     6291456ll
#define STATE_OFF   56623104ll
#define HOLDER_OFF  65011712ll
#define TAGGED_OFF  65077248ll
#define VISIBLE_OFF 65142784ll
#define RW_OFF      65208320ll

// ---------------------------------------------------------------------------
// Scratch (device globals: allocation-free)
// ---------------------------------------------------------------------------
__device__ float g_proj[ROWS * DSq];          //  4.2 MB  projected [8192,128]
__device__ float g_Q[ROWS * 3 * DSq];         // 12.6 MB  Q = proj @ W_ih^T [8192,384]
__device__ float g_Mc[Dq * NEq * DSq];        //  3.1 MB  Mc [768,1024]
__device__ float g_WmT[DSq * Dq];             //  0.4 MB  Wm^T [128,768]
__device__ float g_hid0[SROWS * Hq];          // 16.8 MB  head hidden (pre-GELU)
__device__ float g_hid1[SROWS * Hq];
__device__ float g_hid2[SROWS * Hq];
__device__ float g_pbias[Dq];                 // pooled bias: bs + Ws @ tiled(bm)

// ---------------------------------------------------------------------------
// Generic fp32 GEMM:  C[m,n] = sum_k A[m*lda+k] * B[n*ldb+k] (+ bias[n])
// BM=BN=64, BK=16, 256 threads, 4x4 per thread. M,N,K multiples of 64/64/16.
// ---------------------------------------------------------------------------
#define BM 64
#define BN 64
#define BKq 16

__global__ __launch_bounds__(256)
void sgemm_tn(const float* __restrict__ A, int lda,
              const float* __restrict__ B, int ldb,
              float* __restrict__ C, int ldc, int cOff,
              const float* __restrict__ bias, int K)
{
    __shared__ float As[BKq * BM];
    __shared__ float Bs[BKq * BN];
    const int tid  = threadIdx.x;
    const int m0   = blockIdx.y * BM;
    const int n0   = blockIdx.x * BN;
    const int tRow = tid >> 2;       // 0..63
    const int tc4  = tid & 3;        // 0..3  (which float4 in the 16-wide k tile)
    const int tx   = tid & 15;       // n frag
    const int ty   = tid >> 4;       // m frag

    float acc[4][4];
#pragma unroll
    for (int i = 0; i < 4; i++)
#pragma unroll
        for (int j = 0; j < 4; j++) acc[i][j] = 0.f;

    for (int k0 = 0; k0 < K; k0 += BKq) {
        float4 a = *reinterpret_cast<const float4*>(A + (size_t)(m0 + tRow) * lda + k0 + tc4 * 4);
        float4 b = *reinterpret_cast<const float4*>(B + (size_t)(n0 + tRow) * ldb + k0 + tc4 * 4);
        As[(tc4 * 4 + 0) * BM + tRow] = a.x;
        As[(tc4 * 4 + 1) * BM + tRow] = a.y;
        As[(tc4 * 4 + 2) * BM + tRow] = a.z;
        As[(tc4 * 4 + 3) * BM + tRow] = a.w;
        Bs[(tc4 * 4 + 0) * BN + tRow] = b.x;
        Bs[(tc4 * 4 + 1) * BN + tRow] = b.y;
        Bs[(tc4 * 4 + 2) * BN + tRow] = b.z;
        Bs[(tc4 * 4 + 3) * BN + tRow] = b.w;
        __syncthreads();
#pragma unroll
        for (int k = 0; k < BKq; k++) {
            float4 av = *reinterpret_cast<const float4*>(&As[k * BM + ty * 4]);
            float4 bv = *reinterpret_cast<const float4*>(&Bs[k * BN + tx * 4]);
            acc[0][0] = fmaf(av.x, bv.x, acc[0][0]);
            acc[0][1] = fmaf(av.x, bv.y, acc[0][1]);
            acc[0][2] = fmaf(av.x, bv.z, acc[0][2]);
            acc[0][3] = fmaf(av.x, bv.w, acc[0][3]);
            acc[1][0] = fmaf(av.y, bv.x, acc[1][0]);
            acc[1][1] = fmaf(av.y, bv.y, acc[1][1]);
            acc[1][2] = fmaf(av.y, bv.z, acc[1][2]);
            acc[1][3] = fmaf(av.y, bv.w, acc[1][3]);
            acc[2][0] = fmaf(av.z, bv.x, acc[2][0]);
            acc[2][1] = fmaf(av.z, bv.y, acc[2][1]);
            acc[2][2] = fmaf(av.z, bv.z, acc[2][2]);
            acc[2][3] = fmaf(av.z, bv.w, acc[2][3]);
            acc[3][0] = fmaf(av.w, bv.x, acc[3][0]);
            acc[3][1] = fmaf(av.w, bv.y, acc[3][1]);
            acc[3][2] = fmaf(av.w, bv.z, acc[3][2]);
            acc[3][3] = fmaf(av.w, bv.w, acc[3][3]);
        }
        __syncthreads();
    }

    float4 bv;
    if (bias) {
        bv = *reinterpret_cast<const float4*>(bias + n0 + tx * 4);
    } else {
        bv.x = bv.y = bv.z = bv.w = 0.f;
    }
#pragma unroll
    for (int i = 0; i < 4; i++) {
        float4 o;
        o.x = acc[i][0] + bv.x;
        o.y = acc[i][1] + bv.y;
        o.z = acc[i][2] + bv.z;
        o.w = acc[i][3] + bv.w;
        *reinterpret_cast<float4*>(C + (size_t)(m0 + ty * 4 + i) * ldc + cOff + n0 + tx * 4) = o;
    }
}

// ---------------------------------------------------------------------------
// Route: logits[b,t,e] = dot(h_seq[b,t], ek[e]) / (sqrt(D)*temp); softmax over e
// One block per (b,t) row; one warp per entity.
// ---------------------------------------------------------------------------
__global__ __launch_bounds__(256)
void route_kernel(const float* __restrict__ h_seq,
                  const float* __restrict__ ek,
                  float* __restrict__ rw)
{
    const int row  = blockIdx.x;
    const int w    = threadIdx.x >> 5;
    const int lane = threadIdx.x & 31;
    const float* hr = h_seq + (size_t)row * Dq;
    const float* er = ek + (size_t)w * Dq;
    float s = 0.f;
#pragma unroll 4
    for (int k = lane; k < Dq; k += 32) s = fmaf(hr[k], er[k], s);
#pragma unroll
    for (int o = 16; o; o >>= 1) s += __shfl_xor_sync(0xffffffffu, s, o);
    __shared__ float lg[NEq];
    if (lane == 0) lg[w] = s;
    __syncthreads();
    if (threadIdx.x == 0) {
        const float inv = 0.036084391824351615f; // 1/(sqrt(768)*1.0)
        float v[NEq], m = -1e30f;
#pragma unroll
        for (int e = 0; e < NEq; e++) { v[e] = lg[e] * inv; m = fmaxf(m, v[e]); }
        float den = 0.f;
#pragma unroll
        for (int e = 0; e < NEq; e++) { v[e] = __expf(v[e] - m); den += v[e]; }
        float id = 1.f / den;
#pragma unroll
        for (int e = 0; e < NEq; e++) rw[(size_t)row * NEq + e] = v[e] * id;
    }
}

// ---------------------------------------------------------------------------
// Wm^T  (Wm [768,128] -> WmT [128,768])
// ---------------------------------------------------------------------------
__global__ void transpose_wm(const float* __restrict__ Wm, float* __restrict__ WmT)
{
    int idx = blockIdx.x * 256 + threadIdx.x;
    if (idx < Dq * DSq) {
        int j = idx / DSq, n = idx % DSq;
        WmT[(size_t)n * Dq + j] = Wm[idx];
    }
}

// ---------------------------------------------------------------------------
// pooled bias: pb[d] = bs[d] + sum_{e,d'} bm[d'] * Ws[d, e*768+d']
// ---------------------------------------------------------------------------
__global__ __launch_bounds__(256)
void pbias_kernel(const float* __restrict__ Ws, const float* __restrict__ bm,
                  const float* __restrict__ bs, float* __restrict__ pb)
{
    int d = blockIdx.x, tid = threadIdx.x;
    float s = 0.f;
    for (int j = tid; j < NEq * Dq; j += 256) s = fmaf(bm[j % Dq], Ws[(size_t)d * (NEq * Dq) + j], s);
    __shared__ float red[256];
    red[tid] = s; __syncthreads();
    for (int o = 128; o; o >>= 1) { if (tid < o) red[tid] += red[tid + o]; __syncthreads(); }
    if (tid == 0) pb[d] = red[0] + bs[d];
}

// ---------------------------------------------------------------------------
// GRU scan: one block per (b,e) chain, 384 threads, W_hh rows in registers.
//   gh = h @ W_hh^T + b_hh  (phase 1, all 384 threads, 128 FMAs each)
//   gate update for 128 state dims (phase 2, threads 0..127)
// ---------------------------------------------------------------------------
__global__ __launch_bounds__(384, 1)
void gru_scan(const float* __restrict__ Q,       // [8192,384]
              const float* __restrict__ rw,      // [8192,8]
              const float* __restrict__ state0,  // [8,128]
              const float* __restrict__ W_hh,    // [384,128]
              const float* __restrict__ b_ih,    // [384]
              const float* __restrict__ b_hh,    // [384]
              float* __restrict__ state_out)     // [8192,8,128]
{
    const int b = blockIdx.x >> 3;
    const int e = blockIdx.x & 7;
    const int j = threadIdx.x;               // 0..383

    float4 w4[32];
    {
        const float4* wr = reinterpret_cast<const float4*>(W_hh + (size_t)j * DSq);
#pragma unroll
        for (int i = 0; i < 32; i++) w4[i] = wr[i];
    }
    __shared__ float4 h4[32];
    __shared__ float gh[3 * DSq];

    if (j < 32) h4[j] = reinterpret_cast<const float4*>(state0 + e * DSq)[j];
    const float bhh = b_hh[j];
    float bir = 0.f, biz = 0.f, bin = 0.f;
    if (j < DSq) { bir = b_ih[j]; biz = b_ih[DSq + j]; bin = b_ih[2 * DSq + j]; }
    __syncthreads();

    for (int t = 0; t < Tq; t++) {
        const int row = b * Tq + t;
        float qr = 0.f, qz = 0.f, qn = 0.f, rwv = 0.f;
        if (j < DSq) {
            const float* qp = Q + (size_t)row * (3 * DSq);
            qr = qp[j]; qz = qp[DSq + j]; qn = qp[2 * DSq + j];
            rwv = rw[(size_t)row * NEq + e];
        }
        // phase 1: gh[j] = W_hh[j,:] . h  + b_hh[j]
        float acc0 = bhh, acc1 = 0.f;
#pragma unroll
        for (int i = 0; i < 32; i += 2) {
            float4 hv0 = h4[i];
            float4 hv1 = h4[i + 1];
            acc0 = fmaf(w4[i].x, hv0.x, acc0);
            acc0 = fmaf(w4[i].y, hv0.y, acc0);
            acc0 = fmaf(w4[i].z, hv0.z, acc0);
            acc0 = fmaf(w4[i].w, hv0.w, acc0);
            acc1 = fmaf(w4[i + 1].x, hv1.x, acc1);
            acc1 = fmaf(w4[i + 1].y, hv1.y, acc1);
            acc1 = fmaf(w4[i + 1].z, hv1.z, acc1);
            acc1 = fmaf(w4[i + 1].w, hv1.w, acc1);
        }
        gh[j] = acc0 + acc1;
        __syncthreads();
        // phase 2: gate update
        if (j < DSq) {
            float gir = fmaf(rwv, qr, bir);
            float giz = fmaf(rwv, qz, biz);
            float gin = fmaf(rwv, qn, bin);
            float r = 1.f / (1.f + __expf(-(gir + gh[j])));
            float z = 1.f / (1.f + __expf(-(giz + gh[DSq + j])));
            float n = tanhf(fmaf(r, gh[2 * DSq + j], gin));
            float hold = reinterpret_cast<float*>(h4)[j];
            float hnew = fmaf(z, hold - n, n);      // (1-z)*n + z*h
            reinterpret_cast<float*>(h4)[j] = hnew;
            state_out[(((size_t)row) * NEq + e) * DSq + j] = hnew;
        }
        __syncthreads();
    }
}

// ---------------------------------------------------------------------------
// Heads final: out[r] = b2 + sum_h gelu(hidden[r,h]) * W2[h]   (exact GELU)
// ---------------------------------------------------------------------------
__device__ __forceinline__ float gelu_exact(float x)
{
    return 0.5f * x * (1.0f + erff(x * 0.70710678118654752f));
}

__global__ __launch_bounds__(256)
void heads_final(const float* __restrict__ h0, const float* __restrict__ h1,
                 const float* __restrict__ h2,
                 const float* __restrict__ W2a, const float* __restrict__ b2a,
                 const float* __restrict__ W2b, const float* __restrict__ b2b,
                 const float* __restrict__ W2c, const float* __restrict__ b2c,
                 float* __restrict__ oA, float* __restrict__ oB, float* __restrict__ oC)
{
    __shared__ float w2[3][Hq];
    int tid = threadIdx.x;
    if (tid < Hq) { w2[0][tid] = W2a[tid]; w2[1][tid] = W2b[tid]; w2[2][tid] = W2c[tid]; }
    __syncthreads();
    size_t r = (size_t)blockIdx.x * 256 + tid;

    const float* hp[3] = { h0, h1, h2 };
    float bb[3] = { b2a[0], b2b[0], b2c[0] };
    float* op[3] = { oA, oB, oC };
#pragma unroll
    for (int p = 0; p < 3; p++) {
        const float4* hr = reinterpret_cast<const float4*>(hp[p] + r * Hq);
        float s = bb[p];
#pragma unroll
        for (int i = 0; i < Hq / 4; i++) {
            float4 x = hr[i];
            s = fmaf(gelu_exact(x.x), w2[p][i * 4 + 0], s);
            s = fmaf(gelu_exact(x.y), w2[p][i * 4 + 1], s);
            s = fmaf(gelu_exact(x.z), w2[p][i * 4 + 2], s);
            s = fmaf(gelu_exact(x.w), w2[p][i * 4 + 3], s);
        }
        op[p][r] = s;
    }
}

// ---------------------------------------------------------------------------
// Launch
// ---------------------------------------------------------------------------
extern "C" void kernel_launch(void* const* d_in, const int* in_sizes, int n_in,
                              void* d_out, int out_size)
{
    const float* h_seq = (const float*)d_in[0];
    const float* ek    = (const float*)d_in[1];
    const float* state0= (const float*)d_in[2];
    const float* Wi    = (const float*)d_in[3];
    const float* bi    = (const float*)d_in[4];
    const float* W_ih  = (const float*)d_in[5];
    const float* W_hh  = (const float*)d_in[6];
    const float* b_ih  = (const float*)d_in[7];
    const float* b_hh  = (const float*)d_in[8];
    const float* Wm    = (const float*)d_in[9];
    const float* bm    = (const float*)d_in[10];
    const float* Ws    = (const float*)d_in[11];
    const float* bs    = (const float*)d_in[12];
    const float* Wh1   = (const float*)d_in[13];
    const float* bh1   = (const float*)d_in[14];
    const float* Wh2   = (const float*)d_in[15];
    const float* bh2   = (const float*)d_in[16];
    const float* Wt1   = (const float*)d_in[17];
    const float* bt1   = (const float*)d_in[18];
    const float* Wt2   = (const float*)d_in[19];
    const float* bt2   = (const float*)d_in[20];
    const float* Wv1   = (const float*)d_in[21];
    const float* bv1   = (const float*)d_in[22];
    const float* Wv2   = (const float*)d_in[23];
    const float* bv2   = (const float*)d_in[24];
    float* out = (float*)d_out;

    float *p_proj, *p_Q, *p_Mc, *p_WmT, *p_h0, *p_h1, *p_h2, *p_pb;
    cudaGetSymbolAddress((void**)&p_proj, g_proj);
    cudaGetSymbolAddress((void**)&p_Q,    g_Q);
    cudaGetSymbolAddress((void**)&p_Mc,   g_Mc);
    cudaGetSymbolAddress((void**)&p_WmT,  g_WmT);
    cudaGetSymbolAddress((void**)&p_h0,   g_hid0);
    cudaGetSymbolAddress((void**)&p_h1,   g_hid1);
    cudaGetSymbolAddress((void**)&p_h2,   g_hid2);
    cudaGetSymbolAddress((void**)&p_pb,   g_pbias);

    // 1. routing softmax -> route_weights (output)
    route_kernel<<<ROWS, 256>>>(h_seq, ek, out + RW_OFF);

    // 2. projected = h_seq @ Wi^T + bi          [8192,128]
    sgemm_tn<<<dim3(DSq / BN, ROWS / BM), 256>>>(h_seq, Dq, Wi, Dq, p_proj, DSq, 0, bi, Dq);

    // 3. Q = projected @ W_ih^T                 [8192,384]  (bias folded in scan)
    sgemm_tn<<<dim3(3 * DSq / BN, ROWS / BM), 256>>>(p_proj, DSq, W_ih, DSq, p_Q, 3 * DSq, 0, nullptr, DSq);

    // 4. Mc[d, e*128+k] = (Ws_e @ Wm)[d,k]      [768,1024]
    transpose_wm<<<(Dq * DSq + 255) / 256, 256>>>(Wm, p_WmT);
    for (int e = 0; e < NEq; e++)
        sgemm_tn<<<dim3(DSq / BN, Dq / BM), 256>>>(Ws + e * Dq, NEq * Dq, p_WmT, Dq,
                                                   p_Mc, NEq * DSq, e * DSq, nullptr, Dq);
    pbias_kernel<<<Dq, 256>>>(Ws, bm, bs, p_pb);

    // 5. GRU scan -> state_stack (output)
    gru_scan<<<Bq * NEq, 384>>>(p_Q, out + RW_OFF, state0, W_hh, b_ih, b_hh, out + STATE_OFF);

    // 6. memory_stack = state @ Wm^T + bm       [65536,768] (output)
    sgemm_tn<<<dim3(Dq / BN, SROWS / BM), 256>>>(out + STATE_OFF, DSq, Wm, DSq,
                                                 out + MEM_OFF, Dq, 0, bm, DSq);

    // 7. pooled = state_flat @ Mc^T + pbias     [8192,768] (output)
    sgemm_tn<<<dim3(Dq / BN, ROWS / BM), 256>>>(out + STATE_OFF, NEq * DSq, p_Mc, NEq * DSq,
                                                out + POOLED_OFF, Dq, 0, p_pb, NEq * DSq);

    // 8. head hidden layers (pre-GELU)          [65536,64] x3
    sgemm_tn<<<dim3(Hq / BN, SROWS / BM), 256>>>(out + STATE_OFF, DSq, Wh1, DSq, p_h0, Hq, 0, bh1, DSq);
    sgemm_tn<<<dim3(Hq / BN, SROWS / BM), 256>>>(out + STATE_OFF, DSq, Wt1, DSq, p_h1, Hq, 0, bt1, DSq);
    sgemm_tn<<<dim3(Hq / BN, SROWS / BM), 256>>>(out + STATE_OFF, DSq, Wv1, DSq, p_h2, Hq, 0, bv1, DSq);

    // 9. heads final: gelu + dot(64) + bias -> holder/tagged/visible (outputs)
    heads_final<<<SROWS / 256, 256>>>(p_h0, p_h1, p_h2, Wh2, bh2, Wt2, bt2, Wv2, bv2,
                                      out + HOLDER_OFF, out + TAGGED_OFF, out + VISIBLE_OFF);

    (void)in_sizes; (void)n_in; (void)out_size;
}

// round 2
// speedup vs baseline: 1.0690x; 1.0690x over previous
#include <cuda_runtime.h>
#include <cuda_bf16.h>
#include <math.h>

// ---------------------------------------------------------------------------
// Problem constants
// ---------------------------------------------------------------------------
#define Bq   8
#define Tq   1024
#define Dq   768
#define NEq  8
#define DSq  128
#define Hq   64
#define ROWS (Bq*Tq)            // 8192
#define SROWS (Bq*Tq*NEq)       // 65536

// Output layout (concatenated, float32, reference return order)
#define POOLED_OFF  0ll
#define MEM_OFF     6291456ll
#define STATE_OFF   56623104ll
#define HOLDER_OFF  65011712ll
#define TAGGED_OFF  65077248ll
#define VISIBLE_OFF 65142784ll
#define RW_OFF      65208320ll

// ---------------------------------------------------------------------------
// Scratch (device globals: allocation-free)
// ---------------------------------------------------------------------------
__device__ float g_proj[ROWS * DSq];          //  4.2 MB  projected [8192,128]
__device__ float g_Q[ROWS * 3 * DSq];         // 12.6 MB  Q = proj @ W_ih^T [8192,384]
__device__ float g_Mc[Dq * NEq * DSq];        //  3.1 MB  Mc [768,1024]
__device__ float g_WmT[DSq * Dq];             //  0.4 MB  Wm^T [128,768]
__device__ float g_hid0[SROWS * Hq];          // 16.8 MB  head hidden (pre-GELU)
__device__ float g_hid1[SROWS * Hq];
__device__ float g_hid2[SROWS * Hq];
__device__ float g_pbias[Dq];                 // pooled bias: bs + Ws @ tiled(bm)

// ---------------------------------------------------------------------------
// Generic fp32 GEMM:  C[m,n] = sum_k A[m*lda+k] * B[n*ldb+k] (+ bias[n])
// BM=BN=64, BK=16, 256 threads, 4x4 per thread. M,N,K multiples of 64/64/16.
// ---------------------------------------------------------------------------
#define BM 64
#define BN 64
#define BKq 16

__global__ __launch_bounds__(256)
void sgemm_tn(const float* __restrict__ A, int lda,
              const float* __restrict__ B, int ldb,
              float* __restrict__ C, int ldc, int cOff,
              const float* __restrict__ bias, int K)
{
    __shared__ float As[BKq * BM];
    __shared__ float Bs[BKq * BN];
    const int tid  = threadIdx.x;
    const int m0   = blockIdx.y * BM;
    const int n0   = blockIdx.x * BN;
    const int tRow = tid >> 2;       // 0..63
    const int tc4  = tid & 3;        // 0..3  (which float4 in the 16-wide k tile)
    const int tx   = tid & 15;       // n frag
    const int ty   = tid >> 4;       // m frag

    float acc[4][4];
#pragma unroll
    for (int i = 0; i < 4; i++)
#pragma unroll
        for (int j = 0; j < 4; j++) acc[i][j] = 0.f;

    for (int k0 = 0; k0 < K; k0 += BKq) {
        float4 a = *reinterpret_cast<const float4*>(A + (size_t)(m0 + tRow) * lda + k0 + tc4 * 4);
        float4 b = *reinterpret_cast<const float4*>(B + (size_t)(n0 + tRow) * ldb + k0 + tc4 * 4);
        As[(tc4 * 4 + 0) * BM + tRow] = a.x;
        As[(tc4 * 4 + 1) * BM + tRow] = a.y;
        As[(tc4 * 4 + 2) * BM + tRow] = a.z;
        As[(tc4 * 4 + 3) * BM + tRow] = a.w;
        Bs[(tc4 * 4 + 0) * BN + tRow] = b.x;
        Bs[(tc4 * 4 + 1) * BN + tRow] = b.y;
        Bs[(tc4 * 4 + 2) * BN + tRow] = b.z;
        Bs[(tc4 * 4 + 3) * BN + tRow] = b.w;
        __syncthreads();
#pragma unroll
        for (int k = 0; k < BKq; k++) {
            float4 av = *reinterpret_cast<const float4*>(&As[k * BM + ty * 4]);
            float4 bv = *reinterpret_cast<const float4*>(&Bs[k * BN + tx * 4]);
            acc[0][0] = fmaf(av.x, bv.x, acc[0][0]);
            acc[0][1] = fmaf(av.x, bv.y, acc[0][1]);
            acc[0][2] = fmaf(av.x, bv.z, acc[0][2]);
            acc[0][3] = fmaf(av.x, bv.w, acc[0][3]);
            acc[1][0] = fmaf(av.y, bv.x, acc[1][0]);
            acc[1][1] = fmaf(av.y, bv.y, acc[1][1]);
            acc[1][2] = fmaf(av.y, bv.z, acc[1][2]);
            acc[1][3] = fmaf(av.y, bv.w, acc[1][3]);
            acc[2][0] = fmaf(av.z, bv.x, acc[2][0]);
            acc[2][1] = fmaf(av.z, bv.y, acc[2][1]);
            acc[2][2] = fmaf(av.z, bv.z, acc[2][2]);
            acc[2][3] = fmaf(av.z, bv.w, acc[2][3]);
            acc[3][0] = fmaf(av.w, bv.x, acc[3][0]);
            acc[3][1] = fmaf(av.w, bv.y, acc[3][1]);
            acc[3][2] = fmaf(av.w, bv.z, acc[3][2]);
            acc[3][3] = fmaf(av.w, bv.w, acc[3][3]);
        }
        __syncthreads();
    }

    float4 bv;
    if (bias) {
        bv = *reinterpret_cast<const float4*>(bias + n0 + tx * 4);
    } else {
        bv.x = bv.y = bv.z = bv.w = 0.f;
    }
#pragma unroll
    for (int i = 0; i < 4; i++) {
        float4 o;
        o.x = acc[i][0] + bv.x;
        o.y = acc[i][1] + bv.y;
        o.z = acc[i][2] + bv.z;
        o.w = acc[i][3] + bv.w;
        *reinterpret_cast<float4*>(C + (size_t)(m0 + ty * 4 + i) * ldc + cOff + n0 + tx * 4) = o;
    }
}

// ---------------------------------------------------------------------------
// Route: logits[b,t,e] = dot(h_seq[b,t], ek[e]) / (sqrt(D)*temp); softmax over e
// One block per (b,t) row; one warp per entity.
// ---------------------------------------------------------------------------
__global__ __launch_bounds__(256)
void route_kernel(const float* __restrict__ h_seq,
                  const float* __restrict__ ek,
                  float* __restrict__ rw)
{
    const int row  = blockIdx.x;
    const int w    = threadIdx.x >> 5;
    const int lane = threadIdx.x & 31;
    const float* hr = h_seq + (size_t)row * Dq;
    const float* er = ek + (size_t)w * Dq;
    float s = 0.f;
#pragma unroll 4
    for (int k = lane; k < Dq; k += 32) s = fmaf(hr[k], er[k], s);
#pragma unroll
    for (int o = 16; o; o >>= 1) s += __shfl_xor_sync(0xffffffffu, s, o);
    __shared__ float lg[NEq];
    if (lane == 0) lg[w] = s;
    __syncthreads();
    if (threadIdx.x == 0) {
        const float inv = 0.036084391824351615f; // 1/(sqrt(768)*1.0)
        float v[NEq], m = -1e30f;
#pragma unroll
        for (int e = 0; e < NEq; e++) { v[e] = lg[e] * inv; m = fmaxf(m, v[e]); }
        float den = 0.f;
#pragma unroll
        for (int e = 0; e < NEq; e++) { v[e] = __expf(v[e] - m); den += v[e]; }
        float id = 1.f / den;
#pragma unroll
        for (int e = 0; e < NEq; e++) rw[(size_t)row * NEq + e] = v[e] * id;
    }
}

// ---------------------------------------------------------------------------
// Wm^T  (Wm [768,128] -> WmT [128,768])
// ---------------------------------------------------------------------------
__global__ void transpose_wm(const float* __restrict__ Wm, float* __restrict__ WmT)
{
    int idx = blockIdx.x * 256 + threadIdx.x;
    if (idx < Dq * DSq) {
        int j = idx / DSq, n = idx % DSq;
        WmT[(size_t)n * Dq + j] = Wm[idx];
    }
}

// ---------------------------------------------------------------------------
// pooled bias: pb[d] = bs[d] + sum_{e,d'} bm[d'] * Ws[d, e*768+d']
// ---------------------------------------------------------------------------
__global__ __launch_bounds__(256)
void pbias_kernel(const float* __restrict__ Ws, const float* __restrict__ bm,
                  const float* __restrict__ bs, float* __restrict__ pb)
{
    int d = blockIdx.x, tid = threadIdx.x;
    float s = 0.f;
    for (int j = tid; j < NEq * Dq; j += 256) s = fmaf(bm[j % Dq], Ws[(size_t)d * (NEq * Dq) + j], s);
    __shared__ float red[256];
    red[tid] = s; __syncthreads();
    for (int o = 128; o; o >>= 1) { if (tid < o) red[tid] += red[tid + o]; __syncthreads(); }
    if (tid == 0) pb[d] = red[0] + bs[d];
}

// ---------------------------------------------------------------------------
// GRU scan: one block per (b,e) chain, 384 threads, W_hh rows in registers.
//   gh = h @ W_hh^T + b_hh  (phase 1, all 384 threads, 128 FMAs each)
//   gate update for 128 state dims (phase 2, threads 0..127)
// ---------------------------------------------------------------------------
__global__ __launch_bounds__(384, 1)
void gru_scan(const float* __restrict__ Q,       // [8192,384]
              const float* __restrict__ rw,      // [8192,8]
              const float* __restrict__ state0,  // [8,128]
              const float* __restrict__ W_hh,    // [384,128]
              const float* __restrict__ b_ih,    // [384]
              const float* __restrict__ b_hh,    // [384]
              float* __restrict__ state_out)     // [8192,8,128]
{
    const int b = blockIdx.x >> 3;
    const int e = blockIdx.x & 7;
    const int j = threadIdx.x;               // 0..383

    float4 w4[32];
    {
        const float4* wr = reinterpret_cast<const float4*>(W_hh + (size_t)j * DSq);
#pragma unroll
        for (int i = 0; i < 32; i++) w4[i] = wr[i];
    }
    __shared__ float4 h4[32];
    __shared__ float gh[3 * DSq];

    if (j < 32) h4[j] = reinterpret_cast<const float4*>(state0 + e * DSq)[j];
    const float bhh = b_hh[j];
    float bir = 0.f, biz = 0.f, bin = 0.f;
    if (j < DSq) { bir = b_ih[j]; biz = b_ih[DSq + j]; bin = b_ih[2 * DSq + j]; }
    __syncthreads();

    for (int t = 0; t < Tq; t++) {
        const int row = b * Tq + t;
        float qr = 0.f, qz = 0.f, qn = 0.f, rwv = 0.f;
        if (j < DSq) {
            const float* qp = Q + (size_t)row * (3 * DSq);
            qr = qp[j]; qz = qp[DSq + j]; qn = qp[2 * DSq + j];
            rwv = rw[(size_t)row * NEq + e];
        }
        // phase 1: gh[j] = W_hh[j,:] . h  + b_hh[j]
        float acc0 = bhh, acc1 = 0.f;
#pragma unroll
        for (int i = 0; i < 32; i += 2) {
            float4 hv0 = h4[i];
            float4 hv1 = h4[i + 1];
            acc0 = fmaf(w4[i].x, hv0.x, acc0);
            acc0 = fmaf(w4[i].y, hv0.y, acc0);
            acc0 = fmaf(w4[i].z, hv0.z, acc0);
            acc0 = fmaf(w4[i].w, hv0.w, acc0);
            acc1 = fmaf(w4[i + 1].x, hv1.x, acc1);
            acc1 = fmaf(w4[i + 1].y, hv1.y, acc1);
            acc1 = fmaf(w4[i + 1].z, hv1.z, acc1);
            acc1 = fmaf(w4[i + 1].w, hv1.w, acc1);
        }
        gh[j] = acc0 + acc1;
        __syncthreads();
        // phase 2: gate update
        if (j < DSq) {
            float gir = fmaf(rwv, qr, bir);
            float giz = fmaf(rwv, qz, biz);
            float gin = fmaf(rwv, qn, bin);
            float r = 1.f / (1.f + __expf(-(gir + gh[j])));
            float z = 1.f / (1.f + __expf(-(giz + gh[DSq + j])));
            float n = tanhf(fmaf(r, gh[2 * DSq + j], gin));
            float hold = reinterpret_cast<float*>(h4)[j];
            float hnew = fmaf(z, hold - n, n);      // (1-z)*n + z*h
            reinterpret_cast<float*>(h4)[j] = hnew;
            state_out[(((size_t)row) * NEq + e) * DSq + j] = hnew;
        }
        __syncthreads();
    }
}

// ---------------------------------------------------------------------------
// Heads final: out[r] = b2 + sum_h gelu(hidden[r,h]) * W2[h]   (exact GELU)
// ---------------------------------------------------------------------------
__device__ __forceinline__ float gelu_exact(float x)
{
    return 0.5f * x * (1.0f + erff(x * 0.70710678118654752f));
}

__global__ __launch_bounds__(256)
void heads_final(const float* __restrict__ h0, const float* __restrict__ h1,
                 const float* __restrict__ h2,
                 const float* __restrict__ W2a, const float* __restrict__ b2a,
                 const float* __restrict__ W2b, const float* __restrict__ b2b,
                 const float* __restrict__ W2c, const float* __restrict__ b2c,
                 float* __restrict__ oA, float* __restrict__ oB, float* __restrict__ oC)
{
    __shared__ float w2[3][Hq];
    int tid = threadIdx.x;
    if (tid < Hq) { w2[0][tid] = W2a[tid]; w2[1][tid] = W2b[tid]; w2[2][tid] = W2c[tid]; }
    __syncthreads();
    size_t r = (size_t)blockIdx.x * 256 + tid;

    const float* hp[3] = { h0, h1, h2 };
    float bb[3] = { b2a[0], b2b[0], b2c[0] };
    float* op[3] = { oA, oB, oC };
#pragma unroll
    for (int p = 0; p < 3; p++) {
        const float4* hr = reinterpret_cast<const float4*>(hp[p] + r * Hq);
        float s = bb[p];
#pragma unroll
        for (int i = 0; i < Hq / 4; i++) {
            float4 x = hr[i];
            s = fmaf(gelu_exact(x.x), w2[p][i * 4 + 0], s);
            s = fmaf(gelu_exact(x.y), w2[p][i * 4 + 1], s);
            s = fmaf(gelu_exact(x.z), w2[p][i * 4 + 2], s);
            s = fmaf(gelu_exact(x.w), w2[p][i * 4 + 3], s);
        }
        op[p][r] = s;
    }
}

// ---------------------------------------------------------------------------
// Launch
// ---------------------------------------------------------------------------
extern "C" void kernel_launch(void* const* d_in, const int* in_sizes, int n_in,
                              void* d_out, int out_size)
{
    const float* h_seq = (const float*)d_in[0];
    const float* ek    = (const float*)d_in[1];
    const float* state0= (const float*)d_in[2];
    const float* Wi    = (const float*)d_in[3];
    const float* bi    = (const float*)d_in[4];
    const float* W_ih  = (const float*)d_in[5];
    const float* W_hh  = (const float*)d_in[6];
    const float* b_ih  = (const float*)d_in[7];
    const float* b_hh  = (const float*)d_in[8];
    const float* Wm    = (const float*)d_in[9];
    const float* bm    = (const float*)d_in[10];
    const float* Ws    = (const float*)d_in[11];
    const float* bs    = (const float*)d_in[12];
    const float* Wh1   = (const float*)d_in[13];
    const float* bh1   = (const float*)d_in[14];
    const float* Wh2   = (const float*)d_in[15];
    const float* bh2   = (const float*)d_in[16];
    const float* Wt1   = (const float*)d_in[17];
    const float* bt1   = (const float*)d_in[18];
    const float* Wt2   = (const float*)d_in[19];
    const float* bt2   = (const float*)d_in[20];
    const float* Wv1   = (const float*)d_in[21];
    const float* bv1   = (const float*)d_in[22];
    const float* Wv2   = (const float*)d_in[23];
    const float* bv2   = (const float*)d_in[24];
    float* out = (float*)d_out;

    float *p_proj, *p_Q, *p_Mc, *p_WmT, *p_h0, *p_h1, *p_h2, *p_pb;
    cudaGetSymbolAddress((void**)&p_proj, g_proj);
    cudaGetSymbolAddress((void**)&p_Q,    g_Q);
    cudaGetSymbolAddress((void**)&p_Mc,   g_Mc);
    cudaGetSymbolAddress((void**)&p_WmT,  g_WmT);
    cudaGetSymbolAddress((void**)&p_h0,   g_hid0);
    cudaGetSymbolAddress((void**)&p_h1,   g_hid1);
    cudaGetSymbolAddress((void**)&p_h2,   g_hid2);
    cudaGetSymbolAddress((void**)&p_pb,   g_pbias);

    // 1. routing softmax -> route_weights (output)
    route_kernel<<<ROWS, 256>>>(h_seq, ek, out + RW_OFF);

    // 2. projected = h_seq @ Wi^T + bi          [8192,128]
    sgemm_tn<<<dim3(DSq / BN, ROWS / BM), 256>>>(h_seq, Dq, Wi, Dq, p_proj, DSq, 0, bi, Dq);

    // 3. Q = projected @ W_ih^T                 [8192,384]  (bias folded in scan)
    sgemm_tn<<<dim3(3 * DSq / BN, ROWS / BM), 256>>>(p_proj, DSq, W_ih, DSq, p_Q, 3 * DSq, 0, nullptr, DSq);

    // 4. Mc[d, e*128+k] = (Ws_e @ Wm)[d,k]      [768,1024]
    transpose_wm<<<(Dq * DSq + 255) / 256, 256>>>(Wm, p_WmT);
    for (int e = 0; e < NEq; e++)
        sgemm_tn<<<dim3(DSq / BN, Dq / BM), 256>>>(Ws + e * Dq, NEq * Dq, p_WmT, Dq,
                                                   p_Mc, NEq * DSq, e * DSq, nullptr, Dq);
    pbias_kernel<<<Dq, 256>>>(Ws, bm, bs, p_pb);

    // 5. GRU scan -> state_stack (output)
    gru_scan<<<Bq * NEq, 384>>>(p_Q, out + RW_OFF, state0, W_hh, b_ih, b_hh, out + STATE_OFF);

    // 6. memory_stack = state @ Wm^T + bm       [65536,768] (output)
    sgemm_tn<<<dim3(Dq / BN, SROWS / BM), 256>>>(out + STATE_OFF, DSq, Wm, DSq,
                                                 out + MEM_OFF, Dq, 0, bm, DSq);

    // 7. pooled = state_flat @ Mc^T + pbias     [8192,768] (output)
    sgemm_tn<<<dim3(Dq / BN, ROWS / BM), 256>>>(out + STATE_OFF, NEq * DSq, p_Mc, NEq * DSq,
                                                out + POOLED_OFF, Dq, 0, p_pb, NEq * DSq);

    // 8. head hidden layers (pre-GELU)          [65536,64] x3
    sgemm_tn<<<dim3(Hq / BN, SROWS / BM), 256>>>(out + STATE_OFF, DSq, Wh1, DSq, p_h0, Hq, 0, bh1, DSq);
    sgemm_tn<<<dim3(Hq / BN, SROWS / BM), 256>>>(out + STATE_OFF, DSq, Wt1, DSq, p_h1, Hq, 0, bt1, DSq);
    sgemm_tn<<<dim3(Hq / BN, SROWS / BM), 256>>>(out + STATE_OFF, DSq, Wv1, DSq, p_h2, Hq, 0, bv1, DSq);

    // 9. heads final: gelu + dot(64) + bias -> holder/tagged/visible (outputs)
    heads_final<<<SROWS / 256, 256>>>(p_h0, p_h1, p_h2, Wh2, bh2, Wt2, bt2, Wv2, bv2,
                                      out + HOLDER_OFF, out + TAGGED_OFF, out + VISIBLE_OFF);

    (void)in_sizes; (void)n_in; (void)out_size;
}

// round 4
// speedup vs baseline: 1.5791x; 1.4771x over previous
#include <cuda_runtime.h>
#include <cuda_bf16.h>
#include <mma.h>
#include <math.h>
#include <stdint.h>

using namespace nvcuda;

#define Bq   8
#define Tq   1024
#define Dq   768
#define NEq  8
#define DSq  128
#define ROWS (Bq*Tq)            // 8192
#define SROWS (Bq*Tq*NEq)       // 65536

#define POOLED_OFF  0ll
#define MEM_OFF     6291456ll
#define STATE_OFF   56623104ll
#define HOLDER_OFF  65011712ll
#define TAGGED_OFF  65077248ll
#define VISIBLE_OFF 65142784ll
#define RW_OFF      65208320ll

// ---------------------------------------------------------------------------
// Scratch
// ---------------------------------------------------------------------------
__device__ __nv_bfloat16 g_hseq_hi[ROWS*Dq],    g_hseq_lo[ROWS*Dq];
__device__ __nv_bfloat16 g_state_hi[SROWS*DSq], g_state_lo[SROWS*DSq];
__device__ __nv_bfloat16 g_projh[ROWS*DSq],     g_projl[ROWS*DSq];
__device__ __nv_bfloat16 g_Ws_hi[Dq*NEq*Dq],    g_Ws_lo[Dq*NEq*Dq];
__device__ __nv_bfloat16 g_Wi_hi[DSq*Dq],       g_Wi_lo[DSq*Dq];
__device__ __nv_bfloat16 g_Wih_hi[3*DSq*DSq],   g_Wih_lo[3*DSq*DSq];
__device__ __nv_bfloat16 g_Wm_hi[Dq*DSq],       g_Wm_lo[Dq*DSq];
__device__ __nv_bfloat16 g_WmT_hi[DSq*Dq],      g_WmT_lo[DSq*Dq];
__device__ __nv_bfloat16 g_Mc_hi[Dq*NEq*DSq],   g_Mc_lo[Dq*NEq*DSq];
__device__ __nv_bfloat16 g_W1_hi[256*DSq],      g_W1_lo[256*DSq];
__device__ float g_proj[ROWS*DSq];
__device__ float g_Q[ROWS*3*DSq];
__device__ float g_Mc[Dq*NEq*DSq];
__device__ float g_pbias[Dq];
__device__ float g_b1cat[256];
__device__ float g_W2cat[256];

// ---------------------------------------------------------------------------
// f32x2 packed FMA (base ISA sm_100+, not 'a'-gated)
// ---------------------------------------------------------------------------
__device__ __forceinline__ unsigned long long fma_f32x2(unsigned long long a, unsigned long long b, unsigned long long c) {
    unsigned long long d;
    asm("fma.rn.f32x2 %0, %1, %2, %3;" : "=l"(d) : "l"(a), "l"(b), "l"(c));
    return d;
}
__device__ __forceinline__ float lo_f(unsigned long long v) { return __uint_as_float((uint32_t)v); }
__device__ __forceinline__ float hi_f(unsigned long long v) { return __uint_as_float((uint32_t)(v >> 32)); }

// ---------------------------------------------------------------------------
// WMMA split-bf16 GEMM: C[m,n] = sum_k A[m,k]*B[n,k] (+bias[n])
// block 128x128, BK=32, 8 warps (2x4), warp tile 64x32.
// smem: bf16 tiles padded to 40 cols; f32 C tile overlays afterwards.
// ---------------------------------------------------------------------------
#define BKT   32
#define LDSA  40
#define SM_AHI 0
#define SM_ALO 5120
#define SM_BHI 10240
#define SM_BLO 15360
#define SM_BYTES 65536

__device__ __forceinline__ void stage(__nv_bfloat16* s, const __nv_bfloat16* __restrict__ g,
                                      long long row0, int k0, int ld, int tid)
{
#pragma unroll
    for (int it = 0; it < 4; it++) {
        int flat = it * 256 + tid;            // 0..1023
        int row = flat >> 3;                  // 0..127
        int q   = flat & 7;                   // 0..7 (4 bf16 each)
        *reinterpret_cast<unsigned long long*>(s + row * LDSA + q * 4) =
            *reinterpret_cast<const unsigned long long*>(g + (row0 + row) * (long long)ld + k0 + q * 4);
    }
}

__global__ __launch_bounds__(256)
void gemm_tc(const __nv_bfloat16* __restrict__ Ahi, const __nv_bfloat16* __restrict__ Alo, int lda, int aK0z,
             const __nv_bfloat16* __restrict__ Bhi, const __nv_bfloat16* __restrict__ Blo, int ldb,
             float* __restrict__ C, int ldc, int cZoff,
             const float* __restrict__ bias, int nChunks)
{
    extern __shared__ __align__(16) char smem[];
    __nv_bfloat16* s16 = reinterpret_cast<__nv_bfloat16*>(smem);
    const int tid = threadIdx.x, wid = tid >> 5;
    const int wy = wid >> 2, wx = wid & 3;
    const long long m0 = (long long)blockIdx.y * 128;
    const int n0 = blockIdx.x * 128;
    const int aK0 = blockIdx.z * aK0z;
    const int cOff = n0 + blockIdx.z * cZoff;

    wmma::fragment<wmma::accumulator, 16, 16, 16, float> acc[4][2];
#pragma unroll
    for (int i = 0; i < 4; i++)
#pragma unroll
        for (int j = 0; j < 2; j++) wmma::fill_fragment(acc[i][j], 0.0f);

    for (int c = 0; c < nChunks; c++) {
        stage(s16 + SM_AHI, Ahi, m0, aK0 + c * BKT, lda, tid);
        stage(s16 + SM_ALO, Alo, m0, aK0 + c * BKT, lda, tid);
        stage(s16 + SM_BHI, Bhi, n0, c * BKT, ldb, tid);
        stage(s16 + SM_BLO, Blo, n0, c * BKT, ldb, tid);
        __syncthreads();
#pragma unroll
        for (int ks = 0; ks < BKT; ks += 16) {
            wmma::fragment<wmma::matrix_b, 16, 16, 16, __nv_bfloat16, wmma::col_major> bh[2], bl[2];
#pragma unroll
            for (int fn = 0; fn < 2; fn++) {
                const int nb = wx * 32 + fn * 16;
                wmma::load_matrix_sync(bh[fn], s16 + SM_BHI + nb * LDSA + ks, LDSA);
                wmma::load_matrix_sync(bl[fn], s16 + SM_BLO + nb * LDSA + ks, LDSA);
            }
#pragma unroll
            for (int fm = 0; fm < 4; fm++) {
                const int mb = wy * 64 + fm * 16;
                wmma::fragment<wmma::matrix_a, 16, 16, 16, __nv_bfloat16, wmma::row_major> ah, al;
                wmma::load_matrix_sync(ah, s16 + SM_AHI + mb * LDSA + ks, LDSA);
                wmma::load_matrix_sync(al, s16 + SM_ALO + mb * LDSA + ks, LDSA);
#pragma unroll
                for (int fn = 0; fn < 2; fn++) {
                    wmma::mma_sync(acc[fm][fn], ah, bh[fn], acc[fm][fn]);
                    wmma::mma_sync(acc[fm][fn], ah, bl[fn], acc[fm][fn]);
                    wmma::mma_sync(acc[fm][fn], al, bh[fn], acc[fm][fn]);
                }
            }
        }
        __syncthreads();
    }

    // epilogue via smem C tile (reuses operand smem)
    float* Cs = reinterpret_cast<float*>(smem);
#pragma unroll
    for (int fm = 0; fm < 4; fm++)
#pragma unroll
        for (int fn = 0; fn < 2; fn++)
            wmma::store_matrix_sync(Cs + (wy * 64 + fm * 16) * 128 + wx * 32 + fn * 16,
                                    acc[fm][fn], 128, wmma::mem_row_major);
    __syncthreads();
#pragma unroll
    for (int it = 0; it < 16; it++) {
        int flat = it * 256 + tid;
        int row = flat >> 5, q = flat & 31;
        float4 v = *reinterpret_cast<const float4*>(Cs + row * 128 + q * 4);
        if (bias) {
            const float4 bv = *reinterpret_cast<const float4*>(bias + n0 + q * 4);
            v.x += bv.x; v.y += bv.y; v.z += bv.z; v.w += bv.w;
        }
        *reinterpret_cast<float4*>(C + (size_t)(m0 + row) * ldc + cOff + q * 4) = v;
    }
}

// ---------------------------------------------------------------------------
// Heads GEMM (K=128) with fused GELU . W2 epilogue
// grid (2, 512): x=0 -> heads 0,1 ; x=1 -> head 2 (+64 padded cols)
// ---------------------------------------------------------------------------
__device__ __forceinline__ float gelu_exact(float x) {
    return 0.5f * x * (1.0f + erff(x * 0.70710678118654752f));
}

__global__ __launch_bounds__(256)
void gemm_heads(const __nv_bfloat16* __restrict__ Ahi, const __nv_bfloat16* __restrict__ Alo,
                const __nv_bfloat16* __restrict__ Bhi, const __nv_bfloat16* __restrict__ Blo,
                const float* __restrict__ b1cat, const float* __restrict__ W2cat,
                const float* __restrict__ bh2, const float* __restrict__ bt2, const float* __restrict__ bv2,
                float* __restrict__ oH, float* __restrict__ oT, float* __restrict__ oV)
{
    extern __shared__ __align__(16) char smem[];
    __nv_bfloat16* s16 = reinterpret_cast<__nv_bfloat16*>(smem);
    const int tid = threadIdx.x, wid = tid >> 5;
    const int wy = wid >> 2, wx = wid & 3;
    const long long m0 = (long long)blockIdx.y * 128;
    const int n0 = blockIdx.x * 128;

    wmma::fragment<wmma::accumulator, 16, 16, 16, float> acc[4][2];
#pragma unroll
    for (int i = 0; i < 4; i++)
#pragma unroll
        for (int j = 0; j < 2; j++) wmma::fill_fragment(acc[i][j], 0.0f);

    for (int c = 0; c < 4; c++) {
        stage(s16 + SM_AHI, Ahi, m0, c * BKT, DSq, tid);
        stage(s16 + SM_ALO, Alo, m0, c * BKT, DSq, tid);
        stage(s16 + SM_BHI, Bhi, n0, c * BKT, DSq, tid);
        stage(s16 + SM_BLO, Blo, n0, c * BKT, DSq, tid);
        __syncthreads();
#pragma unroll
        for (int ks = 0; ks < BKT; ks += 16) {
            wmma::fragment<wmma::matrix_b, 16, 16, 16, __nv_bfloat16, wmma::col_major> bh[2], bl[2];
#pragma unroll
            for (int fn = 0; fn < 2; fn++) {
                const int nb = wx * 32 + fn * 16;
                wmma::load_matrix_sync(bh[fn], s16 + SM_BHI + nb * LDSA + ks, LDSA);
                wmma::load_matrix_sync(bl[fn], s16 + SM_BLO + nb * LDSA + ks, LDSA);
            }
#pragma unroll
            for (int fm = 0; fm < 4; fm++) {
                const int mb = wy * 64 + fm * 16;
                wmma::fragment<wmma::matrix_a, 16, 16, 16, __nv_bfloat16, wmma::row_major> ah, al;
                wmma::load_matrix_sync(ah, s16 + SM_AHI + mb * LDSA + ks, LDSA);
                wmma::load_matrix_sync(al, s16 + SM_ALO + mb * LDSA + ks, LDSA);
#pragma unroll
                for (int fn = 0; fn < 2; fn++) {
                    wmma::mma_sync(acc[fm][fn], ah, bh[fn], acc[fm][fn]);
                    wmma::mma_sync(acc[fm][fn], ah, bl[fn], acc[fm][fn]);
                    wmma::mma_sync(acc[fm][fn], al, bh[fn], acc[fm][fn]);
                }
            }
        }
        __syncthreads();
    }

    float* Cs = reinterpret_cast<float*>(smem);
#pragma unroll
    for (int fm = 0; fm < 4; fm++)
#pragma unroll
        for (int fn = 0; fn < 2; fn++)
            wmma::store_matrix_sync(Cs + (wy * 64 + fm * 16) * 128 + wx * 32 + fn * 16,
                                    acc[fm][fn], 128, wmma::mem_row_major);
    __syncthreads();

    // per-thread row dot: tid -> (row = tid>>1, half = tid&1)
    const int row = tid >> 1, half = tid & 1;
    const int headIdx = blockIdx.x * 2 + half;
    if (headIdx < 3) {
        float dot = 0.f;
#pragma unroll
        for (int q = 0; q < 16; q++) {
            int qq = (q + row) & 15;                       // stagger banks
            float4 v = *reinterpret_cast<const float4*>(Cs + row * 128 + half * 64 + qq * 4);
            int col = n0 + half * 64 + qq * 4;
            dot = fmaf(gelu_exact(v.x + __ldg(b1cat + col + 0)), __ldg(W2cat + col + 0), dot);
            dot = fmaf(gelu_exact(v.y + __ldg(b1cat + col + 1)), __ldg(W2cat + col + 1), dot);
            dot = fmaf(gelu_exact(v.z + __ldg(b1cat + col + 2)), __ldg(W2cat + col + 2), dot);
            dot = fmaf(gelu_exact(v.w + __ldg(b1cat + col + 3)), __ldg(W2cat + col + 3), dot);
        }
        float* op = (headIdx == 0) ? oH : (headIdx == 1) ? oT : oV;
        float b2 = (headIdx == 0) ? __ldg(bh2) : (headIdx == 1) ? __ldg(bt2) : __ldg(bv2);
        op[m0 + row] = dot + b2;
    }
}

// ---------------------------------------------------------------------------
// Conversions / weight prep
// ---------------------------------------------------------------------------
__device__ __forceinline__ void hilo(float v, __nv_bfloat16& h, __nv_bfloat16& l) {
    h = __float2bfloat16(v);
    l = __float2bfloat16(v - __bfloat162float(h));
}

__global__ void cvt_hilo(const float* __restrict__ x, __nv_bfloat16* __restrict__ hi,
                         __nv_bfloat16* __restrict__ lo, int n)
{
    int i = blockIdx.x * 256 + threadIdx.x;
    if (i < n) { __nv_bfloat16 h, l; hilo(x[i], h, l); hi[i] = h; lo[i] = l; }
}

__global__ void prep_weights(const float* __restrict__ Wi, const float* __restrict__ W_ih,
                             const float* __restrict__ Wm, const float* __restrict__ Ws,
                             const float* __restrict__ Wh1, const float* __restrict__ Wt1,
                             const float* __restrict__ Wv1,
                             const float* __restrict__ bh1, const float* __restrict__ bt1,
                             const float* __restrict__ bv1,
                             const float* __restrict__ Wh2, const float* __restrict__ Wt2,
                             const float* __restrict__ Wv2)
{
    const int N_Wi = DSq * Dq, N_Wih = 3 * DSq * DSq, N_Wm = Dq * DSq;
    const int N_W1 = 256 * DSq;
    const long long N_Ws = (long long)Dq * NEq * Dq;
    long long idx = (long long)blockIdx.x * 256 + threadIdx.x;
    __nv_bfloat16 h, l;
    if (idx < N_Wi)  { hilo(Wi[idx], h, l);   g_Wi_hi[idx] = h;  g_Wi_lo[idx] = l;  return; }
    idx -= N_Wi;
    if (idx < N_Wih) { hilo(W_ih[idx], h, l); g_Wih_hi[idx] = h; g_Wih_lo[idx] = l; return; }
    idx -= N_Wih;
    if (idx < N_Wm)  { hilo(Wm[idx], h, l);   g_Wm_hi[idx] = h;  g_Wm_lo[idx] = l;  return; }
    idx -= N_Wm;
    if (idx < N_Wm) {
        int j = (int)(idx / DSq), k = (int)(idx % DSq);
        hilo(Wm[idx], h, l);
        g_WmT_hi[(size_t)k * Dq + j] = h; g_WmT_lo[(size_t)k * Dq + j] = l; return;
    }
    idx -= N_Wm;
    if (idx < N_W1) {
        int r = (int)(idx / DSq), c = (int)(idx % DSq);
        float v = (r < 64) ? Wh1[r * DSq + c] : (r < 128) ? Wt1[(r - 64) * DSq + c]
                : (r < 192) ? Wv1[(r - 128) * DSq + c] : 0.f;
        hilo(v, h, l); g_W1_hi[idx] = h; g_W1_lo[idx] = l; return;
    }
    idx -= N_W1;
    if (idx < 256) {
        int i = (int)idx;
        g_b1cat[i] = (i < 64) ? bh1[i] : (i < 128) ? bt1[i - 64] : (i < 192) ? bv1[i - 128] : 0.f;
        g_W2cat[i] = (i < 64) ? Wh2[i] : (i < 128) ? Wt2[i - 64] : (i < 192) ? Wv2[i - 128] : 0.f;
        return;
    }
    idx -= 256;
    if (idx < N_Ws) { hilo(Ws[idx], h, l); g_Ws_hi[idx] = h; g_Ws_lo[idx] = l; }
}
#define PREP_TOTAL (DSq*Dq + 3*DSq*DSq + Dq*DSq + Dq*DSq + 256*DSq + 256 + Dq*NEq*Dq)

// ---------------------------------------------------------------------------
// Route softmax
// ---------------------------------------------------------------------------
__global__ __launch_bounds__(256)
void route_kernel(const float* __restrict__ h_seq, const float* __restrict__ ek,
                  float* __restrict__ rw)
{
    const int row = blockIdx.x;
    const int w = threadIdx.x >> 5, lane = threadIdx.x & 31;
    const float* hr = h_seq + (size_t)row * Dq;
    const float* er = ek + (size_t)w * Dq;
    float s = 0.f;
#pragma unroll 4
    for (int k = lane; k < Dq; k += 32) s = fmaf(hr[k], er[k], s);
#pragma unroll
    for (int o = 16; o; o >>= 1) s += __shfl_xor_sync(0xffffffffu, s, o);
    __shared__ float lg[NEq];
    if (lane == 0) lg[w] = s;
    __syncthreads();
    if (threadIdx.x == 0) {
        const float inv = 0.036084391824351615f;
        float v[NEq], m = -1e30f;
#pragma unroll
        for (int e = 0; e < NEq; e++) { v[e] = lg[e] * inv; m = fmaxf(m, v[e]); }
        float den = 0.f;
#pragma unroll
        for (int e = 0; e < NEq; e++) { v[e] = __expf(v[e] - m); den += v[e]; }
        float id = 1.f / den;
#pragma unroll
        for (int e = 0; e < NEq; e++) rw[(size_t)row * NEq + e] = v[e] * id;
    }
}

__global__ __launch_bounds__(256)
void pbias_kernel(const float* __restrict__ Ws, const float* __restrict__ bm,
                  const float* __restrict__ bs, float* __restrict__ pb)
{
    int d = blockIdx.x, tid = threadIdx.x;
    float s = 0.f;
    for (int j = tid; j < NEq * Dq; j += 256) s = fmaf(bm[j % Dq], Ws[(size_t)d * (NEq * Dq) + j], s);
    __shared__ float red[256];
    red[tid] = s; __syncthreads();
    for (int o = 128; o; o >>= 1) { if (tid < o) red[tid] += red[tid + o]; __syncthreads(); }
    if (tid == 0) pb[d] = red[0] + bs[d];
}

// ---------------------------------------------------------------------------
// GRU scan, fma.rn.f32x2 matvec
// ---------------------------------------------------------------------------
__global__ __launch_bounds__(384, 1)
void gru_scan(const float* __restrict__ Q, const float* __restrict__ rw,
              const float* __restrict__ state0, const float* __restrict__ W_hh,
              const float* __restrict__ b_ih, const float* __restrict__ b_hh,
              float* __restrict__ state_out)
{
    const int b = blockIdx.x >> 3;
    const int e = blockIdx.x & 7;
    const int j = threadIdx.x;

    unsigned long long w2r[64];
    {
        const unsigned long long* wr = reinterpret_cast<const unsigned long long*>(W_hh + (size_t)j * DSq);
#pragma unroll
        for (int i = 0; i < 64; i++) w2r[i] = wr[i];
    }
    __shared__ __align__(16) float hbuf[DSq];
    __shared__ float gh[3 * DSq];

    if (j < 32) reinterpret_cast<float4*>(hbuf)[j] = reinterpret_cast<const float4*>(state0 + e * DSq)[j];
    const float bhh = b_hh[j];
    float bir = 0.f, biz = 0.f, bin = 0.f;
    if (j < DSq) { bir = b_ih[j]; biz = b_ih[DSq + j]; bin = b_ih[2 * DSq + j]; }
    __syncthreads();

    const ulonglong2* hs2 = reinterpret_cast<const ulonglong2*>(hbuf);

    for (int t = 0; t < Tq; t++) {
        const int row = b * Tq + t;
        float qr = 0.f, qz = 0.f, qn = 0.f, rwv = 0.f;
        if (j < DSq) {
            const float* qp = Q + (size_t)row * (3 * DSq);
            qr = qp[j]; qz = qp[DSq + j]; qn = qp[2 * DSq + j];
            rwv = rw[(size_t)row * NEq + e];
        }
        unsigned long long a0 = 0, a1 = 0, a2 = 0, a3 = 0;
#pragma unroll
        for (int i = 0; i < 32; i += 2) {
            ulonglong2 h0 = hs2[i];
            ulonglong2 h1 = hs2[i + 1];
            a0 = fma_f32x2(w2r[i * 2 + 0], h0.x, a0);
            a1 = fma_f32x2(w2r[i * 2 + 1], h0.y, a1);
            a2 = fma_f32x2(w2r[i * 2 + 2], h1.x, a2);
            a3 = fma_f32x2(w2r[i * 2 + 3], h1.y, a3);
        }
        float acc = ((lo_f(a0) + hi_f(a0)) + (lo_f(a1) + hi_f(a1)))
                  + ((lo_f(a2) + hi_f(a2)) + (lo_f(a3) + hi_f(a3)));
        gh[j] = acc + bhh;
        __syncthreads();
        if (j < DSq) {
            float gir = fmaf(rwv, qr, bir);
            float giz = fmaf(rwv, qz, biz);
            float gin = fmaf(rwv, qn, bin);
            float r = 1.f / (1.f + __expf(-(gir + gh[j])));
            float z = 1.f / (1.f + __expf(-(giz + gh[DSq + j])));
            float n = tanhf(fmaf(r, gh[2 * DSq + j], gin));
            float hnew = fmaf(z, hbuf[j] - n, n);
            hbuf[j] = hnew;
            state_out[(((size_t)row) * NEq + e) * DSq + j] = hnew;
        }
        __syncthreads();
    }
}

// ---------------------------------------------------------------------------
// Launch
// ---------------------------------------------------------------------------
extern "C" void kernel_launch(void* const* d_in, const int* in_sizes, int n_in,
                              void* d_out, int out_size)
{
    const float* h_seq = (const float*)d_in[0];
    const float* ek    = (const float*)d_in[1];
    const float* state0= (const float*)d_in[2];
    const float* Wi    = (const float*)d_in[3];
    const float* bi    = (const float*)d_in[4];
    const float* W_ih  = (const float*)d_in[5];
    const float* W_hh  = (const float*)d_in[6];
    const float* b_ih  = (const float*)d_in[7];
    const float* b_hh  = (const float*)d_in[8];
    const float* Wm    = (const float*)d_in[9];
    const float* bm    = (const float*)d_in[10];
    const float* Ws    = (const float*)d_in[11];
    const float* bs    = (const float*)d_in[12];
    const float* Wh1   = (const float*)d_in[13];
    const float* bh1   = (const float*)d_in[14];
    const float* Wh2   = (const float*)d_in[15];
    const float* bh2   = (const float*)d_in[16];
    const float* Wt1   = (const float*)d_in[17];
    const float* bt1   = (const float*)d_in[18];
    const float* Wt2   = (const float*)d_in[19];
    const float* bt2   = (const float*)d_in[20];
    const float* Wv1   = (const float*)d_in[21];
    const float* bv1   = (const float*)d_in[22];
    const float* Wv2   = (const float*)d_in[23];
    const float* bv2   = (const float*)d_in[24];
    float* out = (float*)d_out;

    cudaFuncSetAttribute(gemm_tc, cudaFuncAttributeMaxDynamicSharedMemorySize, SM_BYTES);
    cudaFuncSetAttribute(gemm_heads, cudaFuncAttributeMaxDynamicSharedMemorySize, SM_BYTES);

#define SYMF(p, s) float* p; cudaGetSymbolAddress((void**)&p, s)
#define SYMB(p, s) __nv_bfloat16* p; cudaGetSymbolAddress((void**)&p, s)
    SYMB(p_hsh, g_hseq_hi);  SYMB(p_hsl, g_hseq_lo);
    SYMB(p_sth, g_state_hi); SYMB(p_stl, g_state_lo);
    SYMB(p_prh, g_projh);    SYMB(p_prl, g_projl);
    SYMB(p_wsh, g_Ws_hi);    SYMB(p_wsl, g_Ws_lo);
    SYMB(p_wih, g_Wi_hi);    SYMB(p_wil, g_Wi_lo);
    SYMB(p_whh, g_Wih_hi);   SYMB(p_whl, g_Wih_lo);
    SYMB(p_wmh, g_Wm_hi);    SYMB(p_wml, g_Wm_lo);
    SYMB(p_wth, g_WmT_hi);   SYMB(p_wtl, g_WmT_lo);
    SYMB(p_mch, g_Mc_hi);    SYMB(p_mcl, g_Mc_lo);
    SYMB(p_w1h, g_W1_hi);    SYMB(p_w1l, g_W1_lo);
    SYMF(p_proj, g_proj); SYMF(p_Q, g_Q); SYMF(p_Mc, g_Mc); SYMF(p_pb, g_pbias);
    SYMF(p_b1, g_b1cat);  SYMF(p_w2, g_W2cat);

    // 1) prep + conversions + route
    prep_weights<<<(PREP_TOTAL + 255) / 256, 256>>>(Wi, W_ih, Wm, Ws, Wh1, Wt1, Wv1,
                                                    bh1, bt1, bv1, Wh2, Wt2, Wv2);
    cvt_hilo<<<(ROWS * Dq + 255) / 256, 256>>>(h_seq, p_hsh, p_hsl, ROWS * Dq);
    route_kernel<<<ROWS, 256>>>(h_seq, ek, out + RW_OFF);

    // 2) proj = h_seq @ Wi^T + bi   [8192,128] K=768
    gemm_tc<<<dim3(1, ROWS / 128, 1), 256, SM_BYTES>>>(p_hsh, p_hsl, Dq, 0,
                                                       p_wih, p_wil, Dq,
                                                       p_proj, DSq, 0, bi, Dq / BKT);
    cvt_hilo<<<(ROWS * DSq + 255) / 256, 256>>>(p_proj, p_prh, p_prl, ROWS * DSq);

    // 3) Q = proj @ W_ih^T          [8192,384] K=128
    gemm_tc<<<dim3(3, ROWS / 128, 1), 256, SM_BYTES>>>(p_prh, p_prl, DSq, 0,
                                                       p_whh, p_whl, DSq,
                                                       p_Q, 3 * DSq, 0, nullptr, DSq / BKT);

    // 4) Mc[d, e*128+k] = (Ws_e @ Wm)[d,k]  + pbias
    gemm_tc<<<dim3(1, Dq / 128, NEq), 256, SM_BYTES>>>(p_wsh, p_wsl, NEq * Dq, Dq,
                                                       p_wth, p_wtl, Dq,
                                                       p_Mc, NEq * DSq, DSq, nullptr, Dq / BKT);
    pbias_kernel<<<Dq, 256>>>(Ws, bm, bs, p_pb);
    cvt_hilo<<<(Dq * NEq * DSq + 255) / 256, 256>>>(p_Mc, p_mch, p_mcl, Dq * NEq * DSq);

    // 5) GRU scan -> state_stack (output)
    gru_scan<<<Bq * NEq, 384>>>(p_Q, out + RW_OFF, state0, W_hh, b_ih, b_hh, out + STATE_OFF);
    cvt_hilo<<<(SROWS * DSq + 255) / 256, 256>>>(out + STATE_OFF, p_sth, p_stl, SROWS * DSq);

    // 6) memory = state @ Wm^T + bm   [65536,768] K=128
    gemm_tc<<<dim3(Dq / 128, SROWS / 128, 1), 256, SM_BYTES>>>(p_sth, p_stl, DSq, 0,
                                                               p_wmh, p_wml, DSq,
                                                               out + MEM_OFF, Dq, 0, bm, DSq / BKT);

    // 7) pooled = state_flat @ Mc^T + pbias   [8192,768] K=1024
    gemm_tc<<<dim3(Dq / 128, ROWS / 128, 1), 256, SM_BYTES>>>(p_sth, p_stl, NEq * DSq, 0,
                                                              p_mch, p_mcl, NEq * DSq,
                                                              out + POOLED_OFF, Dq, 0, p_pb, (NEq * DSq) / BKT);

    // 8) heads fused -> holder/tagged/visible (outputs)
    gemm_heads<<<dim3(2, SROWS / 128, 1), 256, SM_BYTES>>>(p_sth, p_stl, p_w1h, p_w1l,
                                                           p_b1, p_w2, bh2, bt2, bv2,
                                                           out + HOLDER_OFF, out + TAGGED_OFF, out + VISIBLE_OFF);

    (void)in_sizes; (void)n_in; (void)out_size;
}

// round 5
// speedup vs baseline: 1.6629x; 1.0531x over previous
#include <cuda_runtime.h>
#include <cuda_bf16.h>
#include <mma.h>
#include <math.h>
#include <stdint.h>

using namespace nvcuda;

#define Bq   8
#define Tq   1024
#define Dq   768
#define NEq  8
#define DSq  128
#define ROWS (Bq*Tq)            // 8192
#define SROWS (Bq*Tq*NEq)       // 65536

#define POOLED_OFF  0ll
#define MEM_OFF     6291456ll
#define STATE_OFF   56623104ll
#define HOLDER_OFF  65011712ll
#define TAGGED_OFF  65077248ll
#define VISIBLE_OFF 65142784ll
#define RW_OFF      65208320ll

// ---------------------------------------------------------------------------
// Scratch (16B-aligned for cp.async)
// ---------------------------------------------------------------------------
__device__ __align__(16) __nv_bfloat16 g_hseq_hi[ROWS*Dq],    g_hseq_lo[ROWS*Dq];
__device__ __align__(16) __nv_bfloat16 g_state_hi[SROWS*DSq], g_state_lo[SROWS*DSq];
__device__ __align__(16) __nv_bfloat16 g_projh[ROWS*DSq],     g_projl[ROWS*DSq];
__device__ __align__(16) __nv_bfloat16 g_Ws_hi[Dq*NEq*Dq],    g_Ws_lo[Dq*NEq*Dq];
__device__ __align__(16) __nv_bfloat16 g_Wi_hi[DSq*Dq],       g_Wi_lo[DSq*Dq];
__device__ __align__(16) __nv_bfloat16 g_Wih_hi[3*DSq*DSq],   g_Wih_lo[3*DSq*DSq];
__device__ __align__(16) __nv_bfloat16 g_Wm_hi[Dq*DSq],       g_Wm_lo[Dq*DSq];
__device__ __align__(16) __nv_bfloat16 g_WmT_hi[DSq*Dq],      g_WmT_lo[DSq*Dq];
__device__ __align__(16) __nv_bfloat16 g_Mc_hi[Dq*NEq*DSq],   g_Mc_lo[Dq*NEq*DSq];
__device__ __align__(16) __nv_bfloat16 g_W1_hi[256*DSq],      g_W1_lo[256*DSq];
__device__ __align__(16) float g_proj[ROWS*DSq];
__device__ __align__(16) float g_Q[ROWS*3*DSq];
__device__ __align__(16) float g_Mc[Dq*NEq*DSq];
__device__ __align__(16) float g_pbias[Dq];
__device__ __align__(16) float g_b1cat[256];
__device__ __align__(16) float g_W2cat[256];

// ---------------------------------------------------------------------------
// f32x2 packed FMA (base ISA sm_100+)
// ---------------------------------------------------------------------------
__device__ __forceinline__ unsigned long long fma_f32x2(unsigned long long a, unsigned long long b, unsigned long long c) {
    unsigned long long d;
    asm("fma.rn.f32x2 %0, %1, %2, %3;" : "=l"(d) : "l"(a), "l"(b), "l"(c));
    return d;
}
__device__ __forceinline__ float lo_f(unsigned long long v) { return __uint_as_float((uint32_t)v); }
__device__ __forceinline__ float hi_f(unsigned long long v) { return __uint_as_float((uint32_t)(v >> 32)); }

__device__ __forceinline__ uint32_t smem_u32(const void* p) {
    uint32_t a;
    asm("{ .reg .u64 t; cvta.to.shared.u64 t, %1; cvt.u32.u64 %0, t; }" : "=r"(a) : "l"(p));
    return a;
}
#define CP_COMMIT() asm volatile("cp.async.commit_group;" ::: "memory")
#define CP_WAIT0()  asm volatile("cp.async.wait_group 0;" ::: "memory")
#define CP_WAIT1()  asm volatile("cp.async.wait_group 1;" ::: "memory")

// ---------------------------------------------------------------------------
// GEMM tiling: block 128x128, BK=32, 8 warps (2x4), warp tile 64x32.
// Double-buffered cp.async staging: 4 tiles x 10240B per buffer.
// ---------------------------------------------------------------------------
#define BKT    32
#define LDSA   40
#define TILE_B 10240              // 128*40*2 bytes
#define BUF_B  40960              // 4 tiles
#define SM_BYTES 81920            // 2 buffers (epilogue C 64KB reuses this)

// async-stage one 128x32 bf16 tile: 512 x 16B, 2 per thread
__device__ __forceinline__ void stage_async(uint32_t sdst, const __nv_bfloat16* __restrict__ g,
                                            long long row0, int k0, int ld, int tid)
{
#pragma unroll
    for (int it = 0; it < 2; it++) {
        int flat = it * 256 + tid;
        int row  = flat >> 2;
        int q    = flat & 3;
        uint32_t d = sdst + row * (LDSA * 2) + q * 16;
        const void* s = g + (row0 + row) * (long long)ld + k0 + q * 8;
        asm volatile("cp.async.cg.shared.global [%0], [%1], 16;" :: "r"(d), "l"(s));
    }
}

__device__ __forceinline__ void hilo(float v, __nv_bfloat16& h, __nv_bfloat16& l) {
    h = __float2bfloat16(v);
    l = __float2bfloat16(v - __bfloat162float(h));
}

// C[m,n] = sum_k A[m,k]*B[n,k] (+bias[n]); optional bf16 hi/lo outputs.
__global__ __launch_bounds__(256, 2)
void gemm_tc(const __nv_bfloat16* __restrict__ Ahi, const __nv_bfloat16* __restrict__ Alo, int lda, int aK0z,
             const __nv_bfloat16* __restrict__ Bhi, const __nv_bfloat16* __restrict__ Blo, int ldb,
             float* __restrict__ C, int ldc, int cZoff,
             const float* __restrict__ bias, int nChunks,
             __nv_bfloat16* __restrict__ outH, __nv_bfloat16* __restrict__ outL)
{
    extern __shared__ __align__(16) char smem[];
    __nv_bfloat16* s16 = reinterpret_cast<__nv_bfloat16*>(smem);
    const uint32_t sb = smem_u32(smem);
    const int tid = threadIdx.x, wid = tid >> 5;
    const int wy = wid >> 2, wx = wid & 3;
    const long long m0 = (long long)blockIdx.y * 128;
    const int n0 = blockIdx.x * 128;
    const int aK0 = blockIdx.z * aK0z;
    const int cOff = n0 + blockIdx.z * cZoff;

    wmma::fragment<wmma::accumulator, 16, 16, 16, float> acc[4][2];
#pragma unroll
    for (int i = 0; i < 4; i++)
#pragma unroll
        for (int j = 0; j < 2; j++) wmma::fill_fragment(acc[i][j], 0.0f);

    // prologue: stage chunk 0 into buffer 0
    {
        uint32_t b0 = sb;
        stage_async(b0,              Ahi, m0, aK0, lda, tid);
        stage_async(b0 + TILE_B,     Alo, m0, aK0, lda, tid);
        stage_async(b0 + 2 * TILE_B, Bhi, n0, 0,   ldb, tid);
        stage_async(b0 + 3 * TILE_B, Blo, n0, 0,   ldb, tid);
        CP_COMMIT();
    }

    for (int c = 0; c < nChunks; c++) {
        if (c + 1 < nChunks) {
            uint32_t bn = sb + ((c + 1) & 1) * BUF_B;
            stage_async(bn,              Ahi, m0, aK0 + (c + 1) * BKT, lda, tid);
            stage_async(bn + TILE_B,     Alo, m0, aK0 + (c + 1) * BKT, lda, tid);
            stage_async(bn + 2 * TILE_B, Bhi, n0, (c + 1) * BKT, ldb, tid);
            stage_async(bn + 3 * TILE_B, Blo, n0, (c + 1) * BKT, ldb, tid);
            CP_COMMIT();
            CP_WAIT1();
        } else {
            CP_WAIT0();
        }
        __syncthreads();
        const __nv_bfloat16* base = s16 + (c & 1) * (BUF_B / 2);
#pragma unroll
        for (int ks = 0; ks < BKT; ks += 16) {
            wmma::fragment<wmma::matrix_b, 16, 16, 16, __nv_bfloat16, wmma::col_major> bh[2], bl[2];
#pragma unroll
            for (int fn = 0; fn < 2; fn++) {
                const int nb = wx * 32 + fn * 16;
                wmma::load_matrix_sync(bh[fn], base + (TILE_B) + nb * LDSA + ks, LDSA);
                wmma::load_matrix_sync(bl[fn], base + (TILE_B / 2) * 3 + nb * LDSA + ks, LDSA);
            }
#pragma unroll
            for (int fm = 0; fm < 4; fm++) {
                const int mb = wy * 64 + fm * 16;
                wmma::fragment<wmma::matrix_a, 16, 16, 16, __nv_bfloat16, wmma::row_major> ah, al;
                wmma::load_matrix_sync(ah, base + mb * LDSA + ks, LDSA);
                wmma::load_matrix_sync(al, base + (TILE_B / 2) + mb * LDSA + ks, LDSA);
#pragma unroll
                for (int fn = 0; fn < 2; fn++) {
                    wmma::mma_sync(acc[fm][fn], ah, bh[fn], acc[fm][fn]);
                    wmma::mma_sync(acc[fm][fn], ah, bl[fn], acc[fm][fn]);
                    wmma::mma_sync(acc[fm][fn], al, bh[fn], acc[fm][fn]);
                }
            }
        }
        __syncthreads();
    }

    // epilogue via smem C tile
    float* Cs = reinterpret_cast<float*>(smem);
#pragma unroll
    for (int fm = 0; fm < 4; fm++)
#pragma unroll
        for (int fn = 0; fn < 2; fn++)
            wmma::store_matrix_sync(Cs + (wy * 64 + fm * 16) * 128 + wx * 32 + fn * 16,
                                    acc[fm][fn], 128, wmma::mem_row_major);
    __syncthreads();
#pragma unroll
    for (int it = 0; it < 16; it++) {
        int flat = it * 256 + tid;
        int row = flat >> 5, q = flat & 31;
        float4 v = *reinterpret_cast<const float4*>(Cs + row * 128 + q * 4);
        if (bias) {
            const float4 bv = *reinterpret_cast<const float4*>(bias + n0 + q * 4);
            v.x += bv.x; v.y += bv.y; v.z += bv.z; v.w += bv.w;
        }
        size_t co = (size_t)(m0 + row) * ldc + cOff + q * 4;
        *reinterpret_cast<float4*>(C + co) = v;
        if (outH) {
            __nv_bfloat16 h0,l0,h1,l1,h2,l2,h3,l3;
            hilo(v.x,h0,l0); hilo(v.y,h1,l1); hilo(v.z,h2,l2); hilo(v.w,h3,l3);
            __nv_bfloat162 ph0 = {h0,h1}, ph1 = {h2,h3}, pl0 = {l0,l1}, pl1 = {l2,l3};
            *reinterpret_cast<__nv_bfloat162*>(outH + co)     = ph0;
            *reinterpret_cast<__nv_bfloat162*>(outH + co + 2) = ph1;
            *reinterpret_cast<__nv_bfloat162*>(outL + co)     = pl0;
            *reinterpret_cast<__nv_bfloat162*>(outL + co + 2) = pl1;
        }
    }
}

// ---------------------------------------------------------------------------
// Heads GEMM (K=128) with fused GELU . W2 epilogue
// ---------------------------------------------------------------------------
__device__ __forceinline__ float gelu_exact(float x) {
    return 0.5f * x * (1.0f + erff(x * 0.70710678118654752f));
}

__global__ __launch_bounds__(256, 2)
void gemm_heads(const __nv_bfloat16* __restrict__ Ahi, const __nv_bfloat16* __restrict__ Alo,
                const __nv_bfloat16* __restrict__ Bhi, const __nv_bfloat16* __restrict__ Blo,
                const float* __restrict__ b1cat, const float* __restrict__ W2cat,
                const float* __restrict__ bh2, const float* __restrict__ bt2, const float* __restrict__ bv2,
                float* __restrict__ oH, float* __restrict__ oT, float* __restrict__ oV)
{
    extern __shared__ __align__(16) char smem[];
    __nv_bfloat16* s16 = reinterpret_cast<__nv_bfloat16*>(smem);
    const uint32_t sb = smem_u32(smem);
    const int tid = threadIdx.x, wid = tid >> 5;
    const int wy = wid >> 2, wx = wid & 3;
    const long long m0 = (long long)blockIdx.y * 128;
    const int n0 = blockIdx.x * 128;
    const int nChunks = 4;

    wmma::fragment<wmma::accumulator, 16, 16, 16, float> acc[4][2];
#pragma unroll
    for (int i = 0; i < 4; i++)
#pragma unroll
        for (int j = 0; j < 2; j++) wmma::fill_fragment(acc[i][j], 0.0f);

    {
        uint32_t b0 = sb;
        stage_async(b0,              Ahi, m0, 0, DSq, tid);
        stage_async(b0 + TILE_B,     Alo, m0, 0, DSq, tid);
        stage_async(b0 + 2 * TILE_B, Bhi, n0, 0, DSq, tid);
        stage_async(b0 + 3 * TILE_B, Blo, n0, 0, DSq, tid);
        CP_COMMIT();
    }
    for (int c = 0; c < nChunks; c++) {
        if (c + 1 < nChunks) {
            uint32_t bn = sb + ((c + 1) & 1) * BUF_B;
            stage_async(bn,              Ahi, m0, (c + 1) * BKT, DSq, tid);
            stage_async(bn + TILE_B,     Alo, m0, (c + 1) * BKT, DSq, tid);
            stage_async(bn + 2 * TILE_B, Bhi, n0, (c + 1) * BKT, DSq, tid);
            stage_async(bn + 3 * TILE_B, Blo, n0, (c + 1) * BKT, DSq, tid);
            CP_COMMIT();
            CP_WAIT1();
        } else {
            CP_WAIT0();
        }
        __syncthreads();
        const __nv_bfloat16* base = s16 + (c & 1) * (BUF_B / 2);
#pragma unroll
        for (int ks = 0; ks < BKT; ks += 16) {
            wmma::fragment<wmma::matrix_b, 16, 16, 16, __nv_bfloat16, wmma::col_major> bh[2], bl[2];
#pragma unroll
            for (int fn = 0; fn < 2; fn++) {
                const int nb = wx * 32 + fn * 16;
                wmma::load_matrix_sync(bh[fn], base + (TILE_B) + nb * LDSA + ks, LDSA);
                wmma::load_matrix_sync(bl[fn], base + (TILE_B / 2) * 3 + nb * LDSA + ks, LDSA);
            }
#pragma unroll
            for (int fm = 0; fm < 4; fm++) {
                const int mb = wy * 64 + fm * 16;
                wmma::fragment<wmma::matrix_a, 16, 16, 16, __nv_bfloat16, wmma::row_major> ah, al;
                wmma::load_matrix_sync(ah, base + mb * LDSA + ks, LDSA);
                wmma::load_matrix_sync(al, base + (TILE_B / 2) + mb * LDSA + ks, LDSA);
#pragma unroll
                for (int fn = 0; fn < 2; fn++) {
                    wmma::mma_sync(acc[fm][fn], ah, bh[fn], acc[fm][fn]);
                    wmma::mma_sync(acc[fm][fn], ah, bl[fn], acc[fm][fn]);
                    wmma::mma_sync(acc[fm][fn], al, bh[fn], acc[fm][fn]);
                }
            }
        }
        __syncthreads();
    }

    float* Cs = reinterpret_cast<float*>(smem);
#pragma unroll
    for (int fm = 0; fm < 4; fm++)
#pragma unroll
        for (int fn = 0; fn < 2; fn++)
            wmma::store_matrix_sync(Cs + (wy * 64 + fm * 16) * 128 + wx * 32 + fn * 16,
                                    acc[fm][fn], 128, wmma::mem_row_major);
    __syncthreads();

    const int row = tid >> 1, half = tid & 1;
    const int headIdx = blockIdx.x * 2 + half;
    if (headIdx < 3) {
        float dot = 0.f;
#pragma unroll
        for (int q = 0; q < 16; q++) {
            int qq = (q + row) & 15;
            float4 v = *reinterpret_cast<const float4*>(Cs + row * 128 + half * 64 + qq * 4);
            int col = n0 + half * 64 + qq * 4;
            dot = fmaf(gelu_exact(v.x + __ldg(b1cat + col + 0)), __ldg(W2cat + col + 0), dot);
            dot = fmaf(gelu_exact(v.y + __ldg(b1cat + col + 1)), __ldg(W2cat + col + 1), dot);
            dot = fmaf(gelu_exact(v.z + __ldg(b1cat + col + 2)), __ldg(W2cat + col + 2), dot);
            dot = fmaf(gelu_exact(v.w + __ldg(b1cat + col + 3)), __ldg(W2cat + col + 3), dot);
        }
        float* op = (headIdx == 0) ? oH : (headIdx == 1) ? oT : oV;
        float b2 = (headIdx == 0) ? __ldg(bh2) : (headIdx == 1) ? __ldg(bt2) : __ldg(bv2);
        op[m0 + row] = dot + b2;
    }
}

// ---------------------------------------------------------------------------
// Conversions / weight prep
// ---------------------------------------------------------------------------
__global__ void cvt_hilo(const float* __restrict__ x, __nv_bfloat16* __restrict__ hi,
                         __nv_bfloat16* __restrict__ lo, int n)
{
    int i = blockIdx.x * 256 + threadIdx.x;
    if (i < n) { __nv_bfloat16 h, l; hilo(x[i], h, l); hi[i] = h; lo[i] = l; }
}

__global__ void prep_weights(const float* __restrict__ Wi, const float* __restrict__ W_ih,
                             const float* __restrict__ Wm, const float* __restrict__ Ws,
                             const float* __restrict__ Wh1, const float* __restrict__ Wt1,
                             const float* __restrict__ Wv1,
                             const float* __restrict__ bh1, const float* __restrict__ bt1,
                             const float* __restrict__ bv1,
                             const float* __restrict__ Wh2, const float* __restrict__ Wt2,
                             const float* __restrict__ Wv2)
{
    const int N_Wi = DSq * Dq, N_Wih = 3 * DSq * DSq, N_Wm = Dq * DSq;
    const int N_W1 = 256 * DSq;
    const long long N_Ws = (long long)Dq * NEq * Dq;
    long long idx = (long long)blockIdx.x * 256 + threadIdx.x;
    __nv_bfloat16 h, l;
    if (idx < N_Wi)  { hilo(Wi[idx], h, l);   g_Wi_hi[idx] = h;  g_Wi_lo[idx] = l;  return; }
    idx -= N_Wi;
    if (idx < N_Wih) { hilo(W_ih[idx], h, l); g_Wih_hi[idx] = h; g_Wih_lo[idx] = l; return; }
    idx -= N_Wih;
    if (idx < N_Wm)  { hilo(Wm[idx], h, l);   g_Wm_hi[idx] = h;  g_Wm_lo[idx] = l;  return; }
    idx -= N_Wm;
    if (idx < N_Wm) {
        int j = (int)(idx / DSq), k = (int)(idx % DSq);
        hilo(Wm[idx], h, l);
        g_WmT_hi[(size_t)k * Dq + j] = h; g_WmT_lo[(size_t)k * Dq + j] = l; return;
    }
    idx -= N_Wm;
    if (idx < N_W1) {
        int r = (int)(idx / DSq), c = (int)(idx % DSq);
        float v = (r < 64) ? Wh1[r * DSq + c] : (r < 128) ? Wt1[(r - 64) * DSq + c]
                : (r < 192) ? Wv1[(r - 128) * DSq + c] : 0.f;
        hilo(v, h, l); g_W1_hi[idx] = h; g_W1_lo[idx] = l; return;
    }
    idx -= N_W1;
    if (idx < 256) {
        int i = (int)idx;
        g_b1cat[i] = (i < 64) ? bh1[i] : (i < 128) ? bt1[i - 64] : (i < 192) ? bv1[i - 128] : 0.f;
        g_W2cat[i] = (i < 64) ? Wh2[i] : (i < 128) ? Wt2[i - 64] : (i < 192) ? Wv2[i - 128] : 0.f;
        return;
    }
    idx -= 256;
    if (idx < N_Ws) { hilo(Ws[idx], h, l); g_Ws_hi[idx] = h; g_Ws_lo[idx] = l; }
}
#define PREP_TOTAL (DSq*Dq + 3*DSq*DSq + Dq*DSq + Dq*DSq + 256*DSq + 256 + Dq*NEq*Dq)

// ---------------------------------------------------------------------------
// Route softmax
// ---------------------------------------------------------------------------
__global__ __launch_bounds__(256)
void route_kernel(const float* __restrict__ h_seq, const float* __restrict__ ek,
                  float* __restrict__ rw)
{
    const int row = blockIdx.x;
    const int w = threadIdx.x >> 5, lane = threadIdx.x & 31;
    const float* hr = h_seq + (size_t)row * Dq;
    const float* er = ek + (size_t)w * Dq;
    float s = 0.f;
#pragma unroll 4
    for (int k = lane; k < Dq; k += 32) s = fmaf(hr[k], er[k], s);
#pragma unroll
    for (int o = 16; o; o >>= 1) s += __shfl_xor_sync(0xffffffffu, s, o);
    __shared__ float lg[NEq];
    if (lane == 0) lg[w] = s;
    __syncthreads();
    if (threadIdx.x == 0) {
        const float inv = 0.036084391824351615f;
        float v[NEq], m = -1e30f;
#pragma unroll
        for (int e = 0; e < NEq; e++) { v[e] = lg[e] * inv; m = fmaxf(m, v[e]); }
        float den = 0.f;
#pragma unroll
        for (int e = 0; e < NEq; e++) { v[e] = __expf(v[e] - m); den += v[e]; }
        float id = 1.f / den;
#pragma unroll
        for (int e = 0; e < NEq; e++) rw[(size_t)row * NEq + e] = v[e] * id;
    }
}

__global__ __launch_bounds__(256)
void pbias_kernel(const float* __restrict__ Ws, const float* __restrict__ bm,
                  const float* __restrict__ bs, float* __restrict__ pb)
{
    int d = blockIdx.x, tid = threadIdx.x;
    float s = 0.f;
    for (int j = tid; j < NEq * Dq; j += 256) s = fmaf(bm[j % Dq], Ws[(size_t)d * (NEq * Dq) + j], s);
    __shared__ float red[256];
    red[tid] = s; __syncthreads();
    for (int o = 128; o; o >>= 1) { if (tid < o) red[tid] += red[tid + o]; __syncthreads(); }
    if (tid == 0) pb[d] = red[0] + bs[d];
}

// ---------------------------------------------------------------------------
// GRU scan: f32x2 matvec, fast tanh, fused bf16 hi/lo state write
// ---------------------------------------------------------------------------
__global__ __launch_bounds__(384, 1)
void gru_scan(const float* __restrict__ Q, const float* __restrict__ rw,
              const float* __restrict__ state0, const float* __restrict__ W_hh,
              const float* __restrict__ b_ih, const float* __restrict__ b_hh,
              float* __restrict__ state_out,
              __nv_bfloat16* __restrict__ sth, __nv_bfloat16* __restrict__ stl)
{
    const int b = blockIdx.x >> 3;
    const int e = blockIdx.x & 7;
    const int j = threadIdx.x;

    unsigned long long w2r[64];
    {
        const unsigned long long* wr = reinterpret_cast<const unsigned long long*>(W_hh + (size_t)j * DSq);
#pragma unroll
        for (int i = 0; i < 64; i++) w2r[i] = wr[i];
    }
    __shared__ __align__(16) float hbuf[DSq];
    __shared__ float gh[3 * DSq];

    if (j < 32) reinterpret_cast<float4*>(hbuf)[j] = reinterpret_cast<const float4*>(state0 + e * DSq)[j];
    const float bhh = b_hh[j];
    float bir = 0.f, biz = 0.f, bin = 0.f;
    if (j < DSq) { bir = b_ih[j]; biz = b_ih[DSq + j]; bin = b_ih[2 * DSq + j]; }
    __syncthreads();

    const ulonglong2* hs2 = reinterpret_cast<const ulonglong2*>(hbuf);

    for (int t = 0; t < Tq; t++) {
        const int row = b * Tq + t;
        float qr = 0.f, qz = 0.f, qn = 0.f, rwv = 0.f;
        if (j < DSq) {
            const float* qp = Q + (size_t)row * (3 * DSq);
            qr = qp[j]; qz = qp[DSq + j]; qn = qp[2 * DSq + j];
            rwv = rw[(size_t)row * NEq + e];
        }
        unsigned long long a0 = 0, a1 = 0, a2 = 0, a3 = 0;
#pragma unroll
        for (int i = 0; i < 32; i += 2) {
            ulonglong2 h0 = hs2[i];
            ulonglong2 h1 = hs2[i + 1];
            a0 = fma_f32x2(w2r[i * 2 + 0], h0.x, a0);
            a1 = fma_f32x2(w2r[i * 2 + 1], h0.y, a1);
            a2 = fma_f32x2(w2r[i * 2 + 2], h1.x, a2);
            a3 = fma_f32x2(w2r[i * 2 + 3], h1.y, a3);
        }
        float acc = ((lo_f(a0) + hi_f(a0)) + (lo_f(a1) + hi_f(a1)))
                  + ((lo_f(a2) + hi_f(a2)) + (lo_f(a3) + hi_f(a3)));
        gh[j] = acc + bhh;
        __syncthreads();
        if (j < DSq) {
            float gir = fmaf(rwv, qr, bir);
            float giz = fmaf(rwv, qz, biz);
            float gin = fmaf(rwv, qn, bin);
            float r = __fdividef(1.f, 1.f + __expf(-(gir + gh[j])));
            float z = __fdividef(1.f, 1.f + __expf(-(giz + gh[DSq + j])));
            float xn = fmaf(r, gh[2 * DSq + j], gin);
            float ex = __expf(-2.f * xn);
            float n = __fdividef(1.f - ex, 1.f + ex);
            float hnew = fmaf(z, hbuf[j] - n, n);
            hbuf[j] = hnew;
            size_t idx = (((size_t)row) * NEq + e) * DSq + j;
            state_out[idx] = hnew;
            __nv_bfloat16 hh = __float2bfloat16(hnew);
            sth[idx] = hh;
            stl[idx] = __float2bfloat16(hnew - __bfloat162float(hh));
        }
        __syncthreads();
    }
}

// ---------------------------------------------------------------------------
// Launch
// ---------------------------------------------------------------------------
extern "C" void kernel_launch(void* const* d_in, const int* in_sizes, int n_in,
                              void* d_out, int out_size)
{
    const float* h_seq = (const float*)d_in[0];
    const float* ek    = (const float*)d_in[1];
    const float* state0= (const float*)d_in[2];
    const float* Wi    = (const float*)d_in[3];
    const float* bi    = (const float*)d_in[4];
    const float* W_ih  = (const float*)d_in[5];
    const float* W_hh  = (const float*)d_in[6];
    const float* b_ih  = (const float*)d_in[7];
    const float* b_hh  = (const float*)d_in[8];
    const float* Wm    = (const float*)d_in[9];
    const float* bm    = (const float*)d_in[10];
    const float* Ws    = (const float*)d_in[11];
    const float* bs    = (const float*)d_in[12];
    const float* Wh1   = (const float*)d_in[13];
    const float* bh1   = (const float*)d_in[14];
    const float* Wh2   = (const float*)d_in[15];
    const float* bh2   = (const float*)d_in[16];
    const float* Wt1   = (const float*)d_in[17];
    const float* bt1   = (const float*)d_in[18];
    const float* Wt2   = (const float*)d_in[19];
    const float* bt2   = (const float*)d_in[20];
    const float* Wv1   = (const float*)d_in[21];
    const float* bv1   = (const float*)d_in[22];
    const float* Wv2   = (const float*)d_in[23];
    const float* bv2   = (const float*)d_in[24];
    float* out = (float*)d_out;

    cudaFuncSetAttribute(gemm_tc, cudaFuncAttributeMaxDynamicSharedMemorySize, SM_BYTES);
    cudaFuncSetAttribute(gemm_heads, cudaFuncAttributeMaxDynamicSharedMemorySize, SM_BYTES);

#define SYMF(p, s) float* p; cudaGetSymbolAddress((void**)&p, s)
#define SYMB(p, s) __nv_bfloat16* p; cudaGetSymbolAddress((void**)&p, s)
    SYMB(p_hsh, g_hseq_hi);  SYMB(p_hsl, g_hseq_lo);
    SYMB(p_sth, g_state_hi); SYMB(p_stl, g_state_lo);
    SYMB(p_prh, g_projh);    SYMB(p_prl, g_projl);
    SYMB(p_wsh, g_Ws_hi);    SYMB(p_wsl, g_Ws_lo);
    SYMB(p_wih, g_Wi_hi);    SYMB(p_wil, g_Wi_lo);
    SYMB(p_whh, g_Wih_hi);   SYMB(p_whl, g_Wih_lo);
    SYMB(p_wmh, g_Wm_hi);    SYMB(p_wml, g_Wm_lo);
    SYMB(p_wth, g_WmT_hi);   SYMB(p_wtl, g_WmT_lo);
    SYMB(p_mch, g_Mc_hi);    SYMB(p_mcl, g_Mc_lo);
    SYMB(p_w1h, g_W1_hi);    SYMB(p_w1l, g_W1_lo);
    SYMF(p_proj, g_proj); SYMF(p_Q, g_Q); SYMF(p_Mc, g_Mc); SYMF(p_pb, g_pbias);
    SYMF(p_b1, g_b1cat);  SYMF(p_w2, g_W2cat);

    // 1) prep + conversions + route
    prep_weights<<<(PREP_TOTAL + 255) / 256, 256>>>(Wi, W_ih, Wm, Ws, Wh1, Wt1, Wv1,
                                                    bh1, bt1, bv1, Wh2, Wt2, Wv2);
    cvt_hilo<<<(ROWS * Dq + 255) / 256, 256>>>(h_seq, p_hsh, p_hsl, ROWS * Dq);
    route_kernel<<<ROWS, 256>>>(h_seq, ek, out + RW_OFF);

    // 2) proj = h_seq @ Wi^T + bi  [8192,128] K=768  (+ fused bf16 out)
    gemm_tc<<<dim3(1, ROWS / 128, 1), 256, SM_BYTES>>>(p_hsh, p_hsl, Dq, 0,
                                                       p_wih, p_wil, Dq,
                                                       p_proj, DSq, 0, bi, Dq / BKT,
                                                       p_prh, p_prl);

    // 3) Q = proj @ W_ih^T  [8192,384] K=128
    gemm_tc<<<dim3(3, ROWS / 128, 1), 256, SM_BYTES>>>(p_prh, p_prl, DSq, 0,
                                                       p_whh, p_whl, DSq,
                                                       p_Q, 3 * DSq, 0, nullptr, DSq / BKT,
                                                       nullptr, nullptr);

    // 4) Mc = per-entity Ws_e @ Wm  (+ fused bf16 out) + pbias
    gemm_tc<<<dim3(1, Dq / 128, NEq), 256, SM_BYTES>>>(p_wsh, p_wsl, NEq * Dq, Dq,
                                                       p_wth, p_wtl, Dq,
                                                       p_Mc, NEq * DSq, DSq, nullptr, Dq / BKT,
                                                       p_mch, p_mcl);
    pbias_kernel<<<Dq, 256>>>(Ws, bm, bs, p_pb);

    // 5) GRU scan -> state_stack (output) + bf16 hi/lo fused
    gru_scan<<<Bq * NEq, 384>>>(p_Q, out + RW_OFF, state0, W_hh, b_ih, b_hh,
                                out + STATE_OFF, p_sth, p_stl);

    // 6) memory = state @ Wm^T + bm  [65536,768] K=128
    gemm_tc<<<dim3(Dq / 128, SROWS / 128, 1), 256, SM_BYTES>>>(p_sth, p_stl, DSq, 0,
                                                               p_wmh, p_wml, DSq,
                                                               out + MEM_OFF, Dq, 0, bm, DSq / BKT,
                                                               nullptr, nullptr);

    // 7) pooled = state_flat @ Mc^T + pbias  [8192,768] K=1024
    gemm_tc<<<dim3(Dq / 128, ROWS / 128, 1), 256, SM_BYTES>>>(p_sth, p_stl, NEq * DSq, 0,
                                                              p_mch, p_mcl, NEq * DSq,
                                                              out + POOLED_OFF, Dq, 0, p_pb, (NEq * DSq) / BKT,
                                                              nullptr, nullptr);

    // 8) heads fused -> holder/tagged/visible
    gemm_heads<<<dim3(2, SROWS / 128, 1), 256, SM_BYTES>>>(p_sth, p_stl, p_w1h, p_w1l,
                                                           p_b1, p_w2, bh2, bt2, bv2,
                                                           out + HOLDER_OFF, out + TAGGED_OFF, out + VISIBLE_OFF);

    (void)in_sizes; (void)n_in; (void)out_size;
}

// round 6
// speedup vs baseline: 1.7763x; 1.0682x over previous
#include <cuda_runtime.h>
#include <cuda_bf16.h>
#include <mma.h>
#include <math.h>
#include <stdint.h>

using namespace nvcuda;

#define Bq   8
#define Tq   1024
#define Dq   768
#define NEq  8
#define DSq  128
#define ROWS (Bq*Tq)            // 8192
#define SROWS (Bq*Tq*NEq)       // 65536

#define POOLED_OFF  0ll
#define MEM_OFF     6291456ll
#define STATE_OFF   56623104ll
#define HOLDER_OFF  65011712ll
#define TAGGED_OFF  65077248ll
#define VISIBLE_OFF 65142784ll
#define RW_OFF      65208320ll

// ---------------------------------------------------------------------------
// Scratch (16B-aligned for cp.async)
// ---------------------------------------------------------------------------
__device__ __align__(16) __nv_bfloat16 g_hseq_hi[ROWS*Dq],    g_hseq_lo[ROWS*Dq];
__device__ __align__(16) __nv_bfloat16 g_state_hi[SROWS*DSq], g_state_lo[SROWS*DSq];
__device__ __align__(16) __nv_bfloat16 g_projh[ROWS*DSq],     g_projl[ROWS*DSq];
__device__ __align__(16) __nv_bfloat16 g_Ws_hi[Dq*NEq*Dq],    g_Ws_lo[Dq*NEq*Dq];
__device__ __align__(16) __nv_bfloat16 g_Wi_hi[DSq*Dq],       g_Wi_lo[DSq*Dq];
__device__ __align__(16) __nv_bfloat16 g_Wih_hi[3*DSq*DSq],   g_Wih_lo[3*DSq*DSq];
__device__ __align__(16) __nv_bfloat16 g_Wm_hi[Dq*DSq],       g_Wm_lo[Dq*DSq];
__device__ __align__(16) __nv_bfloat16 g_WmT_hi[DSq*Dq],      g_WmT_lo[DSq*Dq];
__device__ __align__(16) __nv_bfloat16 g_Mc_hi[Dq*NEq*DSq],   g_Mc_lo[Dq*NEq*DSq];
__device__ __align__(16) __nv_bfloat16 g_W1_hi[256*DSq],      g_W1_lo[256*DSq];
__device__ __align__(16) float g_proj[ROWS*DSq];
__device__ __align__(16) float g_Q[ROWS*3*DSq];
__device__ __align__(16) float g_Mc[Dq*NEq*DSq];
__device__ __align__(16) float g_pbias[Dq];
__device__ __align__(16) float g_b1cat[256];
__device__ __align__(16) float g_W2cat[256];

// ---------------------------------------------------------------------------
// helpers
// ---------------------------------------------------------------------------
__device__ __forceinline__ unsigned long long fma_f32x2(unsigned long long a, unsigned long long b, unsigned long long c) {
    unsigned long long d;
    asm("fma.rn.f32x2 %0, %1, %2, %3;" : "=l"(d) : "l"(a), "l"(b), "l"(c));
    return d;
}
__device__ __forceinline__ float lo_f(unsigned long long v) { return __uint_as_float((uint32_t)v); }
__device__ __forceinline__ float hi_f(unsigned long long v) { return __uint_as_float((uint32_t)(v >> 32)); }

__device__ __forceinline__ uint32_t smem_u32(const void* p) {
    uint32_t a;
    asm("{ .reg .u64 t; cvta.to.shared.u64 t, %1; cvt.u32.u64 %0, t; }" : "=r"(a) : "l"(p));
    return a;
}
#define CP_COMMIT() asm volatile("cp.async.commit_group;" ::: "memory")
#define CP_WAIT0()  asm volatile("cp.async.wait_group 0;" ::: "memory")
#define CP_WAIT1()  asm volatile("cp.async.wait_group 1;" ::: "memory")

__device__ __forceinline__ void hilo(float v, __nv_bfloat16& h, __nv_bfloat16& l) {
    h = __float2bfloat16(v);
    l = __float2bfloat16(v - __bfloat162float(h));
}

// ---------------------------------------------------------------------------
// GEMM: block 128x128, BK=32, 512 threads = 16 warps (4x4), warp tile 32x32.
// Double-buffered cp.async. smem element offsets within a buffer:
//   Ahi 0, Alo 5120, Bhi 10240, Blo 15360 ; buffer stride 20480 elems.
// ---------------------------------------------------------------------------
#define BKT    32
#define LDSA   40
#define E_ALO  5120
#define E_BHI  10240
#define E_BLO  15360
#define E_BUF  20480
#define TILE_B 10240              // bytes per tile
#define BUF_B  40960              // bytes per buffer
#define SM_BYTES 81920

// stage one 128x32 bf16 tile: 512 x 16B, one per thread
__device__ __forceinline__ void stage_async(uint32_t sdst, const __nv_bfloat16* __restrict__ g,
                                            long long row0, int k0, int ld, int tid)
{
    int row = tid >> 2, q = tid & 3;
    uint32_t d = sdst + row * (LDSA * 2) + q * 16;
    const void* s = g + (row0 + row) * (long long)ld + k0 + q * 8;
    asm volatile("cp.async.cg.shared.global [%0], [%1], 16;" :: "r"(d), "l"(s));
}

__global__ __launch_bounds__(512, 1)
void gemm_tc(const __nv_bfloat16* __restrict__ Ahi, const __nv_bfloat16* __restrict__ Alo, int lda, int aK0z,
             const __nv_bfloat16* __restrict__ Bhi, const __nv_bfloat16* __restrict__ Blo, int ldb,
             float* __restrict__ C, int ldc, int cZoff,
             const float* __restrict__ bias, int nChunks,
             __nv_bfloat16* __restrict__ outH, __nv_bfloat16* __restrict__ outL)
{
    extern __shared__ __align__(16) char smem[];
    __nv_bfloat16* s16 = reinterpret_cast<__nv_bfloat16*>(smem);
    const uint32_t sb = smem_u32(smem);
    const int tid = threadIdx.x, wid = tid >> 5;
    const int wy = wid >> 2, wx = wid & 3;
    const long long m0 = (long long)blockIdx.y * 128;
    const int n0 = blockIdx.x * 128;
    const int aK0 = blockIdx.z * aK0z;
    const int cOff = n0 + blockIdx.z * cZoff;

    wmma::fragment<wmma::accumulator, 16, 16, 16, float> acc[2][2];
#pragma unroll
    for (int i = 0; i < 2; i++)
#pragma unroll
        for (int j = 0; j < 2; j++) wmma::fill_fragment(acc[i][j], 0.0f);

    // prologue
    {
        stage_async(sb,              Ahi, m0, aK0, lda, tid);
        stage_async(sb + TILE_B,     Alo, m0, aK0, lda, tid);
        stage_async(sb + 2 * TILE_B, Bhi, n0, 0,   ldb, tid);
        stage_async(sb + 3 * TILE_B, Blo, n0, 0,   ldb, tid);
        CP_COMMIT();
    }

    for (int c = 0; c < nChunks; c++) {
        if (c + 1 < nChunks) {
            uint32_t bn = sb + ((c + 1) & 1) * BUF_B;
            stage_async(bn,              Ahi, m0, aK0 + (c + 1) * BKT, lda, tid);
            stage_async(bn + TILE_B,     Alo, m0, aK0 + (c + 1) * BKT, lda, tid);
            stage_async(bn + 2 * TILE_B, Bhi, n0, (c + 1) * BKT, ldb, tid);
            stage_async(bn + 3 * TILE_B, Blo, n0, (c + 1) * BKT, ldb, tid);
            CP_COMMIT();
            CP_WAIT1();
        } else {
            CP_WAIT0();
        }
        __syncthreads();
        const __nv_bfloat16* base = s16 + (c & 1) * E_BUF;
#pragma unroll
        for (int ks = 0; ks < BKT; ks += 16) {
            wmma::fragment<wmma::matrix_b, 16, 16, 16, __nv_bfloat16, wmma::col_major> bh[2], bl[2];
#pragma unroll
            for (int fn = 0; fn < 2; fn++) {
                const int nb = wx * 32 + fn * 16;
                wmma::load_matrix_sync(bh[fn], base + E_BHI + nb * LDSA + ks, LDSA);
                wmma::load_matrix_sync(bl[fn], base + E_BLO + nb * LDSA + ks, LDSA);
            }
#pragma unroll
            for (int fm = 0; fm < 2; fm++) {
                const int mb = wy * 32 + fm * 16;
                wmma::fragment<wmma::matrix_a, 16, 16, 16, __nv_bfloat16, wmma::row_major> ah, al;
                wmma::load_matrix_sync(ah, base + mb * LDSA + ks, LDSA);
                wmma::load_matrix_sync(al, base + E_ALO + mb * LDSA + ks, LDSA);
#pragma unroll
                for (int fn = 0; fn < 2; fn++) {
                    wmma::mma_sync(acc[fm][fn], ah, bh[fn], acc[fm][fn]);
                    wmma::mma_sync(acc[fm][fn], ah, bl[fn], acc[fm][fn]);
                    wmma::mma_sync(acc[fm][fn], al, bh[fn], acc[fm][fn]);
                }
            }
        }
        __syncthreads();
    }

    // epilogue via smem C tile (64KB, reuses staging smem)
    float* Cs = reinterpret_cast<float*>(smem);
#pragma unroll
    for (int fm = 0; fm < 2; fm++)
#pragma unroll
        for (int fn = 0; fn < 2; fn++)
            wmma::store_matrix_sync(Cs + (wy * 32 + fm * 16) * 128 + wx * 32 + fn * 16,
                                    acc[fm][fn], 128, wmma::mem_row_major);
    __syncthreads();
#pragma unroll
    for (int it = 0; it < 8; it++) {
        int flat = it * 512 + tid;
        int row = flat >> 5, q = flat & 31;
        float4 v = *reinterpret_cast<const float4*>(Cs + row * 128 + q * 4);
        if (bias) {
            const float4 bv = *reinterpret_cast<const float4*>(bias + n0 + q * 4);
            v.x += bv.x; v.y += bv.y; v.z += bv.z; v.w += bv.w;
        }
        size_t co = (size_t)(m0 + row) * ldc + cOff + q * 4;
        *reinterpret_cast<float4*>(C + co) = v;
        if (outH) {
            __nv_bfloat16 h0,l0,h1,l1,h2,l2,h3,l3;
            hilo(v.x,h0,l0); hilo(v.y,h1,l1); hilo(v.z,h2,l2); hilo(v.w,h3,l3);
            __nv_bfloat162 ph0 = {h0,h1}, ph1 = {h2,h3}, pl0 = {l0,l1}, pl1 = {l2,l3};
            *reinterpret_cast<__nv_bfloat162*>(outH + co)     = ph0;
            *reinterpret_cast<__nv_bfloat162*>(outH + co + 2) = ph1;
            *reinterpret_cast<__nv_bfloat162*>(outL + co)     = pl0;
            *reinterpret_cast<__nv_bfloat162*>(outL + co + 2) = pl1;
        }
    }
}

// ---------------------------------------------------------------------------
// Heads GEMM (K=128) with fused GELU . W2 epilogue
// ---------------------------------------------------------------------------
__device__ __forceinline__ float gelu_exact(float x) {
    return 0.5f * x * (1.0f + erff(x * 0.70710678118654752f));
}

__global__ __launch_bounds__(512, 1)
void gemm_heads(const __nv_bfloat16* __restrict__ Ahi, const __nv_bfloat16* __restrict__ Alo,
                const __nv_bfloat16* __restrict__ Bhi, const __nv_bfloat16* __restrict__ Blo,
                const float* __restrict__ b1cat, const float* __restrict__ W2cat,
                const float* __restrict__ bh2, const float* __restrict__ bt2, const float* __restrict__ bv2,
                float* __restrict__ oH, float* __restrict__ oT, float* __restrict__ oV)
{
    extern __shared__ __align__(16) char smem[];
    __nv_bfloat16* s16 = reinterpret_cast<__nv_bfloat16*>(smem);
    const uint32_t sb = smem_u32(smem);
    const int tid = threadIdx.x, wid = tid >> 5;
    const int wy = wid >> 2, wx = wid & 3;
    const long long m0 = (long long)blockIdx.y * 128;
    const int n0 = blockIdx.x * 128;
    const int nChunks = 4;

    wmma::fragment<wmma::accumulator, 16, 16, 16, float> acc[2][2];
#pragma unroll
    for (int i = 0; i < 2; i++)
#pragma unroll
        for (int j = 0; j < 2; j++) wmma::fill_fragment(acc[i][j], 0.0f);

    {
        stage_async(sb,              Ahi, m0, 0, DSq, tid);
        stage_async(sb + TILE_B,     Alo, m0, 0, DSq, tid);
        stage_async(sb + 2 * TILE_B, Bhi, n0, 0, DSq, tid);
        stage_async(sb + 3 * TILE_B, Blo, n0, 0, DSq, tid);
        CP_COMMIT();
    }
    for (int c = 0; c < nChunks; c++) {
        if (c + 1 < nChunks) {
            uint32_t bn = sb + ((c + 1) & 1) * BUF_B;
            stage_async(bn,              Ahi, m0, (c + 1) * BKT, DSq, tid);
            stage_async(bn + TILE_B,     Alo, m0, (c + 1) * BKT, DSq, tid);
            stage_async(bn + 2 * TILE_B, Bhi, n0, (c + 1) * BKT, DSq, tid);
            stage_async(bn + 3 * TILE_B, Blo, n0, (c + 1) * BKT, DSq, tid);
            CP_COMMIT();
            CP_WAIT1();
        } else {
            CP_WAIT0();
        }
        __syncthreads();
        const __nv_bfloat16* base = s16 + (c & 1) * E_BUF;
#pragma unroll
        for (int ks = 0; ks < BKT; ks += 16) {
            wmma::fragment<wmma::matrix_b, 16, 16, 16, __nv_bfloat16, wmma::col_major> bh[2], bl[2];
#pragma unroll
            for (int fn = 0; fn < 2; fn++) {
                const int nb = wx * 32 + fn * 16;
                wmma::load_matrix_sync(bh[fn], base + E_BHI + nb * LDSA + ks, LDSA);
                wmma::load_matrix_sync(bl[fn], base + E_BLO + nb * LDSA + ks, LDSA);
            }
#pragma unroll
            for (int fm = 0; fm < 2; fm++) {
                const int mb = wy * 32 + fm * 16;
                wmma::fragment<wmma::matrix_a, 16, 16, 16, __nv_bfloat16, wmma::row_major> ah, al;
                wmma::load_matrix_sync(ah, base + mb * LDSA + ks, LDSA);
                wmma::load_matrix_sync(al, base + E_ALO + mb * LDSA + ks, LDSA);
#pragma unroll
                for (int fn = 0; fn < 2; fn++) {
                    wmma::mma_sync(acc[fm][fn], ah, bh[fn], acc[fm][fn]);
                    wmma::mma_sync(acc[fm][fn], ah, bl[fn], acc[fm][fn]);
                    wmma::mma_sync(acc[fm][fn], al, bh[fn], acc[fm][fn]);
                }
            }
        }
        __syncthreads();
    }

    float* Cs = reinterpret_cast<float*>(smem);
#pragma unroll
    for (int fm = 0; fm < 2; fm++)
#pragma unroll
        for (int fn = 0; fn < 2; fn++)
            wmma::store_matrix_sync(Cs + (wy * 32 + fm * 16) * 128 + wx * 32 + fn * 16,
                                    acc[fm][fn], 128, wmma::mem_row_major);
    __syncthreads();

    if (tid < 256) {
        const int row = tid >> 1, half = tid & 1;
        const int headIdx = blockIdx.x * 2 + half;
        if (headIdx < 3) {
            float dot = 0.f;
#pragma unroll
            for (int q = 0; q < 16; q++) {
                int qq = (q + row) & 15;
                float4 v = *reinterpret_cast<const float4*>(Cs + row * 128 + half * 64 + qq * 4);
                int col = n0 + half * 64 + qq * 4;
                dot = fmaf(gelu_exact(v.x + __ldg(b1cat + col + 0)), __ldg(W2cat + col + 0), dot);
                dot = fmaf(gelu_exact(v.y + __ldg(b1cat + col + 1)), __ldg(W2cat + col + 1), dot);
                dot = fmaf(gelu_exact(v.z + __ldg(b1cat + col + 2)), __ldg(W2cat + col + 2), dot);
                dot = fmaf(gelu_exact(v.w + __ldg(b1cat + col + 3)), __ldg(W2cat + col + 3), dot);
            }
            float* op = (headIdx == 0) ? oH : (headIdx == 1) ? oT : oV;
            float b2 = (headIdx == 0) ? __ldg(bh2) : (headIdx == 1) ? __ldg(bt2) : __ldg(bv2);
            op[m0 + row] = dot + b2;
        }
    }
}

// ---------------------------------------------------------------------------
// Weight prep
// ---------------------------------------------------------------------------
__global__ void prep_weights(const float* __restrict__ Wi, const float* __restrict__ W_ih,
                             const float* __restrict__ Wm, const float* __restrict__ Ws,
                             const float* __restrict__ Wh1, const float* __restrict__ Wt1,
                             const float* __restrict__ Wv1,
                             const float* __restrict__ bh1, const float* __restrict__ bt1,
                             const float* __restrict__ bv1,
                             const float* __restrict__ Wh2, const float* __restrict__ Wt2,
                             const float* __restrict__ Wv2)
{
    const int N_Wi = DSq * Dq, N_Wih = 3 * DSq * DSq, N_Wm = Dq * DSq;
    const int N_W1 = 256 * DSq;
    const long long N_Ws = (long long)Dq * NEq * Dq;
    long long idx = (long long)blockIdx.x * 256 + threadIdx.x;
    __nv_bfloat16 h, l;
    if (idx < N_Wi)  { hilo(Wi[idx], h, l);   g_Wi_hi[idx] = h;  g_Wi_lo[idx] = l;  return; }
    idx -= N_Wi;
    if (idx < N_Wih) { hilo(W_ih[idx], h, l); g_Wih_hi[idx] = h; g_Wih_lo[idx] = l; return; }
    idx -= N_Wih;
    if (idx < N_Wm)  { hilo(Wm[idx], h, l);   g_Wm_hi[idx] = h;  g_Wm_lo[idx] = l;  return; }
    idx -= N_Wm;
    if (idx < N_Wm) {
        int j = (int)(idx / DSq), k = (int)(idx % DSq);
        hilo(Wm[idx], h, l);
        g_WmT_hi[(size_t)k * Dq + j] = h; g_WmT_lo[(size_t)k * Dq + j] = l; return;
    }
    idx -= N_Wm;
    if (idx < N_W1) {
        int r = (int)(idx / DSq), c = (int)(idx % DSq);
        float v = (r < 64) ? Wh1[r * DSq + c] : (r < 128) ? Wt1[(r - 64) * DSq + c]
                : (r < 192) ? Wv1[(r - 128) * DSq + c] : 0.f;
        hilo(v, h, l); g_W1_hi[idx] = h; g_W1_lo[idx] = l; return;
    }
    idx -= N_W1;
    if (idx < 256) {
        int i = (int)idx;
        g_b1cat[i] = (i < 64) ? bh1[i] : (i < 128) ? bt1[i - 64] : (i < 192) ? bv1[i - 128] : 0.f;
        g_W2cat[i] = (i < 64) ? Wh2[i] : (i < 128) ? Wt2[i - 64] : (i < 192) ? Wv2[i - 128] : 0.f;
        return;
    }
    idx -= 256;
    if (idx < N_Ws) { hilo(Ws[idx], h, l); g_Ws_hi[idx] = h; g_Ws_lo[idx] = l; }
}
#define PREP_TOTAL (DSq*Dq + 3*DSq*DSq + Dq*DSq + Dq*DSq + 256*DSq + 256 + Dq*NEq*Dq)

// ---------------------------------------------------------------------------
// Route softmax + fused h_seq hi/lo conversion (row is already resident)
// ---------------------------------------------------------------------------
__global__ __launch_bounds__(256)
void route_cvt(const float* __restrict__ h_seq, const float* __restrict__ ek,
               float* __restrict__ rw,
               __nv_bfloat16* __restrict__ hi, __nv_bfloat16* __restrict__ lo)
{
    const int row = blockIdx.x;
    const int w = threadIdx.x >> 5, lane = threadIdx.x & 31;
    const float* hr = h_seq + (size_t)row * Dq;
    const float* er = ek + (size_t)w * Dq;
    float s = 0.f;
#pragma unroll 4
    for (int k = lane; k < Dq; k += 32) s = fmaf(hr[k], er[k], s);
#pragma unroll
    for (int o = 16; o; o >>= 1) s += __shfl_xor_sync(0xffffffffu, s, o);
    __shared__ float lg[NEq];
    if (lane == 0) lg[w] = s;

    // fused hi/lo conversion: 768 elems / 256 threads = 3 each
#pragma unroll
    for (int i = threadIdx.x; i < Dq; i += 256) {
        __nv_bfloat16 h, l; hilo(hr[i], h, l);
        hi[(size_t)row * Dq + i] = h;
        lo[(size_t)row * Dq + i] = l;
    }
    __syncthreads();
    if (threadIdx.x == 0) {
        const float inv = 0.036084391824351615f;
        float v[NEq], m = -1e30f;
#pragma unroll
        for (int e = 0; e < NEq; e++) { v[e] = lg[e] * inv; m = fmaxf(m, v[e]); }
        float den = 0.f;
#pragma unroll
        for (int e = 0; e < NEq; e++) { v[e] = __expf(v[e] - m); den += v[e]; }
        float id = 1.f / den;
#pragma unroll
        for (int e = 0; e < NEq; e++) rw[(size_t)row * NEq + e] = v[e] * id;
    }
}

__global__ __launch_bounds__(256)
void pbias_kernel(const float* __restrict__ Ws, const float* __restrict__ bm,
                  const float* __restrict__ bs, float* __restrict__ pb)
{
    int d = blockIdx.x, tid = threadIdx.x;
    float s = 0.f;
    for (int j = tid; j < NEq * Dq; j += 256) s = fmaf(bm[j % Dq], Ws[(size_t)d * (NEq * Dq) + j], s);
    __shared__ float red[256];
    red[tid] = s; __syncthreads();
    for (int o = 128; o; o >>= 1) { if (tid < o) red[tid] += red[tid + o]; __syncthreads(); }
    if (tid == 0) pb[d] = red[0] + bs[d];
}

// ---------------------------------------------------------------------------
// GRU scan: f32x2 matvec, prefetched Q/rw, fused bf16 hi/lo state write
// ---------------------------------------------------------------------------
__global__ __launch_bounds__(384, 1)
void gru_scan(const float* __restrict__ Q, const float* __restrict__ rw,
              const float* __restrict__ state0, const float* __restrict__ W_hh,
              const float* __restrict__ b_ih, const float* __restrict__ b_hh,
              float* __restrict__ state_out,
              __nv_bfloat16* __restrict__ sth, __nv_bfloat16* __restrict__ stl)
{
    const int b = blockIdx.x >> 3;
    const int e = blockIdx.x & 7;
    const int j = threadIdx.x;

    unsigned long long w2r[64];
    {
        const unsigned long long* wr = reinterpret_cast<const unsigned long long*>(W_hh + (size_t)j * DSq);
#pragma unroll
        for (int i = 0; i < 64; i++) w2r[i] = wr[i];
    }
    __shared__ __align__(16) float hbuf[DSq];
    __shared__ float gh[3 * DSq];

    if (j < 32) reinterpret_cast<float4*>(hbuf)[j] = reinterpret_cast<const float4*>(state0 + e * DSq)[j];
    const float bhh = b_hh[j];
    float bir = 0.f, biz = 0.f, bin = 0.f;
    if (j < DSq) { bir = b_ih[j]; biz = b_ih[DSq + j]; bin = b_ih[2 * DSq + j]; }
    __syncthreads();

    const ulonglong2* hs2 = reinterpret_cast<const ulonglong2*>(hbuf);

    // prefetch t=0
    float qr = 0.f, qz = 0.f, qn = 0.f, rwv = 0.f;
    if (j < DSq) {
        const float* qp = Q + (size_t)(b * Tq) * (3 * DSq);
        qr = qp[j]; qz = qp[DSq + j]; qn = qp[2 * DSq + j];
        rwv = rw[(size_t)(b * Tq) * NEq + e];
    }

    for (int t = 0; t < Tq; t++) {
        const int row = b * Tq + t;
        // issue next step's loads early (latency hidden behind matvec)
        float nqr = 0.f, nqz = 0.f, nqn = 0.f, nrw = 0.f;
        if (t + 1 < Tq && j < DSq) {
            const float* qp = Q + (size_t)(row + 1) * (3 * DSq);
            nqr = __ldg(qp + j); nqz = __ldg(qp + DSq + j); nqn = __ldg(qp + 2 * DSq + j);
            nrw = __ldg(rw + (size_t)(row + 1) * NEq + e);
        }
        unsigned long long a0 = 0, a1 = 0, a2 = 0, a3 = 0;
#pragma unroll
        for (int i = 0; i < 32; i += 2) {
            ulonglong2 h0 = hs2[i];
            ulonglong2 h1 = hs2[i + 1];
            a0 = fma_f32x2(w2r[i * 2 + 0], h0.x, a0);
            a1 = fma_f32x2(w2r[i * 2 + 1], h0.y, a1);
            a2 = fma_f32x2(w2r[i * 2 + 2], h1.x, a2);
            a3 = fma_f32x2(w2r[i * 2 + 3], h1.y, a3);
        }
        float acc = ((lo_f(a0) + hi_f(a0)) + (lo_f(a1) + hi_f(a1)))
                  + ((lo_f(a2) + hi_f(a2)) + (lo_f(a3) + hi_f(a3)));
        gh[j] = acc + bhh;
        __syncthreads();
        if (j < DSq) {
            float gir = fmaf(rwv, qr, bir);
            float giz = fmaf(rwv, qz, biz);
            float gin = fmaf(rwv, qn, bin);
            float r = __fdividef(1.f, 1.f + __expf(-(gir + gh[j])));
            float z = __fdividef(1.f, 1.f + __expf(-(giz + gh[DSq + j])));
            float xn = fmaf(r, gh[2 * DSq + j], gin);
            float ex = __expf(-2.f * xn);
            float n = __fdividef(1.f - ex, 1.f + ex);
            float hnew = fmaf(z, hbuf[j] - n, n);
            hbuf[j] = hnew;
            size_t idx = (((size_t)row) * NEq + e) * DSq + j;
            state_out[idx] = hnew;
            __nv_bfloat16 hh = __float2bfloat16(hnew);
            sth[idx] = hh;
            stl[idx] = __float2bfloat16(hnew - __bfloat162float(hh));
        }
        __syncthreads();
        qr = nqr; qz = nqz; qn = nqn; rwv = nrw;
    }
}

// ---------------------------------------------------------------------------
// Launch
// ---------------------------------------------------------------------------
extern "C" void kernel_launch(void* const* d_in, const int* in_sizes, int n_in,
                              void* d_out, int out_size)
{
    const float* h_seq = (const float*)d_in[0];
    const float* ek    = (const float*)d_in[1];
    const float* state0= (const float*)d_in[2];
    const float* Wi    = (const float*)d_in[3];
    const float* bi    = (const float*)d_in[4];
    const float* W_ih  = (const float*)d_in[5];
    const float* W_hh  = (const float*)d_in[6];
    const float* b_ih  = (const float*)d_in[7];
    const float* b_hh  = (const float*)d_in[8];
    const float* Wm    = (const float*)d_in[9];
    const float* bm    = (const float*)d_in[10];
    const float* Ws    = (const float*)d_in[11];
    const float* bs    = (const float*)d_in[12];
    const float* Wh1   = (const float*)d_in[13];
    const float* bh1   = (const float*)d_in[14];
    const float* Wh2   = (const float*)d_in[15];
    const float* bh2   = (const float*)d_in[16];
    const float* Wt1   = (const float*)d_in[17];
    const float* bt1   = (const float*)d_in[18];
    const float* Wt2   = (const float*)d_in[19];
    const float* bt2   = (const float*)d_in[20];
    const float* Wv1   = (const float*)d_in[21];
    const float* bv1   = (const float*)d_in[22];
    const float* Wv2   = (const float*)d_in[23];
    const float* bv2   = (const float*)d_in[24];
    float* out = (float*)d_out;

    cudaFuncSetAttribute(gemm_tc, cudaFuncAttributeMaxDynamicSharedMemorySize, SM_BYTES);
    cudaFuncSetAttribute(gemm_heads, cudaFuncAttributeMaxDynamicSharedMemorySize, SM_BYTES);

#define SYMF(p, s) float* p; cudaGetSymbolAddress((void**)&p, s)
#define SYMB(p, s) __nv_bfloat16* p; cudaGetSymbolAddress((void**)&p, s)
    SYMB(p_hsh, g_hseq_hi);  SYMB(p_hsl, g_hseq_lo);
    SYMB(p_sth, g_state_hi); SYMB(p_stl, g_state_lo);
    SYMB(p_prh, g_projh);    SYMB(p_prl, g_projl);
    SYMB(p_wsh, g_Ws_hi);    SYMB(p_wsl, g_Ws_lo);
    SYMB(p_wih, g_Wi_hi);    SYMB(p_wil, g_Wi_lo);
    SYMB(p_whh, g_Wih_hi);   SYMB(p_whl, g_Wih_lo);
    SYMB(p_wmh, g_Wm_hi);    SYMB(p_wml, g_Wm_lo);
    SYMB(p_wth, g_WmT_hi);   SYMB(p_wtl, g_WmT_lo);
    SYMB(p_mch, g_Mc_hi);    SYMB(p_mcl, g_Mc_lo);
    SYMB(p_w1h, g_W1_hi);    SYMB(p_w1l, g_W1_lo);
    SYMF(p_proj, g_proj); SYMF(p_Q, g_Q); SYMF(p_Mc, g_Mc); SYMF(p_pb, g_pbias);
    SYMF(p_b1, g_b1cat);  SYMF(p_w2, g_W2cat);

    // 1) prep + route(+cvt)
    prep_weights<<<(PREP_TOTAL + 255) / 256, 256>>>(Wi, W_ih, Wm, Ws, Wh1, Wt1, Wv1,
                                                    bh1, bt1, bv1, Wh2, Wt2, Wv2);
    route_cvt<<<ROWS, 256>>>(h_seq, ek, out + RW_OFF, p_hsh, p_hsl);

    // 2) proj = h_seq @ Wi^T + bi  [8192,128] K=768 (+ fused bf16 out)
    gemm_tc<<<dim3(1, ROWS / 128, 1), 512, SM_BYTES>>>(p_hsh, p_hsl, Dq, 0,
                                                       p_wih, p_wil, Dq,
                                                       p_proj, DSq, 0, bi, Dq / BKT,
                                                       p_prh, p_prl);

    // 3) Q = proj @ W_ih^T  [8192,384] K=128
    gemm_tc<<<dim3(3, ROWS / 128, 1), 512, SM_BYTES>>>(p_prh, p_prl, DSq, 0,
                                                       p_whh, p_whl, DSq,
                                                       p_Q, 3 * DSq, 0, nullptr, DSq / BKT,
                                                       nullptr, nullptr);

    // 4) Mc = per-entity Ws_e @ Wm (+ fused bf16 out) + pbias
    gemm_tc<<<dim3(1, Dq / 128, NEq), 512, SM_BYTES>>>(p_wsh, p_wsl, NEq * Dq, Dq,
                                                       p_wth, p_wtl, Dq,
                                                       p_Mc, NEq * DSq, DSq, nullptr, Dq / BKT,
                                                       p_mch, p_mcl);
    pbias_kernel<<<Dq, 256>>>(Ws, bm, bs, p_pb);

    // 5) GRU scan -> state_stack (output) + bf16 hi/lo fused
    gru_scan<<<Bq * NEq, 384>>>(p_Q, out + RW_OFF, state0, W_hh, b_ih, b_hh,
                                out + STATE_OFF, p_sth, p_stl);

    // 6) memory = state @ Wm^T + bm  [65536,768] K=128
    gemm_tc<<<dim3(Dq / 128, SROWS / 128, 1), 512, SM_BYTES>>>(p_sth, p_stl, DSq, 0,
                                                               p_wmh, p_wml, DSq,
                                                               out + MEM_OFF, Dq, 0, bm, DSq / BKT,
                                                               nullptr, nullptr);

    // 7) pooled = state_flat @ Mc^T + pbias  [8192,768] K=1024
    gemm_tc<<<dim3(Dq / 128, ROWS / 128, 1), 512, SM_BYTES>>>(p_sth, p_stl, NEq * DSq, 0,
                                                              p_mch, p_mcl, NEq * DSq,
                                                              out + POOLED_OFF, Dq, 0, p_pb, (NEq * DSq) / BKT,
                                                              nullptr, nullptr);

    // 8) heads fused -> holder/tagged/visible
    gemm_heads<<<dim3(2, SROWS / 128, 1), 512, SM_BYTES>>>(p_sth, p_stl, p_w1h, p_w1l,
                                                           p_b1, p_w2, bh2, bt2, bv2,
                                                           out + HOLDER_OFF, out + TAGGED_OFF, out + VISIBLE_OFF);

    (void)in_sizes; (void)n_in; (void)out_size;
}

// round 7
// speedup vs baseline: 1.7771x; 1.0005x over previous
#include <cuda_runtime.h>
#include <cuda_bf16.h>
#include <mma.h>
#include <math.h>
#include <stdint.h>

using namespace nvcuda;

#define Bq   8
#define Tq   1024
#define Dq   768
#define NEq  8
#define DSq  128
#define ROWS (Bq*Tq)            // 8192
#define SROWS (Bq*Tq*NEq)       // 65536

#define POOLED_OFF  0ll
#define MEM_OFF     6291456ll
#define STATE_OFF   56623104ll
#define HOLDER_OFF  65011712ll
#define TAGGED_OFF  65077248ll
#define VISIBLE_OFF 65142784ll
#define RW_OFF      65208320ll

// ---------------------------------------------------------------------------
// Scratch (16B-aligned for cp.async)
// ---------------------------------------------------------------------------
__device__ __align__(16) __nv_bfloat16 g_hseq_hi[ROWS*Dq],    g_hseq_lo[ROWS*Dq];
__device__ __align__(16) __nv_bfloat16 g_state_hi[SROWS*DSq], g_state_lo[SROWS*DSq];
__device__ __align__(16) __nv_bfloat16 g_projh[ROWS*DSq],     g_projl[ROWS*DSq];
__device__ __align__(16) __nv_bfloat16 g_Ws_hi[Dq*NEq*Dq],    g_Ws_lo[Dq*NEq*Dq];
__device__ __align__(16) __nv_bfloat16 g_Wi_hi[DSq*Dq],       g_Wi_lo[DSq*Dq];
__device__ __align__(16) __nv_bfloat16 g_Wih_hi[3*DSq*DSq],   g_Wih_lo[3*DSq*DSq];
__device__ __align__(16) __nv_bfloat16 g_Wm_hi[Dq*DSq],       g_Wm_lo[Dq*DSq];
__device__ __align__(16) __nv_bfloat16 g_WmT_hi[DSq*Dq],      g_WmT_lo[DSq*Dq];
__device__ __align__(16) __nv_bfloat16 g_Mc_hi[Dq*NEq*DSq],   g_Mc_lo[Dq*NEq*DSq];
__device__ __align__(16) __nv_bfloat16 g_W1_hi[256*DSq],      g_W1_lo[256*DSq];
__device__ __align__(16) float g_Q[ROWS*3*DSq];
__device__ __align__(16) float g_pbias[Dq];
__device__ __align__(16) float g_b1cat[256];
__device__ __align__(16) float g_W2cat[256];

// ---------------------------------------------------------------------------
// helpers
// ---------------------------------------------------------------------------
__device__ __forceinline__ unsigned long long fma_f32x2(unsigned long long a, unsigned long long b, unsigned long long c) {
    unsigned long long d;
    asm("fma.rn.f32x2 %0, %1, %2, %3;" : "=l"(d) : "l"(a), "l"(b), "l"(c));
    return d;
}
__device__ __forceinline__ float lo_f(unsigned long long v) { return __uint_as_float((uint32_t)v); }
__device__ __forceinline__ float hi_f(unsigned long long v) { return __uint_as_float((uint32_t)(v >> 32)); }

__device__ __forceinline__ uint32_t smem_u32(const void* p) {
    uint32_t a;
    asm("{ .reg .u64 t; cvta.to.shared.u64 t, %1; cvt.u32.u64 %0, t; }" : "=r"(a) : "l"(p));
    return a;
}
#define CP_COMMIT() asm volatile("cp.async.commit_group;" ::: "memory")
#define CP_WAIT0()  asm volatile("cp.async.wait_group 0;" ::: "memory")
#define CP_WAIT1()  asm volatile("cp.async.wait_group 1;" ::: "memory")
#define CP_WAIT2()  asm volatile("cp.async.wait_group 2;" ::: "memory")

__device__ __forceinline__ void hilo(float v, __nv_bfloat16& h, __nv_bfloat16& l) {
    h = __float2bfloat16(v);
    l = __float2bfloat16(v - __bfloat162float(h));
}

// ---------------------------------------------------------------------------
// GEMM: block 128x128, BK=32, 512 threads = 16 warps (4x4), warp tile 32x32.
// 3-stage cp.async pipeline. smem element offsets within a buffer:
//   Ahi 0, Alo 5120, Bhi 10240, Blo 15360 ; buffer stride 20480 elems.
// ---------------------------------------------------------------------------
#define BKT    32
#define LDSA   40
#define E_ALO  5120
#define E_BHI  10240
#define E_BLO  15360
#define E_BUF  20480
#define TILE_B 10240              // bytes per tile
#define BUF_B  40960              // bytes per buffer
#define SM_BYTES 122880           // 3 buffers; epilogue C (64KB) reuses this

// stage one 128x32 bf16 tile: 512 x 16B, one per thread
__device__ __forceinline__ void stage_async(uint32_t sdst, const __nv_bfloat16* __restrict__ g,
                                            long long row0, int k0, int ld, int tid)
{
    int row = tid >> 2, q = tid & 3;
    uint32_t d = sdst + row * (LDSA * 2) + q * 16;
    const void* s = g + (row0 + row) * (long long)ld + k0 + q * 8;
    asm volatile("cp.async.cg.shared.global [%0], [%1], 16;" :: "r"(d), "l"(s));
}

__device__ __forceinline__ void stage4(uint32_t bufb,
                                       const __nv_bfloat16* Ahi, const __nv_bfloat16* Alo,
                                       const __nv_bfloat16* Bhi, const __nv_bfloat16* Blo,
                                       long long m0, int n0, int ka, int kb, int lda, int ldb, int tid)
{
    stage_async(bufb,              Ahi, m0, ka, lda, tid);
    stage_async(bufb + TILE_B,     Alo, m0, ka, lda, tid);
    stage_async(bufb + 2 * TILE_B, Bhi, n0, kb, ldb, tid);
    stage_async(bufb + 3 * TILE_B, Blo, n0, kb, ldb, tid);
    CP_COMMIT();
}

__global__ __launch_bounds__(512, 1)
void gemm_tc(const __nv_bfloat16* __restrict__ Ahi, const __nv_bfloat16* __restrict__ Alo, int lda, int aK0z,
             const __nv_bfloat16* __restrict__ Bhi, const __nv_bfloat16* __restrict__ Blo, int ldb,
             float* __restrict__ C, int ldc, int cZoff,
             const float* __restrict__ bias, int nChunks,
             __nv_bfloat16* __restrict__ outH, __nv_bfloat16* __restrict__ outL)
{
    extern __shared__ __align__(16) char smem[];
    __nv_bfloat16* s16 = reinterpret_cast<__nv_bfloat16*>(smem);
    const uint32_t sb = smem_u32(smem);
    const int tid = threadIdx.x, wid = tid >> 5;
    const int wy = wid >> 2, wx = wid & 3;
    const long long m0 = (long long)blockIdx.y * 128;
    const int n0 = blockIdx.x * 128;
    const int aK0 = blockIdx.z * aK0z;
    const int cOff = n0 + blockIdx.z * cZoff;

    wmma::fragment<wmma::accumulator, 16, 16, 16, float> acc[2][2];
#pragma unroll
    for (int i = 0; i < 2; i++)
#pragma unroll
        for (int j = 0; j < 2; j++) wmma::fill_fragment(acc[i][j], 0.0f);

    // prologue: chunks 0,1 into buffers 0,1
    stage4(sb,         Ahi, Alo, Bhi, Blo, m0, n0, aK0,       0,       lda, ldb, tid);
    stage4(sb + BUF_B, Ahi, Alo, Bhi, Blo, m0, n0, aK0 + BKT, BKT,     lda, ldb, tid);

    for (int c = 0; c < nChunks; c++) {
        if (c + 2 < nChunks) {
            stage4(sb + ((c + 2) % 3) * BUF_B, Ahi, Alo, Bhi, Blo, m0, n0,
                   aK0 + (c + 2) * BKT, (c + 2) * BKT, lda, ldb, tid);
            CP_WAIT2();
        } else if (c + 1 < nChunks) {
            CP_WAIT1();
        } else {
            CP_WAIT0();
        }
        __syncthreads();
        const __nv_bfloat16* base = s16 + (c % 3) * E_BUF;
#pragma unroll
        for (int ks = 0; ks < BKT; ks += 16) {
            wmma::fragment<wmma::matrix_b, 16, 16, 16, __nv_bfloat16, wmma::col_major> bh[2], bl[2];
#pragma unroll
            for (int fn = 0; fn < 2; fn++) {
                const int nb = wx * 32 + fn * 16;
                wmma::load_matrix_sync(bh[fn], base + E_BHI + nb * LDSA + ks, LDSA);
                wmma::load_matrix_sync(bl[fn], base + E_BLO + nb * LDSA + ks, LDSA);
            }
#pragma unroll
            for (int fm = 0; fm < 2; fm++) {
                const int mb = wy * 32 + fm * 16;
                wmma::fragment<wmma::matrix_a, 16, 16, 16, __nv_bfloat16, wmma::row_major> ah, al;
                wmma::load_matrix_sync(ah, base + mb * LDSA + ks, LDSA);
                wmma::load_matrix_sync(al, base + E_ALO + mb * LDSA + ks, LDSA);
#pragma unroll
                for (int fn = 0; fn < 2; fn++) {
                    wmma::mma_sync(acc[fm][fn], ah, bh[fn], acc[fm][fn]);
                    wmma::mma_sync(acc[fm][fn], ah, bl[fn], acc[fm][fn]);
                    wmma::mma_sync(acc[fm][fn], al, bh[fn], acc[fm][fn]);
                }
            }
        }
        __syncthreads();
    }

    // epilogue via smem C tile (64KB, reuses staging smem)
    float* Cs = reinterpret_cast<float*>(smem);
#pragma unroll
    for (int fm = 0; fm < 2; fm++)
#pragma unroll
        for (int fn = 0; fn < 2; fn++)
            wmma::store_matrix_sync(Cs + (wy * 32 + fm * 16) * 128 + wx * 32 + fn * 16,
                                    acc[fm][fn], 128, wmma::mem_row_major);
    __syncthreads();
#pragma unroll
    for (int it = 0; it < 8; it++) {
        int flat = it * 512 + tid;
        int row = flat >> 5, q = flat & 31;
        float4 v = *reinterpret_cast<const float4*>(Cs + row * 128 + q * 4);
        if (bias) {
            const float4 bv = *reinterpret_cast<const float4*>(bias + n0 + q * 4);
            v.x += bv.x; v.y += bv.y; v.z += bv.z; v.w += bv.w;
        }
        size_t co = (size_t)(m0 + row) * ldc + cOff + q * 4;
        if (C) *reinterpret_cast<float4*>(C + co) = v;
        if (outH) {
            __nv_bfloat16 h0,l0,h1,l1,h2,l2,h3,l3;
            hilo(v.x,h0,l0); hilo(v.y,h1,l1); hilo(v.z,h2,l2); hilo(v.w,h3,l3);
            __nv_bfloat162 ph0 = {h0,h1}, ph1 = {h2,h3}, pl0 = {l0,l1}, pl1 = {l2,l3};
            *reinterpret_cast<__nv_bfloat162*>(outH + co)     = ph0;
            *reinterpret_cast<__nv_bfloat162*>(outH + co + 2) = ph1;
            *reinterpret_cast<__nv_bfloat162*>(outL + co)     = pl0;
            *reinterpret_cast<__nv_bfloat162*>(outL + co + 2) = pl1;
        }
    }
}

// ---------------------------------------------------------------------------
// Heads GEMM (K=128) with fused GELU . W2 epilogue
// ---------------------------------------------------------------------------
__device__ __forceinline__ float gelu_exact(float x) {
    return 0.5f * x * (1.0f + erff(x * 0.70710678118654752f));
}

__global__ __launch_bounds__(512, 1)
void gemm_heads(const __nv_bfloat16* __restrict__ Ahi, const __nv_bfloat16* __restrict__ Alo,
                const __nv_bfloat16* __restrict__ Bhi, const __nv_bfloat16* __restrict__ Blo,
                const float* __restrict__ b1cat, const float* __restrict__ W2cat,
                const float* __restrict__ bh2, const float* __restrict__ bt2, const float* __restrict__ bv2,
                float* __restrict__ oH, float* __restrict__ oT, float* __restrict__ oV)
{
    extern __shared__ __align__(16) char smem[];
    __nv_bfloat16* s16 = reinterpret_cast<__nv_bfloat16*>(smem);
    const uint32_t sb = smem_u32(smem);
    const int tid = threadIdx.x, wid = tid >> 5;
    const int wy = wid >> 2, wx = wid & 3;
    const long long m0 = (long long)blockIdx.y * 128;
    const int n0 = blockIdx.x * 128;
    const int nChunks = 4;

    wmma::fragment<wmma::accumulator, 16, 16, 16, float> acc[2][2];
#pragma unroll
    for (int i = 0; i < 2; i++)
#pragma unroll
        for (int j = 0; j < 2; j++) wmma::fill_fragment(acc[i][j], 0.0f);

    stage4(sb,         Ahi, Alo, Bhi, Blo, m0, n0, 0,   0,   DSq, DSq, tid);
    stage4(sb + BUF_B, Ahi, Alo, Bhi, Blo, m0, n0, BKT, BKT, DSq, DSq, tid);

    for (int c = 0; c < nChunks; c++) {
        if (c + 2 < nChunks) {
            stage4(sb + ((c + 2) % 3) * BUF_B, Ahi, Alo, Bhi, Blo, m0, n0,
                   (c + 2) * BKT, (c + 2) * BKT, DSq, DSq, tid);
            CP_WAIT2();
        } else if (c + 1 < nChunks) {
            CP_WAIT1();
        } else {
            CP_WAIT0();
        }
        __syncthreads();
        const __nv_bfloat16* base = s16 + (c % 3) * E_BUF;
#pragma unroll
        for (int ks = 0; ks < BKT; ks += 16) {
            wmma::fragment<wmma::matrix_b, 16, 16, 16, __nv_bfloat16, wmma::col_major> bh[2], bl[2];
#pragma unroll
            for (int fn = 0; fn < 2; fn++) {
                const int nb = wx * 32 + fn * 16;
                wmma::load_matrix_sync(bh[fn], base + E_BHI + nb * LDSA + ks, LDSA);
                wmma::load_matrix_sync(bl[fn], base + E_BLO + nb * LDSA + ks, LDSA);
            }
#pragma unroll
            for (int fm = 0; fm < 2; fm++) {
                const int mb = wy * 32 + fm * 16;
                wmma::fragment<wmma::matrix_a, 16, 16, 16, __nv_bfloat16, wmma::row_major> ah, al;
                wmma::load_matrix_sync(ah, base + mb * LDSA + ks, LDSA);
                wmma::load_matrix_sync(al, base + E_ALO + mb * LDSA + ks, LDSA);
#pragma unroll
                for (int fn = 0; fn < 2; fn++) {
                    wmma::mma_sync(acc[fm][fn], ah, bh[fn], acc[fm][fn]);
                    wmma::mma_sync(acc[fm][fn], ah, bl[fn], acc[fm][fn]);
                    wmma::mma_sync(acc[fm][fn], al, bh[fn], acc[fm][fn]);
                }
            }
        }
        __syncthreads();
    }

    float* Cs = reinterpret_cast<float*>(smem);
#pragma unroll
    for (int fm = 0; fm < 2; fm++)
#pragma unroll
        for (int fn = 0; fn < 2; fn++)
            wmma::store_matrix_sync(Cs + (wy * 32 + fm * 16) * 128 + wx * 32 + fn * 16,
                                    acc[fm][fn], 128, wmma::mem_row_major);
    __syncthreads();

    if (tid < 256) {
        const int row = tid >> 1, half = tid & 1;
        const int headIdx = blockIdx.x * 2 + half;
        if (headIdx < 3) {
            float dot = 0.f;
#pragma unroll
            for (int q = 0; q < 16; q++) {
                int qq = (q + row) & 15;
                float4 v = *reinterpret_cast<const float4*>(Cs + row * 128 + half * 64 + qq * 4);
                int col = n0 + half * 64 + qq * 4;
                dot = fmaf(gelu_exact(v.x + __ldg(b1cat + col + 0)), __ldg(W2cat + col + 0), dot);
                dot = fmaf(gelu_exact(v.y + __ldg(b1cat + col + 1)), __ldg(W2cat + col + 1), dot);
                dot = fmaf(gelu_exact(v.z + __ldg(b1cat + col + 2)), __ldg(W2cat + col + 2), dot);
                dot = fmaf(gelu_exact(v.w + __ldg(b1cat + col + 3)), __ldg(W2cat + col + 3), dot);
            }
            float* op = (headIdx == 0) ? oH : (headIdx == 1) ? oT : oV;
            float b2 = (headIdx == 0) ? __ldg(bh2) : (headIdx == 1) ? __ldg(bt2) : __ldg(bv2);
            op[m0 + row] = dot + b2;
        }
    }
}

// ---------------------------------------------------------------------------
// Weight prep
// ---------------------------------------------------------------------------
__global__ void prep_weights(const float* __restrict__ Wi, const float* __restrict__ W_ih,
                             const float* __restrict__ Wm, const float* __restrict__ Ws,
                             const float* __restrict__ Wh1, const float* __restrict__ Wt1,
                             const float* __restrict__ Wv1,
                             const float* __restrict__ bh1, const float* __restrict__ bt1,
                             const float* __restrict__ bv1,
                             const float* __restrict__ Wh2, const float* __restrict__ Wt2,
                             const float* __restrict__ Wv2)
{
    const int N_Wi = DSq * Dq, N_Wih = 3 * DSq * DSq, N_Wm = Dq * DSq;
    const int N_W1 = 256 * DSq;
    const long long N_Ws = (long long)Dq * NEq * Dq;
    long long idx = (long long)blockIdx.x * 256 + threadIdx.x;
    __nv_bfloat16 h, l;
    if (idx < N_Wi)  { hilo(Wi[idx], h, l);   g_Wi_hi[idx] = h;  g_Wi_lo[idx] = l;  return; }
    idx -= N_Wi;
    if (idx < N_Wih) { hilo(W_ih[idx], h, l); g_Wih_hi[idx] = h; g_Wih_lo[idx] = l; return; }
    idx -= N_Wih;
    if (idx < N_Wm)  { hilo(Wm[idx], h, l);   g_Wm_hi[idx] = h;  g_Wm_lo[idx] = l;  return; }
    idx -= N_Wm;
    if (idx < N_Wm) {
        int j = (int)(idx / DSq), k = (int)(idx % DSq);
        hilo(Wm[idx], h, l);
        g_WmT_hi[(size_t)k * Dq + j] = h; g_WmT_lo[(size_t)k * Dq + j] = l; return;
    }
    idx -= N_Wm;
    if (idx < N_W1) {
        int r = (int)(idx / DSq), c = (int)(idx % DSq);
        float v = (r < 64) ? Wh1[r * DSq + c] : (r < 128) ? Wt1[(r - 64) * DSq + c]
                : (r < 192) ? Wv1[(r - 128) * DSq + c] : 0.f;
        hilo(v, h, l); g_W1_hi[idx] = h; g_W1_lo[idx] = l; return;
    }
    idx -= N_W1;
    if (idx < 256) {
        int i = (int)idx;
        g_b1cat[i] = (i < 64) ? bh1[i] : (i < 128) ? bt1[i - 64] : (i < 192) ? bv1[i - 128] : 0.f;
        g_W2cat[i] = (i < 64) ? Wh2[i] : (i < 128) ? Wt2[i - 64] : (i < 192) ? Wv2[i - 128] : 0.f;
        return;
    }
    idx -= 256;
    if (idx < N_Ws) { hilo(Ws[idx], h, l); g_Ws_hi[idx] = h; g_Ws_lo[idx] = l; }
}
#define PREP_TOTAL (DSq*Dq + 3*DSq*DSq + Dq*DSq + Dq*DSq + 256*DSq + 256 + Dq*NEq*Dq)

// ---------------------------------------------------------------------------
// Route softmax + fused h_seq hi/lo conversion
// ---------------------------------------------------------------------------
__global__ __launch_bounds__(256)
void route_cvt(const float* __restrict__ h_seq, const float* __restrict__ ek,
               float* __restrict__ rw,
               __nv_bfloat16* __restrict__ hi, __nv_bfloat16* __restrict__ lo)
{
    const int row = blockIdx.x;
    const int w = threadIdx.x >> 5, lane = threadIdx.x & 31;
    const float* hr = h_seq + (size_t)row * Dq;
    const float* er = ek + (size_t)w * Dq;
    float s = 0.f;
#pragma unroll 4
    for (int k = lane; k < Dq; k += 32) s = fmaf(hr[k], er[k], s);
#pragma unroll
    for (int o = 16; o; o >>= 1) s += __shfl_xor_sync(0xffffffffu, s, o);
    __shared__ float lg[NEq];
    if (lane == 0) lg[w] = s;

#pragma unroll
    for (int i = threadIdx.x; i < Dq; i += 256) {
        __nv_bfloat16 h, l; hilo(hr[i], h, l);
        hi[(size_t)row * Dq + i] = h;
        lo[(size_t)row * Dq + i] = l;
    }
    __syncthreads();
    if (threadIdx.x == 0) {
        const float inv = 0.036084391824351615f;
        float v[NEq], m = -1e30f;
#pragma unroll
        for (int e = 0; e < NEq; e++) { v[e] = lg[e] * inv; m = fmaxf(m, v[e]); }
        float den = 0.f;
#pragma unroll
        for (int e = 0; e < NEq; e++) { v[e] = __expf(v[e] - m); den += v[e]; }
        float id = 1.f / den;
#pragma unroll
        for (int e = 0; e < NEq; e++) rw[(size_t)row * NEq + e] = v[e] * id;
    }
}

__global__ __launch_bounds__(256)
void pbias_kernel(const float* __restrict__ Ws, const float* __restrict__ bm,
                  const float* __restrict__ bs, float* __restrict__ pb)
{
    int d = blockIdx.x, tid = threadIdx.x;
    float s = 0.f;
    for (int j = tid; j < NEq * Dq; j += 256) s = fmaf(bm[j % Dq], Ws[(size_t)d * (NEq * Dq) + j], s);
    __shared__ float red[256];
    red[tid] = s; __syncthreads();
    for (int o = 128; o; o >>= 1) { if (tid < o) red[tid] += red[tid + o]; __syncthreads(); }
    if (tid == 0) pb[d] = red[0] + bs[d];
}

// ---------------------------------------------------------------------------
// GRU scan: f32x2 matvec, prefetched Q/rw; bf16 hi/lo stores for row t-1
// handled by warp-groups 1/2 during the matvec window (hbuf stable there).
// ---------------------------------------------------------------------------
__global__ __launch_bounds__(384, 1)
void gru_scan(const float* __restrict__ Q, const float* __restrict__ rw,
              const float* __restrict__ state0, const float* __restrict__ W_hh,
              const float* __restrict__ b_ih, const float* __restrict__ b_hh,
              float* __restrict__ state_out,
              __nv_bfloat16* __restrict__ sth, __nv_bfloat16* __restrict__ stl)
{
    const int b = blockIdx.x >> 3;
    const int e = blockIdx.x & 7;
    const int j = threadIdx.x;
    const int grp = j >> 7;           // 0,1,2
    const int jm = j & 127;

    unsigned long long w2r[64];
    {
        const unsigned long long* wr = reinterpret_cast<const unsigned long long*>(W_hh + (size_t)j * DSq);
#pragma unroll
        for (int i = 0; i < 64; i++) w2r[i] = wr[i];
    }
    __shared__ __align__(16) float hbuf[DSq];
    __shared__ float gh[3 * DSq];

    if (j < 32) reinterpret_cast<float4*>(hbuf)[j] = reinterpret_cast<const float4*>(state0 + e * DSq)[j];
    const float bhh = b_hh[j];
    float bir = 0.f, biz = 0.f, bin = 0.f;
    if (j < DSq) { bir = b_ih[j]; biz = b_ih[DSq + j]; bin = b_ih[2 * DSq + j]; }
    __syncthreads();

    const ulonglong2* hs2 = reinterpret_cast<const ulonglong2*>(hbuf);

    // prefetch t=0
    float qr = 0.f, qz = 0.f, qn = 0.f, rwv = 0.f;
    if (j < DSq) {
        const float* qp = Q + (size_t)(b * Tq) * (3 * DSq);
        qr = qp[j]; qz = qp[DSq + j]; qn = qp[2 * DSq + j];
        rwv = rw[(size_t)(b * Tq) * NEq + e];
    }

    for (int t = 0; t < Tq; t++) {
        const int row = b * Tq + t;
        // prefetch next step's q/rw
        float nqr = 0.f, nqz = 0.f, nqn = 0.f, nrw = 0.f;
        if (t + 1 < Tq && j < DSq) {
            const float* qp = Q + (size_t)(row + 1) * (3 * DSq);
            nqr = __ldg(qp + j); nqz = __ldg(qp + DSq + j); nqn = __ldg(qp + 2 * DSq + j);
            nrw = __ldg(rw + (size_t)(row + 1) * NEq + e);
        }
        // groups 1/2: store bf16 hi/lo of row t-1 while hbuf is stable
        if (grp && t > 0) {
            float hv = hbuf[jm];
            __nv_bfloat16 hh = __float2bfloat16(hv);
            size_t pidx = (((size_t)(row - 1)) * NEq + e) * DSq + jm;
            if (grp == 1) sth[pidx] = hh;
            else          stl[pidx] = __float2bfloat16(hv - __bfloat162float(hh));
        }
        unsigned long long a0 = 0, a1 = 0, a2 = 0, a3 = 0;
#pragma unroll
        for (int i = 0; i < 32; i += 2) {
            ulonglong2 h0 = hs2[i];
            ulonglong2 h1 = hs2[i + 1];
            a0 = fma_f32x2(w2r[i * 2 + 0], h0.x, a0);
            a1 = fma_f32x2(w2r[i * 2 + 1], h0.y, a1);
            a2 = fma_f32x2(w2r[i * 2 + 2], h1.x, a2);
            a3 = fma_f32x2(w2r[i * 2 + 3], h1.y, a3);
        }
        float acc = ((lo_f(a0) + hi_f(a0)) + (lo_f(a1) + hi_f(a1)))
                  + ((lo_f(a2) + hi_f(a2)) + (lo_f(a3) + hi_f(a3)));
        gh[j] = acc + bhh;
        __syncthreads();
        if (j < DSq) {
            float gir = fmaf(rwv, qr, bir);
            float giz = fmaf(rwv, qz, biz);
            float gin = fmaf(rwv, qn, bin);
            float r = __fdividef(1.f, 1.f + __expf(-(gir + gh[j])));
            float z = __fdividef(1.f, 1.f + __expf(-(giz + gh[DSq + j])));
            float xn = fmaf(r, gh[2 * DSq + j], gin);
            float ex = __expf(-2.f * xn);
            float n = __fdividef(1.f - ex, 1.f + ex);
            float hnew = fmaf(z, hbuf[j] - n, n);
            hbuf[j] = hnew;
            state_out[(((size_t)row) * NEq + e) * DSq + j] = hnew;
        }
        __syncthreads();
        qr = nqr; qz = nqz; qn = nqn; rwv = nrw;
    }
    // final row's bf16 stores
    if (grp) {
        float hv = hbuf[jm];
        __nv_bfloat16 hh = __float2bfloat16(hv);
        size_t pidx = (((size_t)(b * Tq + Tq - 1)) * NEq + e) * DSq + jm;
        if (grp == 1) sth[pidx] = hh;
        else          stl[pidx] = __float2bfloat16(hv - __bfloat162float(hh));
    }
}

// ---------------------------------------------------------------------------
// Launch
// ---------------------------------------------------------------------------
extern "C" void kernel_launch(void* const* d_in, const int* in_sizes, int n_in,
                              void* d_out, int out_size)
{
    const float* h_seq = (const float*)d_in[0];
    const float* ek    = (const float*)d_in[1];
    const float* state0= (const float*)d_in[2];
    const float* Wi    = (const float*)d_in[3];
    const float* bi    = (const float*)d_in[4];
    const float* W_ih  = (const float*)d_in[5];
    const float* W_hh  = (const float*)d_in[6];
    const float* b_ih  = (const float*)d_in[7];
    const float* b_hh  = (const float*)d_in[8];
    const float* Wm    = (const float*)d_in[9];
    const float* bm    = (const float*)d_in[10];
    const float* Ws    = (const float*)d_in[11];
    const float* bs    = (const float*)d_in[12];
    const float* Wh1   = (const float*)d_in[13];
    const float* bh1   = (const float*)d_in[14];
    const float* Wh2   = (const float*)d_in[15];
    const float* bh2   = (const float*)d_in[16];
    const float* Wt1   = (const float*)d_in[17];
    const float* bt1   = (const float*)d_in[18];
    const float* Wt2   = (const float*)d_in[19];
    const float* bt2   = (const float*)d_in[20];
    const float* Wv1   = (const float*)d_in[21];
    const float* bv1   = (const float*)d_in[22];
    const float* Wv2   = (const float*)d_in[23];
    const float* bv2   = (const float*)d_in[24];
    float* out = (float*)d_out;

    cudaFuncSetAttribute(gemm_tc, cudaFuncAttributeMaxDynamicSharedMemorySize, SM_BYTES);
    cudaFuncSetAttribute(gemm_heads, cudaFuncAttributeMaxDynamicSharedMemorySize, SM_BYTES);

#define SYMF(p, s) float* p; cudaGetSymbolAddress((void**)&p, s)
#define SYMB(p, s) __nv_bfloat16* p; cudaGetSymbolAddress((void**)&p, s)
    SYMB(p_hsh, g_hseq_hi);  SYMB(p_hsl, g_hseq_lo);
    SYMB(p_sth, g_state_hi); SYMB(p_stl, g_state_lo);
    SYMB(p_prh, g_projh);    SYMB(p_prl, g_projl);
    SYMB(p_wsh, g_Ws_hi);    SYMB(p_wsl, g_Ws_lo);
    SYMB(p_wih, g_Wi_hi);    SYMB(p_wil, g_Wi_lo);
    SYMB(p_whh, g_Wih_hi);   SYMB(p_whl, g_Wih_lo);
    SYMB(p_wmh, g_Wm_hi);    SYMB(p_wml, g_Wm_lo);
    SYMB(p_wth, g_WmT_hi);   SYMB(p_wtl, g_WmT_lo);
    SYMB(p_mch, g_Mc_hi);    SYMB(p_mcl, g_Mc_lo);
    SYMB(p_w1h, g_W1_hi);    SYMB(p_w1l, g_W1_lo);
    SYMF(p_Q, g_Q); SYMF(p_pb, g_pbias);
    SYMF(p_b1, g_b1cat);  SYMF(p_w2, g_W2cat);

    // 1) prep + route(+cvt)
    prep_weights<<<(PREP_TOTAL + 255) / 256, 256>>>(Wi, W_ih, Wm, Ws, Wh1, Wt1, Wv1,
                                                    bh1, bt1, bv1, Wh2, Wt2, Wv2);
    route_cvt<<<ROWS, 256>>>(h_seq, ek, out + RW_OFF, p_hsh, p_hsl);

    // 2) proj = h_seq @ Wi^T + bi  [8192,128] K=768  (bf16 hi/lo only)
    gemm_tc<<<dim3(1, ROWS / 128, 1), 512, SM_BYTES>>>(p_hsh, p_hsl, Dq, 0,
                                                       p_wih, p_wil, Dq,
                                                       nullptr, DSq, 0, bi, Dq / BKT,
                                                       p_prh, p_prl);

    // 3) Q = proj @ W_ih^T  [8192,384] K=128
    gemm_tc<<<dim3(3, ROWS / 128, 1), 512, SM_BYTES>>>(p_prh, p_prl, DSq, 0,
                                                       p_whh, p_whl, DSq,
                                                       p_Q, 3 * DSq, 0, nullptr, DSq / BKT,
                                                       nullptr, nullptr);

    // 4) Mc = per-entity Ws_e @ Wm  (bf16 hi/lo only) + pbias
    gemm_tc<<<dim3(1, Dq / 128, NEq), 512, SM_BYTES>>>(p_wsh, p_wsl, NEq * Dq, Dq,
                                                       p_wth, p_wtl, Dq,
                                                       nullptr, NEq * DSq, DSq, nullptr, Dq / BKT,
                                                       p_mch, p_mcl);
    pbias_kernel<<<Dq, 256>>>(Ws, bm, bs, p_pb);

    // 5) GRU scan -> state_stack (output) + bf16 hi/lo (split across warp groups)
    gru_scan<<<Bq * NEq, 384>>>(p_Q, out + RW_OFF, state0, W_hh, b_ih, b_hh,
                                out + STATE_OFF, p_sth, p_stl);

    // 6) memory = state @ Wm^T + bm  [65536,768] K=128
    gemm_tc<<<dim3(Dq / 128, SROWS / 128, 1), 512, SM_BYTES>>>(p_sth, p_stl, DSq, 0,
                                                               p_wmh, p_wml, DSq,
                                                               out + MEM_OFF, Dq, 0, bm, DSq / BKT,
                                                               nullptr, nullptr);

    // 7) pooled = state_flat @ Mc^T + pbias  [8192,768] K=1024
    gemm_tc<<<dim3(Dq / 128, ROWS / 128, 1), 512, SM_BYTES>>>(p_sth, p_stl, NEq * DSq, 0,
                                                              p_mch, p_mcl, NEq * DSq,
                                                              out + POOLED_OFF, Dq, 0, p_pb, (NEq * DSq) / BKT,
                                                              nullptr, nullptr);

    // 8) heads fused -> holder/tagged/visible
    gemm_heads<<<dim3(2, SROWS / 128, 1), 512, SM_BYTES>>>(p_sth, p_stl, p_w1h, p_w1l,
                                                           p_b1, p_w2, bh2, bt2, bv2,
                                                           out + HOLDER_OFF, out + TAGGED_OFF, out + VISIBLE_OFF);

    (void)in_sizes; (void)n_in; (void)out_size;
}

// round 8
// speedup vs baseline: 1.8873x; 1.0620x over previous
#include <cuda_runtime.h>
#include <cuda_bf16.h>
#include <mma.h>
#include <math.h>
#include <stdint.h>

using namespace nvcuda;

#define Bq   8
#define Tq   1024
#define Dq   768
#define NEq  8
#define DSq  128
#define ROWS (Bq*Tq)            // 8192
#define SROWS (Bq*Tq*NEq)       // 65536

#define POOLED_OFF  0ll
#define MEM_OFF     6291456ll
#define STATE_OFF   56623104ll
#define HOLDER_OFF  65011712ll
#define TAGGED_OFF  65077248ll
#define VISIBLE_OFF 65142784ll
#define RW_OFF      65208320ll

// ---------------------------------------------------------------------------
// Scratch (16B-aligned for cp.async)
// ---------------------------------------------------------------------------
__device__ __align__(16) __nv_bfloat16 g_hseq_hi[ROWS*Dq],    g_hseq_lo[ROWS*Dq];
__device__ __align__(16) __nv_bfloat16 g_state_hi[SROWS*DSq], g_state_lo[SROWS*DSq];
__device__ __align__(16) __nv_bfloat16 g_projh[ROWS*DSq],     g_projl[ROWS*DSq];
__device__ __align__(16) __nv_bfloat16 g_Ws_hi[Dq*NEq*Dq],    g_Ws_lo[Dq*NEq*Dq];
__device__ __align__(16) __nv_bfloat16 g_Wi_hi[DSq*Dq],       g_Wi_lo[DSq*Dq];
__device__ __align__(16) __nv_bfloat16 g_Wih_hi[3*DSq*DSq],   g_Wih_lo[3*DSq*DSq];
__device__ __align__(16) __nv_bfloat16 g_Wm_hi[Dq*DSq],       g_Wm_lo[Dq*DSq];
__device__ __align__(16) __nv_bfloat16 g_WmT_hi[DSq*Dq],      g_WmT_lo[DSq*Dq];
__device__ __align__(16) __nv_bfloat16 g_Mc_hi[Dq*NEq*DSq],   g_Mc_lo[Dq*NEq*DSq];
__device__ __align__(16) __nv_bfloat16 g_W1_hi[256*DSq],      g_W1_lo[256*DSq];
__device__ __align__(16) float g_Q[ROWS*3*DSq];
__device__ __align__(16) float g_pbias[Dq];
__device__ __align__(16) float g_b1cat[256];
__device__ __align__(16) float g_W2cat[256];

// ---------------------------------------------------------------------------
// helpers
// ---------------------------------------------------------------------------
__device__ __forceinline__ unsigned long long fma_f32x2(unsigned long long a, unsigned long long b, unsigned long long c) {
    unsigned long long d;
    asm("fma.rn.f32x2 %0, %1, %2, %3;" : "=l"(d) : "l"(a), "l"(b), "l"(c));
    return d;
}
__device__ __forceinline__ float lo_f(unsigned long long v) { return __uint_as_float((uint32_t)v); }
__device__ __forceinline__ float hi_f(unsigned long long v) { return __uint_as_float((uint32_t)(v >> 32)); }

__device__ __forceinline__ uint32_t smem_u32(const void* p) {
    uint32_t a;
    asm("{ .reg .u64 t; cvta.to.shared.u64 t, %1; cvt.u32.u64 %0, t; }" : "=r"(a) : "l"(p));
    return a;
}
#define CP_COMMIT() asm volatile("cp.async.commit_group;" ::: "memory")
#define CP_WAIT0()  asm volatile("cp.async.wait_group 0;" ::: "memory")
#define CP_WAIT1()  asm volatile("cp.async.wait_group 1;" ::: "memory")

__device__ __forceinline__ void hilo(float v, __nv_bfloat16& h, __nv_bfloat16& l) {
    h = __float2bfloat16(v);
    l = __float2bfloat16(v - __bfloat162float(h));
}

// ---------------------------------------------------------------------------
// GEMM: block 128x128, BK=64, 512 threads = 16 warps (4x4), warp tile 32x32.
// 2-stage cp.async pipeline; stream-outer MMA order (4 independent acc chains).
// smem: per buffer 4 tiles of 128 x 72 bf16 (row stride 144B, conflict-free
// for ldmatrix). Element offsets within a buffer:
// ---------------------------------------------------------------------------
#define BKT    64
#define LDSK   72
#define E_ALO  9216
#define E_BHI  18432
#define E_BLO  27648
#define E_BUF  36864
#define TILE_B 18432              // bytes per tile
#define BUF_B  73728              // bytes per buffer
#define SM_BYTES 147456           // 2 buffers; epilogue C (64KB) reuses this

// stage one 128x64 bf16 tile: 1024 x 16B, 2 per thread
__device__ __forceinline__ void stage_async(uint32_t sdst, const __nv_bfloat16* __restrict__ g,
                                            long long row0, int k0, int ld, int tid)
{
#pragma unroll
    for (int it = 0; it < 2; it++) {
        int flat = it * 512 + tid;
        int row = flat >> 3, q = flat & 7;
        uint32_t d = sdst + row * (LDSK * 2) + q * 16;
        const void* s = g + (row0 + row) * (long long)ld + k0 + q * 8;
        asm volatile("cp.async.cg.shared.global [%0], [%1], 16;" :: "r"(d), "l"(s));
    }
}

__device__ __forceinline__ void stage4(uint32_t bufb,
                                       const __nv_bfloat16* Ahi, const __nv_bfloat16* Alo,
                                       const __nv_bfloat16* Bhi, const __nv_bfloat16* Blo,
                                       long long m0, int n0, int ka, int kb, int lda, int ldb, int tid)
{
    stage_async(bufb,              Ahi, m0, ka, lda, tid);
    stage_async(bufb + TILE_B,     Alo, m0, ka, lda, tid);
    stage_async(bufb + 2 * TILE_B, Bhi, n0, kb, ldb, tid);
    stage_async(bufb + 3 * TILE_B, Blo, n0, kb, ldb, tid);
    CP_COMMIT();
}

__global__ __launch_bounds__(512, 1)
void gemm_tc(const __nv_bfloat16* __restrict__ Ahi, const __nv_bfloat16* __restrict__ Alo, int lda, int aK0z,
             const __nv_bfloat16* __restrict__ Bhi, const __nv_bfloat16* __restrict__ Blo, int ldb,
             float* __restrict__ C, int ldc, int cZoff,
             const float* __restrict__ bias, int nChunks,
             __nv_bfloat16* __restrict__ outH, __nv_bfloat16* __restrict__ outL)
{
    extern __shared__ __align__(16) char smem[];
    __nv_bfloat16* s16 = reinterpret_cast<__nv_bfloat16*>(smem);
    const uint32_t sb = smem_u32(smem);
    const int tid = threadIdx.x, wid = tid >> 5;
    const int wy = wid >> 2, wx = wid & 3;
    const long long m0 = (long long)blockIdx.y * 128;
    const int n0 = blockIdx.x * 128;
    const int aK0 = blockIdx.z * aK0z;
    const int cOff = n0 + blockIdx.z * cZoff;

    wmma::fragment<wmma::accumulator, 16, 16, 16, float> acc[2][2];
#pragma unroll
    for (int i = 0; i < 2; i++)
#pragma unroll
        for (int j = 0; j < 2; j++) wmma::fill_fragment(acc[i][j], 0.0f);

    stage4(sb, Ahi, Alo, Bhi, Blo, m0, n0, aK0, 0, lda, ldb, tid);

    for (int c = 0; c < nChunks; c++) {
        if (c + 1 < nChunks) {
            stage4(sb + ((c + 1) & 1) * BUF_B, Ahi, Alo, Bhi, Blo, m0, n0,
                   aK0 + (c + 1) * BKT, (c + 1) * BKT, lda, ldb, tid);
            CP_WAIT1();
        } else {
            CP_WAIT0();
        }
        __syncthreads();
        const __nv_bfloat16* base = s16 + (c & 1) * E_BUF;
#pragma unroll
        for (int ks = 0; ks < BKT; ks += 16) {
            wmma::fragment<wmma::matrix_b, 16, 16, 16, __nv_bfloat16, wmma::col_major> bh[2], bl[2];
            wmma::fragment<wmma::matrix_a, 16, 16, 16, __nv_bfloat16, wmma::row_major> ah[2], al[2];
#pragma unroll
            for (int fn = 0; fn < 2; fn++) {
                const int nb = wx * 32 + fn * 16;
                wmma::load_matrix_sync(bh[fn], base + E_BHI + nb * LDSK + ks, LDSK);
                wmma::load_matrix_sync(bl[fn], base + E_BLO + nb * LDSK + ks, LDSK);
            }
#pragma unroll
            for (int fm = 0; fm < 2; fm++) {
                const int mb = wy * 32 + fm * 16;
                wmma::load_matrix_sync(ah[fm], base + mb * LDSK + ks, LDSK);
                wmma::load_matrix_sync(al[fm], base + E_ALO + mb * LDSK + ks, LDSK);
            }
            // stream-outer: consecutive MMAs hit different accumulators
#pragma unroll
            for (int fm = 0; fm < 2; fm++)
#pragma unroll
                for (int fn = 0; fn < 2; fn++)
                    wmma::mma_sync(acc[fm][fn], ah[fm], bh[fn], acc[fm][fn]);
#pragma unroll
            for (int fm = 0; fm < 2; fm++)
#pragma unroll
                for (int fn = 0; fn < 2; fn++)
                    wmma::mma_sync(acc[fm][fn], ah[fm], bl[fn], acc[fm][fn]);
#pragma unroll
            for (int fm = 0; fm < 2; fm++)
#pragma unroll
                for (int fn = 0; fn < 2; fn++)
                    wmma::mma_sync(acc[fm][fn], al[fm], bh[fn], acc[fm][fn]);
        }
        __syncthreads();
    }

    // epilogue via smem C tile (64KB, reuses staging smem)
    float* Cs = reinterpret_cast<float*>(smem);
#pragma unroll
    for (int fm = 0; fm < 2; fm++)
#pragma unroll
        for (int fn = 0; fn < 2; fn++)
            wmma::store_matrix_sync(Cs + (wy * 32 + fm * 16) * 128 + wx * 32 + fn * 16,
                                    acc[fm][fn], 128, wmma::mem_row_major);
    __syncthreads();
#pragma unroll
    for (int it = 0; it < 8; it++) {
        int flat = it * 512 + tid;
        int row = flat >> 5, q = flat & 31;
        float4 v = *reinterpret_cast<const float4*>(Cs + row * 128 + q * 4);
        if (bias) {
            const float4 bv = *reinterpret_cast<const float4*>(bias + n0 + q * 4);
            v.x += bv.x; v.y += bv.y; v.z += bv.z; v.w += bv.w;
        }
        size_t co = (size_t)(m0 + row) * ldc + cOff + q * 4;
        if (C) *reinterpret_cast<float4*>(C + co) = v;
        if (outH) {
            __nv_bfloat16 h0,l0,h1,l1,h2,l2,h3,l3;
            hilo(v.x,h0,l0); hilo(v.y,h1,l1); hilo(v.z,h2,l2); hilo(v.w,h3,l3);
            __nv_bfloat162 ph0 = {h0,h1}, ph1 = {h2,h3}, pl0 = {l0,l1}, pl1 = {l2,l3};
            *reinterpret_cast<__nv_bfloat162*>(outH + co)     = ph0;
            *reinterpret_cast<__nv_bfloat162*>(outH + co + 2) = ph1;
            *reinterpret_cast<__nv_bfloat162*>(outL + co)     = pl0;
            *reinterpret_cast<__nv_bfloat162*>(outL + co + 2) = pl1;
        }
    }
}

// ---------------------------------------------------------------------------
// Heads GEMM (K=128) with fused GELU . W2 epilogue
// ---------------------------------------------------------------------------
__device__ __forceinline__ float gelu_exact(float x) {
    return 0.5f * x * (1.0f + erff(x * 0.70710678118654752f));
}

__global__ __launch_bounds__(512, 1)
void gemm_heads(const __nv_bfloat16* __restrict__ Ahi, const __nv_bfloat16* __restrict__ Alo,
                const __nv_bfloat16* __restrict__ Bhi, const __nv_bfloat16* __restrict__ Blo,
                const float* __restrict__ b1cat, const float* __restrict__ W2cat,
                const float* __restrict__ bh2, const float* __restrict__ bt2, const float* __restrict__ bv2,
                float* __restrict__ oH, float* __restrict__ oT, float* __restrict__ oV)
{
    extern __shared__ __align__(16) char smem[];
    __nv_bfloat16* s16 = reinterpret_cast<__nv_bfloat16*>(smem);
    const uint32_t sb = smem_u32(smem);
    const int tid = threadIdx.x, wid = tid >> 5;
    const int wy = wid >> 2, wx = wid & 3;
    const long long m0 = (long long)blockIdx.y * 128;
    const int n0 = blockIdx.x * 128;
    const int nChunks = 2;

    wmma::fragment<wmma::accumulator, 16, 16, 16, float> acc[2][2];
#pragma unroll
    for (int i = 0; i < 2; i++)
#pragma unroll
        for (int j = 0; j < 2; j++) wmma::fill_fragment(acc[i][j], 0.0f);

    stage4(sb, Ahi, Alo, Bhi, Blo, m0, n0, 0, 0, DSq, DSq, tid);

    for (int c = 0; c < nChunks; c++) {
        if (c + 1 < nChunks) {
            stage4(sb + ((c + 1) & 1) * BUF_B, Ahi, Alo, Bhi, Blo, m0, n0,
                   (c + 1) * BKT, (c + 1) * BKT, DSq, DSq, tid);
            CP_WAIT1();
        } else {
            CP_WAIT0();
        }
        __syncthreads();
        const __nv_bfloat16* base = s16 + (c & 1) * E_BUF;
#pragma unroll
        for (int ks = 0; ks < BKT; ks += 16) {
            wmma::fragment<wmma::matrix_b, 16, 16, 16, __nv_bfloat16, wmma::col_major> bh[2], bl[2];
            wmma::fragment<wmma::matrix_a, 16, 16, 16, __nv_bfloat16, wmma::row_major> ah[2], al[2];
#pragma unroll
            for (int fn = 0; fn < 2; fn++) {
                const int nb = wx * 32 + fn * 16;
                wmma::load_matrix_sync(bh[fn], base + E_BHI + nb * LDSK + ks, LDSK);
                wmma::load_matrix_sync(bl[fn], base + E_BLO + nb * LDSK + ks, LDSK);
            }
#pragma unroll
            for (int fm = 0; fm < 2; fm++) {
                const int mb = wy * 32 + fm * 16;
                wmma::load_matrix_sync(ah[fm], base + mb * LDSK + ks, LDSK);
                wmma::load_matrix_sync(al[fm], base + E_ALO + mb * LDSK + ks, LDSK);
            }
#pragma unroll
            for (int fm = 0; fm < 2; fm++)
#pragma unroll
                for (int fn = 0; fn < 2; fn++)
                    wmma::mma_sync(acc[fm][fn], ah[fm], bh[fn], acc[fm][fn]);
#pragma unroll
            for (int fm = 0; fm < 2; fm++)
#pragma unroll
                for (int fn = 0; fn < 2; fn++)
                    wmma::mma_sync(acc[fm][fn], ah[fm], bl[fn], acc[fm][fn]);
#pragma unroll
            for (int fm = 0; fm < 2; fm++)
#pragma unroll
                for (int fn = 0; fn < 2; fn++)
                    wmma::mma_sync(acc[fm][fn], al[fm], bh[fn], acc[fm][fn]);
        }
        __syncthreads();
    }

    float* Cs = reinterpret_cast<float*>(smem);
#pragma unroll
    for (int fm = 0; fm < 2; fm++)
#pragma unroll
        for (int fn = 0; fn < 2; fn++)
            wmma::store_matrix_sync(Cs + (wy * 32 + fm * 16) * 128 + wx * 32 + fn * 16,
                                    acc[fm][fn], 128, wmma::mem_row_major);
    __syncthreads();

    if (tid < 256) {
        const int row = tid >> 1, half = tid & 1;
        const int headIdx = blockIdx.x * 2 + half;
        if (headIdx < 3) {
            float dot = 0.f;
#pragma unroll
            for (int q = 0; q < 16; q++) {
                int qq = (q + row) & 15;
                float4 v = *reinterpret_cast<const float4*>(Cs + row * 128 + half * 64 + qq * 4);
                int col = n0 + half * 64 + qq * 4;
                dot = fmaf(gelu_exact(v.x + __ldg(b1cat + col + 0)), __ldg(W2cat + col + 0), dot);
                dot = fmaf(gelu_exact(v.y + __ldg(b1cat + col + 1)), __ldg(W2cat + col + 1), dot);
                dot = fmaf(gelu_exact(v.z + __ldg(b1cat + col + 2)), __ldg(W2cat + col + 2), dot);
                dot = fmaf(gelu_exact(v.w + __ldg(b1cat + col + 3)), __ldg(W2cat + col + 3), dot);
            }
            float* op = (headIdx == 0) ? oH : (headIdx == 1) ? oT : oV;
            float b2 = (headIdx == 0) ? __ldg(bh2) : (headIdx == 1) ? __ldg(bt2) : __ldg(bv2);
            op[m0 + row] = dot + b2;
        }
    }
}

// ---------------------------------------------------------------------------
// Weight prep
// ---------------------------------------------------------------------------
__global__ void prep_weights(const float* __restrict__ Wi, const float* __restrict__ W_ih,
                             const float* __restrict__ Wm, const float* __restrict__ Ws,
                             const float* __restrict__ Wh1, const float* __restrict__ Wt1,
                             const float* __restrict__ Wv1,
                             const float* __restrict__ bh1, const float* __restrict__ bt1,
                             const float* __restrict__ bv1,
                             const float* __restrict__ Wh2, const float* __restrict__ Wt2,
                             const float* __restrict__ Wv2)
{
    const int N_Wi = DSq * Dq, N_Wih = 3 * DSq * DSq, N_Wm = Dq * DSq;
    const int N_W1 = 256 * DSq;
    const long long N_Ws = (long long)Dq * NEq * Dq;
    long long idx = (long long)blockIdx.x * 256 + threadIdx.x;
    __nv_bfloat16 h, l;
    if (idx < N_Wi)  { hilo(Wi[idx], h, l);   g_Wi_hi[idx] = h;  g_Wi_lo[idx] = l;  return; }
    idx -= N_Wi;
    if (idx < N_Wih) { hilo(W_ih[idx], h, l); g_Wih_hi[idx] = h; g_Wih_lo[idx] = l; return; }
    idx -= N_Wih;
    if (idx < N_Wm)  { hilo(Wm[idx], h, l);   g_Wm_hi[idx] = h;  g_Wm_lo[idx] = l;  return; }
    idx -= N_Wm;
    if (idx < N_Wm) {
        int j = (int)(idx / DSq), k = (int)(idx % DSq);
        hilo(Wm[idx], h, l);
        g_WmT_hi[(size_t)k * Dq + j] = h; g_WmT_lo[(size_t)k * Dq + j] = l; return;
    }
    idx -= N_Wm;
    if (idx < N_W1) {
        int r = (int)(idx / DSq), c = (int)(idx % DSq);
        float v = (r < 64) ? Wh1[r * DSq + c] : (r < 128) ? Wt1[(r - 64) * DSq + c]
                : (r < 192) ? Wv1[(r - 128) * DSq + c] : 0.f;
        hilo(v, h, l); g_W1_hi[idx] = h; g_W1_lo[idx] = l; return;
    }
    idx -= N_W1;
    if (idx < 256) {
        int i = (int)idx;
        g_b1cat[i] = (i < 64) ? bh1[i] : (i < 128) ? bt1[i - 64] : (i < 192) ? bv1[i - 128] : 0.f;
        g_W2cat[i] = (i < 64) ? Wh2[i] : (i < 128) ? Wt2[i - 64] : (i < 192) ? Wv2[i - 128] : 0.f;
        return;
    }
    idx -= 256;
    if (idx < N_Ws) { hilo(Ws[idx], h, l); g_Ws_hi[idx] = h; g_Ws_lo[idx] = l; }
}
#define PREP_TOTAL (DSq*Dq + 3*DSq*DSq + Dq*DSq + Dq*DSq + 256*DSq + 256 + Dq*NEq*Dq)

// ---------------------------------------------------------------------------
// Route softmax + fused h_seq hi/lo conversion
// ---------------------------------------------------------------------------
__global__ __launch_bounds__(256)
void route_cvt(const float* __restrict__ h_seq, const float* __restrict__ ek,
               float* __restrict__ rw,
               __nv_bfloat16* __restrict__ hi, __nv_bfloat16* __restrict__ lo)
{
    const int row = blockIdx.x;
    const int w = threadIdx.x >> 5, lane = threadIdx.x & 31;
    const float* hr = h_seq + (size_t)row * Dq;
    const float* er = ek + (size_t)w * Dq;
    float s = 0.f;
#pragma unroll 4
    for (int k = lane; k < Dq; k += 32) s = fmaf(hr[k], er[k], s);
#pragma unroll
    for (int o = 16; o; o >>= 1) s += __shfl_xor_sync(0xffffffffu, s, o);
    __shared__ float lg[NEq];
    if (lane == 0) lg[w] = s;

#pragma unroll
    for (int i = threadIdx.x; i < Dq; i += 256) {
        __nv_bfloat16 h, l; hilo(hr[i], h, l);
        hi[(size_t)row * Dq + i] = h;
        lo[(size_t)row * Dq + i] = l;
    }
    __syncthreads();
    if (threadIdx.x == 0) {
        const float inv = 0.036084391824351615f;
        float v[NEq], m = -1e30f;
#pragma unroll
        for (int e = 0; e < NEq; e++) { v[e] = lg[e] * inv; m = fmaxf(m, v[e]); }
        float den = 0.f;
#pragma unroll
        for (int e = 0; e < NEq; e++) { v[e] = __expf(v[e] - m); den += v[e]; }
        float id = 1.f / den;
#pragma unroll
        for (int e = 0; e < NEq; e++) rw[(size_t)row * NEq + e] = v[e] * id;
    }
}

__global__ __launch_bounds__(256)
void pbias_kernel(const float* __restrict__ Ws, const float* __restrict__ bm,
                  const float* __restrict__ bs, float* __restrict__ pb)
{
    int d = blockIdx.x, tid = threadIdx.x;
    float s = 0.f;
    for (int j = tid; j < NEq * Dq; j += 256) s = fmaf(bm[j % Dq], Ws[(size_t)d * (NEq * Dq) + j], s);
    __shared__ float red[256];
    red[tid] = s; __syncthreads();
    for (int o = 128; o; o >>= 1) { if (tid < o) red[tid] += red[tid + o]; __syncthreads(); }
    if (tid == 0) pb[d] = red[0] + bs[d];
}

// ---------------------------------------------------------------------------
// GRU scan (unchanged from round 7 — passing config)
// ---------------------------------------------------------------------------
__global__ __launch_bounds__(384, 1)
void gru_scan(const float* __restrict__ Q, const float* __restrict__ rw,
              const float* __restrict__ state0, const float* __restrict__ W_hh,
              const float* __restrict__ b_ih, const float* __restrict__ b_hh,
              float* __restrict__ state_out,
              __nv_bfloat16* __restrict__ sth, __nv_bfloat16* __restrict__ stl)
{
    const int b = blockIdx.x >> 3;
    const int e = blockIdx.x & 7;
    const int j = threadIdx.x;
    const int grp = j >> 7;
    const int jm = j & 127;

    unsigned long long w2r[64];
    {
        const unsigned long long* wr = reinterpret_cast<const unsigned long long*>(W_hh + (size_t)j * DSq);
#pragma unroll
        for (int i = 0; i < 64; i++) w2r[i] = wr[i];
    }
    __shared__ __align__(16) float hbuf[DSq];
    __shared__ float gh[3 * DSq];

    if (j < 32) reinterpret_cast<float4*>(hbuf)[j] = reinterpret_cast<const float4*>(state0 + e * DSq)[j];
    const float bhh = b_hh[j];
    float bir = 0.f, biz = 0.f, bin = 0.f;
    if (j < DSq) { bir = b_ih[j]; biz = b_ih[DSq + j]; bin = b_ih[2 * DSq + j]; }
    __syncthreads();

    const ulonglong2* hs2 = reinterpret_cast<const ulonglong2*>(hbuf);

    float qr = 0.f, qz = 0.f, qn = 0.f, rwv = 0.f;
    if (j < DSq) {
        const float* qp = Q + (size_t)(b * Tq) * (3 * DSq);
        qr = qp[j]; qz = qp[DSq + j]; qn = qp[2 * DSq + j];
        rwv = rw[(size_t)(b * Tq) * NEq + e];
    }

    for (int t = 0; t < Tq; t++) {
        const int row = b * Tq + t;
        float nqr = 0.f, nqz = 0.f, nqn = 0.f, nrw = 0.f;
        if (t + 1 < Tq && j < DSq) {
            const float* qp = Q + (size_t)(row + 1) * (3 * DSq);
            nqr = __ldg(qp + j); nqz = __ldg(qp + DSq + j); nqn = __ldg(qp + 2 * DSq + j);
            nrw = __ldg(rw + (size_t)(row + 1) * NEq + e);
        }
        if (grp && t > 0) {
            float hv = hbuf[jm];
            __nv_bfloat16 hh = __float2bfloat16(hv);
            size_t pidx = (((size_t)(row - 1)) * NEq + e) * DSq + jm;
            if (grp == 1) sth[pidx] = hh;
            else          stl[pidx] = __float2bfloat16(hv - __bfloat162float(hh));
        }
        unsigned long long a0 = 0, a1 = 0, a2 = 0, a3 = 0;
#pragma unroll
        for (int i = 0; i < 32; i += 2) {
            ulonglong2 h0 = hs2[i];
            ulonglong2 h1 = hs2[i + 1];
            a0 = fma_f32x2(w2r[i * 2 + 0], h0.x, a0);
            a1 = fma_f32x2(w2r[i * 2 + 1], h0.y, a1);
            a2 = fma_f32x2(w2r[i * 2 + 2], h1.x, a2);
            a3 = fma_f32x2(w2r[i * 2 + 3], h1.y, a3);
        }
        float acc = ((lo_f(a0) + hi_f(a0)) + (lo_f(a1) + hi_f(a1)))
                  + ((lo_f(a2) + hi_f(a2)) + (lo_f(a3) + hi_f(a3)));
        gh[j] = acc + bhh;
        __syncthreads();
        if (j < DSq) {
            float gir = fmaf(rwv, qr, bir);
            float giz = fmaf(rwv, qz, biz);
            float gin = fmaf(rwv, qn, bin);
            float r = __fdividef(1.f, 1.f + __expf(-(gir + gh[j])));
            float z = __fdividef(1.f, 1.f + __expf(-(giz + gh[DSq + j])));
            float xn = fmaf(r, gh[2 * DSq + j], gin);
            float ex = __expf(-2.f * xn);
            float n = __fdividef(1.f - ex, 1.f + ex);
            float hnew = fmaf(z, hbuf[j] - n, n);
            hbuf[j] = hnew;
            state_out[(((size_t)row) * NEq + e) * DSq + j] = hnew;
        }
        __syncthreads();
        qr = nqr; qz = nqz; qn = nqn; rwv = nrw;
    }
    if (grp) {
        float hv = hbuf[jm];
        __nv_bfloat16 hh = __float2bfloat16(hv);
        size_t pidx = (((size_t)(b * Tq + Tq - 1)) * NEq + e) * DSq + jm;
        if (grp == 1) sth[pidx] = hh;
        else          stl[pidx] = __float2bfloat16(hv - __bfloat162float(hh));
    }
}

// ---------------------------------------------------------------------------
// Launch
// ---------------------------------------------------------------------------
extern "C" void kernel_launch(void* const* d_in, const int* in_sizes, int n_in,
                              void* d_out, int out_size)
{
    const float* h_seq = (const float*)d_in[0];
    const float* ek    = (const float*)d_in[1];
    const float* state0= (const float*)d_in[2];
    const float* Wi    = (const float*)d_in[3];
    const float* bi    = (const float*)d_in[4];
    const float* W_ih  = (const float*)d_in[5];
    const float* W_hh  = (const float*)d_in[6];
    const float* b_ih  = (const float*)d_in[7];
    const float* b_hh  = (const float*)d_in[8];
    const float* Wm    = (const float*)d_in[9];
    const float* bm    = (const float*)d_in[10];
    const float* Ws    = (const float*)d_in[11];
    const float* bs    = (const float*)d_in[12];
    const float* Wh1   = (const float*)d_in[13];
    const float* bh1   = (const float*)d_in[14];
    const float* Wh2   = (const float*)d_in[15];
    const float* bh2   = (const float*)d_in[16];
    const float* Wt1   = (const float*)d_in[17];
    const float* bt1   = (const float*)d_in[18];
    const float* Wt2   = (const float*)d_in[19];
    const float* bt2   = (const float*)d_in[20];
    const float* Wv1   = (const float*)d_in[21];
    const float* bv1   = (const float*)d_in[22];
    const float* Wv2   = (const float*)d_in[23];
    const float* bv2   = (const float*)d_in[24];
    float* out = (float*)d_out;

    cudaFuncSetAttribute(gemm_tc, cudaFuncAttributeMaxDynamicSharedMemorySize, SM_BYTES);
    cudaFuncSetAttribute(gemm_heads, cudaFuncAttributeMaxDynamicSharedMemorySize, SM_BYTES);

#define SYMF(p, s) float* p; cudaGetSymbolAddress((void**)&p, s)
#define SYMB(p, s) __nv_bfloat16* p; cudaGetSymbolAddress((void**)&p, s)
    SYMB(p_hsh, g_hseq_hi);  SYMB(p_hsl, g_hseq_lo);
    SYMB(p_sth, g_state_hi); SYMB(p_stl, g_state_lo);
    SYMB(p_prh, g_projh);    SYMB(p_prl, g_projl);
    SYMB(p_wsh, g_Ws_hi);    SYMB(p_wsl, g_Ws_lo);
    SYMB(p_wih, g_Wi_hi);    SYMB(p_wil, g_Wi_lo);
    SYMB(p_whh, g_Wih_hi);   SYMB(p_whl, g_Wih_lo);
    SYMB(p_wmh, g_Wm_hi);    SYMB(p_wml, g_Wm_lo);
    SYMB(p_wth, g_WmT_hi);   SYMB(p_wtl, g_WmT_lo);
    SYMB(p_mch, g_Mc_hi);    SYMB(p_mcl, g_Mc_lo);
    SYMB(p_w1h, g_W1_hi);    SYMB(p_w1l, g_W1_lo);
    SYMF(p_Q, g_Q); SYMF(p_pb, g_pbias);
    SYMF(p_b1, g_b1cat);  SYMF(p_w2, g_W2cat);

    // 1) prep + route(+cvt)
    prep_weights<<<(PREP_TOTAL + 255) / 256, 256>>>(Wi, W_ih, Wm, Ws, Wh1, Wt1, Wv1,
                                                    bh1, bt1, bv1, Wh2, Wt2, Wv2);
    route_cvt<<<ROWS, 256>>>(h_seq, ek, out + RW_OFF, p_hsh, p_hsl);

    // 2) proj = h_seq @ Wi^T + bi  [8192,128] K=768  (bf16 hi/lo only)
    gemm_tc<<<dim3(1, ROWS / 128, 1), 512, SM_BYTES>>>(p_hsh, p_hsl, Dq, 0,
                                                       p_wih, p_wil, Dq,
                                                       nullptr, DSq, 0, bi, Dq / BKT,
                                                       p_prh, p_prl);

    // 3) Q = proj @ W_ih^T  [8192,384] K=128
    gemm_tc<<<dim3(3, ROWS / 128, 1), 512, SM_BYTES>>>(p_prh, p_prl, DSq, 0,
                                                       p_whh, p_whl, DSq,
                                                       p_Q, 3 * DSq, 0, nullptr, DSq / BKT,
                                                       nullptr, nullptr);

    // 4) Mc = per-entity Ws_e @ Wm  (bf16 hi/lo only) + pbias
    gemm_tc<<<dim3(1, Dq / 128, NEq), 512, SM_BYTES>>>(p_wsh, p_wsl, NEq * Dq, Dq,
                                                       p_wth, p_wtl, Dq,
                                                       nullptr, NEq * DSq, DSq, nullptr, Dq / BKT,
                                                       p_mch, p_mcl);
    pbias_kernel<<<Dq, 256>>>(Ws, bm, bs, p_pb);

    // 5) GRU scan -> state_stack (output) + bf16 hi/lo (split across warp groups)
    gru_scan<<<Bq * NEq, 384>>>(p_Q, out + RW_OFF, state0, W_hh, b_ih, b_hh,
                                out + STATE_OFF, p_sth, p_stl);

    // 6) memory = state @ Wm^T + bm  [65536,768] K=128
    gemm_tc<<<dim3(Dq / 128, SROWS / 128, 1), 512, SM_BYTES>>>(p_sth, p_stl, DSq, 0,
                                                               p_wmh, p_wml, DSq,
                                                               out + MEM_OFF, Dq, 0, bm, DSq / BKT,
                                                               nullptr, nullptr);

    // 7) pooled = state_flat @ Mc^T + pbias  [8192,768] K=1024
    gemm_tc<<<dim3(Dq / 128, ROWS / 128, 1), 512, SM_BYTES>>>(p_sth, p_stl, NEq * DSq, 0,
                                                              p_mch, p_mcl, NEq * DSq,
                                                              out + POOLED_OFF, Dq, 0, p_pb, (NEq * DSq) / BKT,
                                                              nullptr, nullptr);

    // 8) heads fused -> holder/tagged/visible
    gemm_heads<<<dim3(2, SROWS / 128, 1), 512, SM_BYTES>>>(p_sth, p_stl, p_w1h, p_w1l,
                                                           p_b1, p_w2, bh2, bt2, bv2,
                                                           out + HOLDER_OFF, out + TAGGED_OFF, out + VISIBLE_OFF);

    (void)in_sizes; (void)n_in; (void)out_size;
}

// round 9
// speedup vs baseline: 2.1451x; 1.1366x over previous
#include <cuda_runtime.h>
#include <cuda_bf16.h>
#include <mma.h>
#include <math.h>
#include <stdint.h>

using namespace nvcuda;

#define Bq   8
#define Tq   1024
#define Dq   768
#define NEq  8
#define DSq  128
#define ROWS (Bq*Tq)            // 8192
#define SROWS (Bq*Tq*NEq)       // 65536

#define POOLED_OFF  0ll
#define MEM_OFF     6291456ll
#define STATE_OFF   56623104ll
#define HOLDER_OFF  65011712ll
#define TAGGED_OFF  65077248ll
#define VISIBLE_OFF 65142784ll
#define RW_OFF      65208320ll

// ---------------------------------------------------------------------------
// Scratch
// ---------------------------------------------------------------------------
__device__ __align__(16) __nv_bfloat16 g_hseq_hi[ROWS*Dq],    g_hseq_lo[ROWS*Dq];
__device__ __align__(16) __nv_bfloat16 g_state_hi[SROWS*DSq], g_state_lo[SROWS*DSq];
__device__ __align__(16) __nv_bfloat16 g_projh[ROWS*DSq],     g_projl[ROWS*DSq];
__device__ __align__(16) __nv_bfloat16 g_Ws_hi[Dq*NEq*Dq],    g_Ws_lo[Dq*NEq*Dq];
__device__ __align__(16) __nv_bfloat16 g_Wi_hi[DSq*Dq],       g_Wi_lo[DSq*Dq];
__device__ __align__(16) __nv_bfloat16 g_Wih_hi[3*DSq*DSq],   g_Wih_lo[3*DSq*DSq];
__device__ __align__(16) __nv_bfloat16 g_Wm_hi[Dq*DSq],       g_Wm_lo[Dq*DSq];
__device__ __align__(16) __nv_bfloat16 g_WmT_hi[DSq*Dq],      g_WmT_lo[DSq*Dq];
__device__ __align__(16) __nv_bfloat16 g_Mc_hi[Dq*NEq*DSq],   g_Mc_lo[Dq*NEq*DSq];
__device__ __align__(16) __nv_bfloat16 g_W1_hi[256*DSq],      g_W1_lo[256*DSq];
__device__ __align__(16) float g_Q[ROWS*3*DSq];
__device__ __align__(16) float g_pbias[Dq];
__device__ __align__(16) float g_b1cat[256];
__device__ __align__(16) float g_W2cat[256];
__device__ int g_prog[128];        // per (b, 64-step chunk) completion counters

// ---------------------------------------------------------------------------
// helpers
// ---------------------------------------------------------------------------
__device__ __forceinline__ unsigned long long fma_f32x2(unsigned long long a, unsigned long long b, unsigned long long c) {
    unsigned long long d;
    asm("fma.rn.f32x2 %0, %1, %2, %3;" : "=l"(d) : "l"(a), "l"(b), "l"(c));
    return d;
}
__device__ __forceinline__ float lo_f(unsigned long long v) { return __uint_as_float((uint32_t)v); }
__device__ __forceinline__ float hi_f(unsigned long long v) { return __uint_as_float((uint32_t)(v >> 32)); }

__device__ __forceinline__ uint32_t smem_u32(const void* p) {
    uint32_t a;
    asm("{ .reg .u64 t; cvta.to.shared.u64 t, %1; cvt.u32.u64 %0, t; }" : "=r"(a) : "l"(p));
    return a;
}
#define CP_COMMIT() asm volatile("cp.async.commit_group;" ::: "memory")
#define CP_WAIT0()  asm volatile("cp.async.wait_group 0;" ::: "memory")
#define CP_WAIT1()  asm volatile("cp.async.wait_group 1;" ::: "memory")

__device__ __forceinline__ void cp16(uint32_t d, const void* s) {
    asm volatile("cp.async.cg.shared.global [%0], [%1], 16;" :: "r"(d), "l"(s));
}

__device__ __forceinline__ void hilo(float v, __nv_bfloat16& h, __nv_bfloat16& l) {
    h = __float2bfloat16(v);
    l = __float2bfloat16(v - __bfloat162float(h));
}

// ---------------------------------------------------------------------------
// Generic GEMM (proj/Q/Mc/pooled): block 128x128, BK=64, 512 thr, 16 warps.
// ---------------------------------------------------------------------------
#define BKT    64
#define LDSK   72
#define E_ALO  9216
#define E_BHI  18432
#define E_BLO  27648
#define E_BUF  36864
#define TILE_B 18432
#define BUF_B  73728
#define SM_BYTES 147456

__device__ __forceinline__ void stage_async(uint32_t sdst, const __nv_bfloat16* __restrict__ g,
                                            long long row0, int k0, int ld, int tid)
{
#pragma unroll
    for (int it = 0; it < 2; it++) {
        int flat = it * 512 + tid;
        int row = flat >> 3, q = flat & 7;
        cp16(sdst + row * (LDSK * 2) + q * 16, g + (row0 + row) * (long long)ld + k0 + q * 8);
    }
}

__device__ __forceinline__ void stage4(uint32_t bufb,
                                       const __nv_bfloat16* Ahi, const __nv_bfloat16* Alo,
                                       const __nv_bfloat16* Bhi, const __nv_bfloat16* Blo,
                                       long long m0, int n0, int ka, int kb, int lda, int ldb, int tid)
{
    stage_async(bufb,              Ahi, m0, ka, lda, tid);
    stage_async(bufb + TILE_B,     Alo, m0, ka, lda, tid);
    stage_async(bufb + 2 * TILE_B, Bhi, n0, kb, ldb, tid);
    stage_async(bufb + 3 * TILE_B, Blo, n0, kb, ldb, tid);
    CP_COMMIT();
}

__global__ __launch_bounds__(512, 1)
void gemm_tc(const __nv_bfloat16* __restrict__ Ahi, const __nv_bfloat16* __restrict__ Alo, int lda, int aK0z,
             const __nv_bfloat16* __restrict__ Bhi, const __nv_bfloat16* __restrict__ Blo, int ldb,
             float* __restrict__ C, int ldc, int cZoff,
             const float* __restrict__ bias, int nChunks,
             __nv_bfloat16* __restrict__ outH, __nv_bfloat16* __restrict__ outL)
{
    extern __shared__ __align__(16) char smem[];
    __nv_bfloat16* s16 = reinterpret_cast<__nv_bfloat16*>(smem);
    const uint32_t sb = smem_u32(smem);
    const int tid = threadIdx.x, wid = tid >> 5;
    const int wy = wid >> 2, wx = wid & 3;
    const long long m0 = (long long)blockIdx.y * 128;
    const int n0 = blockIdx.x * 128;
    const int aK0 = blockIdx.z * aK0z;
    const int cOff = n0 + blockIdx.z * cZoff;

    wmma::fragment<wmma::accumulator, 16, 16, 16, float> acc[2][2];
#pragma unroll
    for (int i = 0; i < 2; i++)
#pragma unroll
        for (int j = 0; j < 2; j++) wmma::fill_fragment(acc[i][j], 0.0f);

    stage4(sb, Ahi, Alo, Bhi, Blo, m0, n0, aK0, 0, lda, ldb, tid);

    for (int c = 0; c < nChunks; c++) {
        if (c + 1 < nChunks) {
            stage4(sb + ((c + 1) & 1) * BUF_B, Ahi, Alo, Bhi, Blo, m0, n0,
                   aK0 + (c + 1) * BKT, (c + 1) * BKT, lda, ldb, tid);
            CP_WAIT1();
        } else {
            CP_WAIT0();
        }
        __syncthreads();
        const __nv_bfloat16* base = s16 + (c & 1) * E_BUF;
#pragma unroll
        for (int ks = 0; ks < BKT; ks += 16) {
            wmma::fragment<wmma::matrix_b, 16, 16, 16, __nv_bfloat16, wmma::col_major> bh[2], bl[2];
            wmma::fragment<wmma::matrix_a, 16, 16, 16, __nv_bfloat16, wmma::row_major> ah[2], al[2];
#pragma unroll
            for (int fn = 0; fn < 2; fn++) {
                const int nb = wx * 32 + fn * 16;
                wmma::load_matrix_sync(bh[fn], base + E_BHI + nb * LDSK + ks, LDSK);
                wmma::load_matrix_sync(bl[fn], base + E_BLO + nb * LDSK + ks, LDSK);
            }
#pragma unroll
            for (int fm = 0; fm < 2; fm++) {
                const int mb = wy * 32 + fm * 16;
                wmma::load_matrix_sync(ah[fm], base + mb * LDSK + ks, LDSK);
                wmma::load_matrix_sync(al[fm], base + E_ALO + mb * LDSK + ks, LDSK);
            }
#pragma unroll
            for (int fm = 0; fm < 2; fm++)
#pragma unroll
                for (int fn = 0; fn < 2; fn++)
                    wmma::mma_sync(acc[fm][fn], ah[fm], bh[fn], acc[fm][fn]);
#pragma unroll
            for (int fm = 0; fm < 2; fm++)
#pragma unroll
                for (int fn = 0; fn < 2; fn++)
                    wmma::mma_sync(acc[fm][fn], ah[fm], bl[fn], acc[fm][fn]);
#pragma unroll
            for (int fm = 0; fm < 2; fm++)
#pragma unroll
                for (int fn = 0; fn < 2; fn++)
                    wmma::mma_sync(acc[fm][fn], al[fm], bh[fn], acc[fm][fn]);
        }
        __syncthreads();
    }

    float* Cs = reinterpret_cast<float*>(smem);
#pragma unroll
    for (int fm = 0; fm < 2; fm++)
#pragma unroll
        for (int fn = 0; fn < 2; fn++)
            wmma::store_matrix_sync(Cs + (wy * 32 + fm * 16) * 128 + wx * 32 + fn * 16,
                                    acc[fm][fn], 128, wmma::mem_row_major);
    __syncthreads();
#pragma unroll
    for (int it = 0; it < 8; it++) {
        int flat = it * 512 + tid;
        int row = flat >> 5, q = flat & 31;
        float4 v = *reinterpret_cast<const float4*>(Cs + row * 128 + q * 4);
        if (bias) {
            const float4 bv = *reinterpret_cast<const float4*>(bias + n0 + q * 4);
            v.x += bv.x; v.y += bv.y; v.z += bv.z; v.w += bv.w;
        }
        size_t co = (size_t)(m0 + row) * ldc + cOff + q * 4;
        if (C) *reinterpret_cast<float4*>(C + co) = v;
        if (outH) {
            __nv_bfloat16 h0,l0,h1,l1,h2,l2,h3,l3;
            hilo(v.x,h0,l0); hilo(v.y,h1,l1); hilo(v.z,h2,l2); hilo(v.w,h3,l3);
            __nv_bfloat162 ph0 = {h0,h1}, ph1 = {h2,h3}, pl0 = {l0,l1}, pl1 = {l2,l3};
            *reinterpret_cast<__nv_bfloat162*>(outH + co)     = ph0;
            *reinterpret_cast<__nv_bfloat162*>(outH + co + 2) = ph1;
            *reinterpret_cast<__nv_bfloat162*>(outL + co)     = pl0;
            *reinterpret_cast<__nv_bfloat162*>(outL + co + 2) = pl1;
        }
    }
}

// ---------------------------------------------------------------------------
// Heads GEMM (K=128) with fused GELU . W2 epilogue (unchanged)
// ---------------------------------------------------------------------------
__device__ __forceinline__ float gelu_exact(float x) {
    return 0.5f * x * (1.0f + erff(x * 0.70710678118654752f));
}

__global__ __launch_bounds__(512, 1)
void gemm_heads(const __nv_bfloat16* __restrict__ Ahi, const __nv_bfloat16* __restrict__ Alo,
                const __nv_bfloat16* __restrict__ Bhi, const __nv_bfloat16* __restrict__ Blo,
                const float* __restrict__ b1cat, const float* __restrict__ W2cat,
                const float* __restrict__ bh2, const float* __restrict__ bt2, const float* __restrict__ bv2,
                float* __restrict__ oH, float* __restrict__ oT, float* __restrict__ oV)
{
    extern __shared__ __align__(16) char smem[];
    __nv_bfloat16* s16 = reinterpret_cast<__nv_bfloat16*>(smem);
    const uint32_t sb = smem_u32(smem);
    const int tid = threadIdx.x, wid = tid >> 5;
    const int wy = wid >> 2, wx = wid & 3;
    const long long m0 = (long long)blockIdx.y * 128;
    const int n0 = blockIdx.x * 128;
    const int nChunks = 2;

    wmma::fragment<wmma::accumulator, 16, 16, 16, float> acc[2][2];
#pragma unroll
    for (int i = 0; i < 2; i++)
#pragma unroll
        for (int j = 0; j < 2; j++) wmma::fill_fragment(acc[i][j], 0.0f);

    stage4(sb, Ahi, Alo, Bhi, Blo, m0, n0, 0, 0, DSq, DSq, tid);

    for (int c = 0; c < nChunks; c++) {
        if (c + 1 < nChunks) {
            stage4(sb + ((c + 1) & 1) * BUF_B, Ahi, Alo, Bhi, Blo, m0, n0,
                   (c + 1) * BKT, (c + 1) * BKT, DSq, DSq, tid);
            CP_WAIT1();
        } else {
            CP_WAIT0();
        }
        __syncthreads();
        const __nv_bfloat16* base = s16 + (c & 1) * E_BUF;
#pragma unroll
        for (int ks = 0; ks < BKT; ks += 16) {
            wmma::fragment<wmma::matrix_b, 16, 16, 16, __nv_bfloat16, wmma::col_major> bh[2], bl[2];
            wmma::fragment<wmma::matrix_a, 16, 16, 16, __nv_bfloat16, wmma::row_major> ah[2], al[2];
#pragma unroll
            for (int fn = 0; fn < 2; fn++) {
                const int nb = wx * 32 + fn * 16;
                wmma::load_matrix_sync(bh[fn], base + E_BHI + nb * LDSK + ks, LDSK);
                wmma::load_matrix_sync(bl[fn], base + E_BLO + nb * LDSK + ks, LDSK);
            }
#pragma unroll
            for (int fm = 0; fm < 2; fm++) {
                const int mb = wy * 32 + fm * 16;
                wmma::load_matrix_sync(ah[fm], base + mb * LDSK + ks, LDSK);
                wmma::load_matrix_sync(al[fm], base + E_ALO + mb * LDSK + ks, LDSK);
            }
#pragma unroll
            for (int fm = 0; fm < 2; fm++)
#pragma unroll
                for (int fn = 0; fn < 2; fn++)
                    wmma::mma_sync(acc[fm][fn], ah[fm], bh[fn], acc[fm][fn]);
#pragma unroll
            for (int fm = 0; fm < 2; fm++)
#pragma unroll
                for (int fn = 0; fn < 2; fn++)
                    wmma::mma_sync(acc[fm][fn], ah[fm], bl[fn], acc[fm][fn]);
#pragma unroll
            for (int fm = 0; fm < 2; fm++)
#pragma unroll
                for (int fn = 0; fn < 2; fn++)
                    wmma::mma_sync(acc[fm][fn], al[fm], bh[fn], acc[fm][fn]);
        }
        __syncthreads();
    }

    float* Cs = reinterpret_cast<float*>(smem);
#pragma unroll
    for (int fm = 0; fm < 2; fm++)
#pragma unroll
        for (int fn = 0; fn < 2; fn++)
            wmma::store_matrix_sync(Cs + (wy * 32 + fm * 16) * 128 + wx * 32 + fn * 16,
                                    acc[fm][fn], 128, wmma::mem_row_major);
    __syncthreads();

    if (tid < 256) {
        const int row = tid >> 1, half = tid & 1;
        const int headIdx = blockIdx.x * 2 + half;
        if (headIdx < 3) {
            float dot = 0.f;
#pragma unroll
            for (int q = 0; q < 16; q++) {
                int qq = (q + row) & 15;
                float4 v = *reinterpret_cast<const float4*>(Cs + row * 128 + half * 64 + qq * 4);
                int col = n0 + half * 64 + qq * 4;
                dot = fmaf(gelu_exact(v.x + __ldg(b1cat + col + 0)), __ldg(W2cat + col + 0), dot);
                dot = fmaf(gelu_exact(v.y + __ldg(b1cat + col + 1)), __ldg(W2cat + col + 1), dot);
                dot = fmaf(gelu_exact(v.z + __ldg(b1cat + col + 2)), __ldg(W2cat + col + 2), dot);
                dot = fmaf(gelu_exact(v.w + __ldg(b1cat + col + 3)), __ldg(W2cat + col + 3), dot);
            }
            float* op = (headIdx == 0) ? oH : (headIdx == 1) ? oT : oV;
            float b2 = (headIdx == 0) ? __ldg(bh2) : (headIdx == 1) ? __ldg(bt2) : __ldg(bv2);
            op[m0 + row] = dot + b2;
        }
    }
}

// ---------------------------------------------------------------------------
// FUSED scan + memory-GEMM persistent kernel (384 threads).
// Blocks 0..63: GRU scan chains; publish g_prog[b*16+k] after each 64-step
// chunk. Blocks 64+: memory gemm tiles (128 x 96), ordered by t, spin on flag.
// ---------------------------------------------------------------------------
#define F_EALO  9216
#define F_EBHI  18432
#define F_EBLO  25344
#define F_EBUF  32256
#define F_TA_B  18432            // A tile bytes (128x72 bf16)
#define F_TB_B  13824            // B tile bytes (96x72 bf16)
#define F_BUF_B 64512
#define F_SM    129024

__device__ __forceinline__ void f_stageA(uint32_t sdst, const __nv_bfloat16* __restrict__ g,
                                         long long row0, int k0, int tid)
{
#pragma unroll
    for (int it = 0; it < 3; it++) {
        int u = it * 384 + tid;
        if (u < 1024) {
            int row = u >> 3, q = u & 7;
            cp16(sdst + row * (LDSK * 2) + q * 16, g + (row0 + row) * (long long)DSq + k0 + q * 8);
        }
    }
}
__device__ __forceinline__ void f_stageB(uint32_t sdst, const __nv_bfloat16* __restrict__ g,
                                         int n0, int k0, int tid)
{
#pragma unroll
    for (int it = 0; it < 2; it++) {
        int u = it * 384 + tid;
        int row = u >> 3, q = u & 7;
        cp16(sdst + row * (LDSK * 2) + q * 16, g + (size_t)(n0 + row) * DSq + k0 + q * 8);
    }
}

__global__ __launch_bounds__(384, 1)
void fused_scan_mem(const float* __restrict__ Q, const float* __restrict__ rw,
                    const float* __restrict__ state0, const float* __restrict__ W_hh,
                    const float* __restrict__ b_ih, const float* __restrict__ b_hh,
                    float* __restrict__ state_out,
                    __nv_bfloat16* __restrict__ sth, __nv_bfloat16* __restrict__ stl,
                    const __nv_bfloat16* __restrict__ Wmh, const __nv_bfloat16* __restrict__ Wml,
                    const float* __restrict__ bm, float* __restrict__ Cmem)
{
    extern __shared__ __align__(16) char smem[];
    const int tid = threadIdx.x;

    if (blockIdx.x < 64) {
        // ================= SCAN ROLE =================
        float* hbuf = reinterpret_cast<float*>(smem);              // 128 floats
        float* gh   = hbuf + 128;                                  // 384 floats
        const int b = blockIdx.x >> 3;
        const int e = blockIdx.x & 7;
        const int j = tid;

        unsigned long long w2r[64];
        {
            const unsigned long long* wr = reinterpret_cast<const unsigned long long*>(W_hh + (size_t)j * DSq);
#pragma unroll
            for (int i = 0; i < 64; i++) w2r[i] = wr[i];
        }
        if (j < 32) reinterpret_cast<float4*>(hbuf)[j] = reinterpret_cast<const float4*>(state0 + e * DSq)[j];
        const float bhh = b_hh[j];
        float bir = 0.f, biz = 0.f, bin = 0.f;
        if (j < DSq) { bir = b_ih[j]; biz = b_ih[DSq + j]; bin = b_ih[2 * DSq + j]; }
        __syncthreads();

        const ulonglong2* hs2 = reinterpret_cast<const ulonglong2*>(hbuf);

        float qr = 0.f, qz = 0.f, qn = 0.f, rwv = 0.f;
        if (j < DSq) {
            const float* qp = Q + (size_t)(b * Tq) * (3 * DSq);
            qr = qp[j]; qz = qp[DSq + j]; qn = qp[2 * DSq + j];
            rwv = rw[(size_t)(b * Tq) * NEq + e];
        }

        for (int t = 0; t < Tq; t++) {
            const int row = b * Tq + t;
            float nqr = 0.f, nqz = 0.f, nqn = 0.f, nrw = 0.f;
            if (t + 1 < Tq && j < DSq) {
                const float* qp = Q + (size_t)(row + 1) * (3 * DSq);
                nqr = __ldg(qp + j); nqz = __ldg(qp + DSq + j); nqn = __ldg(qp + 2 * DSq + j);
                nrw = __ldg(rw + (size_t)(row + 1) * NEq + e);
            }
            unsigned long long a0 = 0, a1 = 0, a2 = 0, a3 = 0;
#pragma unroll
            for (int i = 0; i < 32; i += 2) {
                ulonglong2 h0 = hs2[i];
                ulonglong2 h1 = hs2[i + 1];
                a0 = fma_f32x2(w2r[i * 2 + 0], h0.x, a0);
                a1 = fma_f32x2(w2r[i * 2 + 1], h0.y, a1);
                a2 = fma_f32x2(w2r[i * 2 + 2], h1.x, a2);
                a3 = fma_f32x2(w2r[i * 2 + 3], h1.y, a3);
            }
            float acc = ((lo_f(a0) + hi_f(a0)) + (lo_f(a1) + hi_f(a1)))
                      + ((lo_f(a2) + hi_f(a2)) + (lo_f(a3) + hi_f(a3)));
            gh[j] = acc + bhh;
            __syncthreads();
            if (j < DSq) {
                float gir = fmaf(rwv, qr, bir);
                float giz = fmaf(rwv, qz, biz);
                float gin = fmaf(rwv, qn, bin);
                float r = __fdividef(1.f, 1.f + __expf(-(gir + gh[j])));
                float z = __fdividef(1.f, 1.f + __expf(-(giz + gh[DSq + j])));
                float xn = fmaf(r, gh[2 * DSq + j], gin);
                float ex = __expf(-2.f * xn);
                float n = __fdividef(1.f - ex, 1.f + ex);
                float hnew = fmaf(z, hbuf[j] - n, n);
                hbuf[j] = hnew;
                size_t idx = (((size_t)row) * NEq + e) * DSq + j;
                state_out[idx] = hnew;
                __nv_bfloat16 hh = __float2bfloat16(hnew);
                sth[idx] = hh;
                stl[idx] = __float2bfloat16(hnew - __bfloat162float(hh));
            }
            __syncthreads();
            if ((t & 63) == 63 && j == 0) {
                __threadfence();
                atomicAdd(&g_prog[b * 16 + (t >> 6)], 1);
            }
            qr = nqr; qz = nqz; qn = nqn; rwv = nrw;
        }
    } else {
        // ================= MEMORY-GEMM ROLE =================
        __nv_bfloat16* s16 = reinterpret_cast<__nv_bfloat16*>(smem);
        const uint32_t sb = smem_u32(smem);
        const int g = blockIdx.x - 64;
        const int n0 = (g & 7) * 96;
        const int r = g >> 3;             // 0..511, ascending t
        const int b = r & 7;
        const int tb16 = r >> 3;          // 16-step chunk index 0..63
        const long long m0 = (long long)b * 8192 + (long long)tb16 * 128;
        const int kflag = b * 16 + (tb16 >> 2);

        if (tid == 0) {
            while (atomicAdd(&g_prog[kflag], 0) < 8) { }
        }
        __syncthreads();
        __threadfence();

        const int wid = tid >> 5;          // 0..11
        const int wy = wid & 3;            // 4 M-rows of 32
        const int wx = wid >> 2;           // 3 N-cols of 32

        wmma::fragment<wmma::accumulator, 16, 16, 16, float> acc[2][2];
#pragma unroll
        for (int i = 0; i < 2; i++)
#pragma unroll
            for (int jj = 0; jj < 2; jj++) wmma::fill_fragment(acc[i][jj], 0.0f);

        // prologue: chunk 0 into buffer 0
        f_stageA(sb,           g_state_hi, m0, 0, tid);
        f_stageA(sb + F_TA_B,  g_state_lo, m0, 0, tid);
        f_stageB(sb + F_EBHI * 2, Wmh, n0, 0, tid);
        f_stageB(sb + F_EBLO * 2, Wml, n0, 0, tid);
        CP_COMMIT();

        for (int c = 0; c < 2; c++) {
            if (c == 0) {
                uint32_t bn = sb + F_BUF_B;
                f_stageA(bn,           g_state_hi, m0, BKT, tid);
                f_stageA(bn + F_TA_B,  g_state_lo, m0, BKT, tid);
                f_stageB(bn + F_EBHI * 2, Wmh, n0, BKT, tid);
                f_stageB(bn + F_EBLO * 2, Wml, n0, BKT, tid);
                CP_COMMIT();
                CP_WAIT1();
            } else {
                CP_WAIT0();
            }
            __syncthreads();
            const __nv_bfloat16* base = s16 + (c & 1) * F_EBUF;
#pragma unroll
            for (int ks = 0; ks < BKT; ks += 16) {
                wmma::fragment<wmma::matrix_b, 16, 16, 16, __nv_bfloat16, wmma::col_major> bh[2], bl[2];
                wmma::fragment<wmma::matrix_a, 16, 16, 16, __nv_bfloat16, wmma::row_major> ah[2], al[2];
#pragma unroll
                for (int fn = 0; fn < 2; fn++) {
                    const int nb = wx * 32 + fn * 16;
                    wmma::load_matrix_sync(bh[fn], base + F_EBHI + nb * LDSK + ks, LDSK);
                    wmma::load_matrix_sync(bl[fn], base + F_EBLO + nb * LDSK + ks, LDSK);
                }
#pragma unroll
                for (int fm = 0; fm < 2; fm++) {
                    const int mb = wy * 32 + fm * 16;
                    wmma::load_matrix_sync(ah[fm], base + mb * LDSK + ks, LDSK);
                    wmma::load_matrix_sync(al[fm], base + F_EALO + mb * LDSK + ks, LDSK);
                }
#pragma unroll
                for (int fm = 0; fm < 2; fm++)
#pragma unroll
                    for (int fn = 0; fn < 2; fn++)
                        wmma::mma_sync(acc[fm][fn], ah[fm], bh[fn], acc[fm][fn]);
#pragma unroll
                for (int fm = 0; fm < 2; fm++)
#pragma unroll
                    for (int fn = 0; fn < 2; fn++)
                        wmma::mma_sync(acc[fm][fn], ah[fm], bl[fn], acc[fm][fn]);
#pragma unroll
                for (int fm = 0; fm < 2; fm++)
#pragma unroll
                    for (int fn = 0; fn < 2; fn++)
                        wmma::mma_sync(acc[fm][fn], al[fm], bh[fn], acc[fm][fn]);
            }
            __syncthreads();
        }

        float* Cs = reinterpret_cast<float*>(smem);
#pragma unroll
        for (int fm = 0; fm < 2; fm++)
#pragma unroll
            for (int fn = 0; fn < 2; fn++)
                wmma::store_matrix_sync(Cs + (wy * 32 + fm * 16) * 96 + wx * 32 + fn * 16,
                                        acc[fm][fn], 96, wmma::mem_row_major);
        __syncthreads();
#pragma unroll
        for (int it = 0; it < 8; it++) {
            int flat = it * 384 + tid;       // 3072 float4 units
            int row = flat / 24, q = flat % 24;
            float4 v = *reinterpret_cast<const float4*>(Cs + row * 96 + q * 4);
            const float4 bv = *reinterpret_cast<const float4*>(bm + n0 + q * 4);
            v.x += bv.x; v.y += bv.y; v.z += bv.z; v.w += bv.w;
            *reinterpret_cast<float4*>(Cmem + (size_t)(m0 + row) * Dq + n0 + q * 4) = v;
        }
    }
}

// ---------------------------------------------------------------------------
// Weight prep (+ progress flag reset each launch)
// ---------------------------------------------------------------------------
__global__ void prep_weights(const float* __restrict__ Wi, const float* __restrict__ W_ih,
                             const float* __restrict__ Wm, const float* __restrict__ Ws,
                             const float* __restrict__ Wh1, const float* __restrict__ Wt1,
                             const float* __restrict__ Wv1,
                             const float* __restrict__ bh1, const float* __restrict__ bt1,
                             const float* __restrict__ bv1,
                             const float* __restrict__ Wh2, const float* __restrict__ Wt2,
                             const float* __restrict__ Wv2)
{
    if (blockIdx.x == 0 && threadIdx.x < 128) g_prog[threadIdx.x] = 0;

    const int N_Wi = DSq * Dq, N_Wih = 3 * DSq * DSq, N_Wm = Dq * DSq;
    const int N_W1 = 256 * DSq;
    const long long N_Ws = (long long)Dq * NEq * Dq;
    long long idx = (long long)blockIdx.x * 256 + threadIdx.x;
    __nv_bfloat16 h, l;
    if (idx < N_Wi)  { hilo(Wi[idx], h, l);   g_Wi_hi[idx] = h;  g_Wi_lo[idx] = l;  return; }
    idx -= N_Wi;
    if (idx < N_Wih) { hilo(W_ih[idx], h, l); g_Wih_hi[idx] = h; g_Wih_lo[idx] = l; return; }
    idx -= N_Wih;
    if (idx < N_Wm)  { hilo(Wm[idx], h, l);   g_Wm_hi[idx] = h;  g_Wm_lo[idx] = l;  return; }
    idx -= N_Wm;
    if (idx < N_Wm) {
        int j = (int)(idx / DSq), k = (int)(idx % DSq);
        hilo(Wm[idx], h, l);
        g_WmT_hi[(size_t)k * Dq + j] = h; g_WmT_lo[(size_t)k * Dq + j] = l; return;
    }
    idx -= N_Wm;
    if (idx < N_W1) {
        int r = (int)(idx / DSq), c = (int)(idx % DSq);
        float v = (r < 64) ? Wh1[r * DSq + c] : (r < 128) ? Wt1[(r - 64) * DSq + c]
                : (r < 192) ? Wv1[(r - 128) * DSq + c] : 0.f;
        hilo(v, h, l); g_W1_hi[idx] = h; g_W1_lo[idx] = l; return;
    }
    idx -= N_W1;
    if (idx < 256) {
        int i = (int)idx;
        g_b1cat[i] = (i < 64) ? bh1[i] : (i < 128) ? bt1[i - 64] : (i < 192) ? bv1[i - 128] : 0.f;
        g_W2cat[i] = (i < 64) ? Wh2[i] : (i < 128) ? Wt2[i - 64] : (i < 192) ? Wv2[i - 128] : 0.f;
        return;
    }
    idx -= 256;
    if (idx < N_Ws) { hilo(Ws[idx], h, l); g_Ws_hi[idx] = h; g_Ws_lo[idx] = l; }
}
#define PREP_TOTAL (DSq*Dq + 3*DSq*DSq + Dq*DSq + Dq*DSq + 256*DSq + 256 + Dq*NEq*Dq)

// ---------------------------------------------------------------------------
// Route softmax + fused h_seq hi/lo conversion
// ---------------------------------------------------------------------------
__global__ __launch_bounds__(256)
void route_cvt(const float* __restrict__ h_seq, const float* __restrict__ ek,
               float* __restrict__ rw,
               __nv_bfloat16* __restrict__ hi, __nv_bfloat16* __restrict__ lo)
{
    const int row = blockIdx.x;
    const int w = threadIdx.x >> 5, lane = threadIdx.x & 31;
    const float* hr = h_seq + (size_t)row * Dq;
    const float* er = ek + (size_t)w * Dq;
    float s = 0.f;
#pragma unroll 4
    for (int k = lane; k < Dq; k += 32) s = fmaf(hr[k], er[k], s);
#pragma unroll
    for (int o = 16; o; o >>= 1) s += __shfl_xor_sync(0xffffffffu, s, o);
    __shared__ float lg[NEq];
    if (lane == 0) lg[w] = s;

#pragma unroll
    for (int i = threadIdx.x; i < Dq; i += 256) {
        __nv_bfloat16 h, l; hilo(hr[i], h, l);
        hi[(size_t)row * Dq + i] = h;
        lo[(size_t)row * Dq + i] = l;
    }
    __syncthreads();
    if (threadIdx.x == 0) {
        const float inv = 0.036084391824351615f;
        float v[NEq], m = -1e30f;
#pragma unroll
        for (int e = 0; e < NEq; e++) { v[e] = lg[e] * inv; m = fmaxf(m, v[e]); }
        float den = 0.f;
#pragma unroll
        for (int e = 0; e < NEq; e++) { v[e] = __expf(v[e] - m); den += v[e]; }
        float id = 1.f / den;
#pragma unroll
        for (int e = 0; e < NEq; e++) rw[(size_t)row * NEq + e] = v[e] * id;
    }
}

__global__ __launch_bounds__(256)
void pbias_kernel(const float* __restrict__ Ws, const float* __restrict__ bm,
                  const float* __restrict__ bs, float* __restrict__ pb)
{
    int d = blockIdx.x, tid = threadIdx.x;
    float s = 0.f;
    for (int j = tid; j < NEq * Dq; j += 256) s = fmaf(bm[j % Dq], Ws[(size_t)d * (NEq * Dq) + j], s);
    __shared__ float red[256];
    red[tid] = s; __syncthreads();
    for (int o = 128; o; o >>= 1) { if (tid < o) red[tid] += red[tid + o]; __syncthreads(); }
    if (tid == 0) pb[d] = red[0] + bs[d];
}

// ---------------------------------------------------------------------------
// Launch
// ---------------------------------------------------------------------------
extern "C" void kernel_launch(void* const* d_in, const int* in_sizes, int n_in,
                              void* d_out, int out_size)
{
    const float* h_seq = (const float*)d_in[0];
    const float* ek    = (const float*)d_in[1];
    const float* state0= (const float*)d_in[2];
    const float* Wi    = (const float*)d_in[3];
    const float* bi    = (const float*)d_in[4];
    const float* W_ih  = (const float*)d_in[5];
    const float* W_hh  = (const float*)d_in[6];
    const float* b_ih  = (const float*)d_in[7];
    const float* b_hh  = (const float*)d_in[8];
    const float* Wm    = (const float*)d_in[9];
    const float* bm    = (const float*)d_in[10];
    const float* Ws    = (const float*)d_in[11];
    const float* bs    = (const float*)d_in[12];
    const float* Wh1   = (const float*)d_in[13];
    const float* bh1   = (const float*)d_in[14];
    const float* Wh2   = (const float*)d_in[15];
    const float* bh2   = (const float*)d_in[16];
    const float* Wt1   = (const float*)d_in[17];
    const float* bt1   = (const float*)d_in[18];
    const float* Wt2   = (const float*)d_in[19];
    const float* bt2   = (const float*)d_in[20];
    const float* Wv1   = (const float*)d_in[21];
    const float* bv1   = (const float*)d_in[22];
    const float* Wv2   = (const float*)d_in[23];
    const float* bv2   = (const float*)d_in[24];
    float* out = (float*)d_out;

    cudaFuncSetAttribute(gemm_tc, cudaFuncAttributeMaxDynamicSharedMemorySize, SM_BYTES);
    cudaFuncSetAttribute(gemm_heads, cudaFuncAttributeMaxDynamicSharedMemorySize, SM_BYTES);
    cudaFuncSetAttribute(fused_scan_mem, cudaFuncAttributeMaxDynamicSharedMemorySize, F_SM);

#define SYMF(p, s) float* p; cudaGetSymbolAddress((void**)&p, s)
#define SYMB(p, s) __nv_bfloat16* p; cudaGetSymbolAddress((void**)&p, s)
    SYMB(p_hsh, g_hseq_hi);  SYMB(p_hsl, g_hseq_lo);
    SYMB(p_sth, g_state_hi); SYMB(p_stl, g_state_lo);
    SYMB(p_prh, g_projh);    SYMB(p_prl, g_projl);
    SYMB(p_wsh, g_Ws_hi);    SYMB(p_wsl, g_Ws_lo);
    SYMB(p_wih, g_Wi_hi);    SYMB(p_wil, g_Wi_lo);
    SYMB(p_whh, g_Wih_hi);   SYMB(p_whl, g_Wih_lo);
    SYMB(p_wmh, g_Wm_hi);    SYMB(p_wml, g_Wm_lo);
    SYMB(p_wth, g_WmT_hi);   SYMB(p_wtl, g_WmT_lo);
    SYMB(p_mch, g_Mc_hi);    SYMB(p_mcl, g_Mc_lo);
    SYMB(p_w1h, g_W1_hi);    SYMB(p_w1l, g_W1_lo);
    SYMF(p_Q, g_Q); SYMF(p_pb, g_pbias);
    SYMF(p_b1, g_b1cat);  SYMF(p_w2, g_W2cat);

    // 1) prep (+flag reset) + route(+cvt)
    prep_weights<<<(PREP_TOTAL + 255) / 256, 256>>>(Wi, W_ih, Wm, Ws, Wh1, Wt1, Wv1,
                                                    bh1, bt1, bv1, Wh2, Wt2, Wv2);
    route_cvt<<<ROWS, 256>>>(h_seq, ek, out + RW_OFF, p_hsh, p_hsl);

    // 2) proj = h_seq @ Wi^T + bi  (bf16 hi/lo only)
    gemm_tc<<<dim3(1, ROWS / 128, 1), 512, SM_BYTES>>>(p_hsh, p_hsl, Dq, 0,
                                                       p_wih, p_wil, Dq,
                                                       nullptr, DSq, 0, bi, Dq / BKT,
                                                       p_prh, p_prl);

    // 3) Q = proj @ W_ih^T
    gemm_tc<<<dim3(3, ROWS / 128, 1), 512, SM_BYTES>>>(p_prh, p_prl, DSq, 0,
                                                       p_whh, p_whl, DSq,
                                                       p_Q, 3 * DSq, 0, nullptr, DSq / BKT,
                                                       nullptr, nullptr);

    // 4) Mc = per-entity Ws_e @ Wm (bf16 hi/lo only) + pbias
    gemm_tc<<<dim3(1, Dq / 128, NEq), 512, SM_BYTES>>>(p_wsh, p_wsl, NEq * Dq, Dq,
                                                       p_wth, p_wtl, Dq,
                                                       nullptr, NEq * DSq, DSq, nullptr, Dq / BKT,
                                                       p_mch, p_mcl);
    pbias_kernel<<<Dq, 256>>>(Ws, bm, bs, p_pb);

    // 5) FUSED: scan (blocks 0..63) + memory gemm (blocks 64..4159, flag-gated)
    fused_scan_mem<<<64 + 4096, 384, F_SM>>>(p_Q, out + RW_OFF, state0, W_hh, b_ih, b_hh,
                                             out + STATE_OFF, p_sth, p_stl,
                                             p_wmh, p_wml, bm, out + MEM_OFF);

    // 6) pooled = state_flat @ Mc^T + pbias
    gemm_tc<<<dim3(Dq / 128, ROWS / 128, 1), 512, SM_BYTES>>>(p_sth, p_stl, NEq * DSq, 0,
                                                              p_mch, p_mcl, NEq * DSq,
                                                              out + POOLED_OFF, Dq, 0, p_pb, (NEq * DSq) / BKT,
                                                              nullptr, nullptr);

    // 7) heads fused -> holder/tagged/visible
    gemm_heads<<<dim3(2, SROWS / 128, 1), 512, SM_BYTES>>>(p_sth, p_stl, p_w1h, p_w1l,
                                                           p_b1, p_w2, bh2, bt2, bv2,
                                                           out + HOLDER_OFF, out + TAGGED_OFF, out + VISIBLE_OFF);

    (void)in_sizes; (void)n_in; (void)out_size;
}

// round 11
// speedup vs baseline: 2.3420x; 1.0918x over previous
#include <cuda_runtime.h>
#include <cuda_bf16.h>
#include <mma.h>
#include <math.h>
#include <stdint.h>

using namespace nvcuda;

#define Bq   8
#define Tq   1024
#define Dq   768
#define NEq  8
#define DSq  128
#define ROWS (Bq*Tq)            // 8192
#define SROWS (Bq*Tq*NEq)       // 65536

#define POOLED_OFF  0ll
#define MEM_OFF     6291456ll
#define STATE_OFF   56623104ll
#define HOLDER_OFF  65011712ll
#define TAGGED_OFF  65077248ll
#define VISIBLE_OFF 65142784ll
#define RW_OFF      65208320ll

// ---------------------------------------------------------------------------
// Scratch
// ---------------------------------------------------------------------------
__device__ __align__(16) __nv_bfloat16 g_hseq_hi[ROWS*Dq],    g_hseq_lo[ROWS*Dq];
__device__ __align__(16) __nv_bfloat16 g_state_hi[SROWS*DSq], g_state_lo[SROWS*DSq];
__device__ __align__(16) __nv_bfloat16 g_projh[ROWS*DSq],     g_projl[ROWS*DSq];
__device__ __align__(16) __nv_bfloat16 g_Ws_hi[Dq*NEq*Dq],    g_Ws_lo[Dq*NEq*Dq];
__device__ __align__(16) __nv_bfloat16 g_Wi_hi[DSq*Dq],       g_Wi_lo[DSq*Dq];
__device__ __align__(16) __nv_bfloat16 g_Wih_hi[3*DSq*DSq],   g_Wih_lo[3*DSq*DSq];
__device__ __align__(16) __nv_bfloat16 g_Wm_hi[Dq*DSq],       g_Wm_lo[Dq*DSq];
__device__ __align__(16) __nv_bfloat16 g_WmT_hi[DSq*Dq],      g_WmT_lo[DSq*Dq];
__device__ __align__(16) __nv_bfloat16 g_Mc_hi[Dq*NEq*DSq],   g_Mc_lo[Dq*NEq*DSq];
__device__ __align__(16) __nv_bfloat16 g_W1_hi[256*DSq],      g_W1_lo[256*DSq];
__device__ __align__(16) float g_Q[ROWS*3*DSq];
__device__ __align__(16) float g_pbias[Dq];
__device__ __align__(16) float g_b1cat[256];
__device__ __align__(16) float g_W2cat[256];
__device__ int g_prog[128];        // per (b, 64-step chunk) completion counters

// ---------------------------------------------------------------------------
// helpers
// ---------------------------------------------------------------------------
__device__ __forceinline__ unsigned long long fma_f32x2(unsigned long long a, unsigned long long b, unsigned long long c) {
    unsigned long long d;
    asm("fma.rn.f32x2 %0, %1, %2, %3;" : "=l"(d) : "l"(a), "l"(b), "l"(c));
    return d;
}
__device__ __forceinline__ float lo_f(unsigned long long v) { return __uint_as_float((uint32_t)v); }
__device__ __forceinline__ float hi_f(unsigned long long v) { return __uint_as_float((uint32_t)(v >> 32)); }

__device__ __forceinline__ uint32_t smem_u32(const void* p) {
    uint32_t a;
    asm("{ .reg .u64 t; cvta.to.shared.u64 t, %1; cvt.u32.u64 %0, t; }" : "=r"(a) : "l"(p));
    return a;
}
#define CP_COMMIT() asm volatile("cp.async.commit_group;" ::: "memory")
#define CP_WAIT0()  asm volatile("cp.async.wait_group 0;" ::: "memory")
#define CP_WAIT1()  asm volatile("cp.async.wait_group 1;" ::: "memory")

__device__ __forceinline__ void cp16(uint32_t d, const void* s) {
    asm volatile("cp.async.cg.shared.global [%0], [%1], 16;" :: "r"(d), "l"(s));
}

__device__ __forceinline__ void hilo(float v, __nv_bfloat16& h, __nv_bfloat16& l) {
    h = __float2bfloat16(v);
    l = __float2bfloat16(v - __bfloat162float(h));
}

// ---------------------------------------------------------------------------
// Generic GEMM (proj/Q/Mc): block 128x128, BK=64, 512 thr, 16 warps.
// ---------------------------------------------------------------------------
#define BKT    64
#define LDSK   72
#define E_ALO  9216
#define E_BHI  18432
#define E_BLO  27648
#define E_BUF  36864
#define TILE_B 18432
#define BUF_B  73728
#define SM_BYTES 147456

__device__ __forceinline__ void stage_async(uint32_t sdst, const __nv_bfloat16* __restrict__ g,
                                            long long row0, int k0, int ld, int tid)
{
#pragma unroll
    for (int it = 0; it < 2; it++) {
        int flat = it * 512 + tid;
        int row = flat >> 3, q = flat & 7;
        cp16(sdst + row * (LDSK * 2) + q * 16, g + (row0 + row) * (long long)ld + k0 + q * 8);
    }
}

__device__ __forceinline__ void stage4(uint32_t bufb,
                                       const __nv_bfloat16* Ahi, const __nv_bfloat16* Alo,
                                       const __nv_bfloat16* Bhi, const __nv_bfloat16* Blo,
                                       long long m0, int n0, int ka, int kb, int lda, int ldb, int tid)
{
    stage_async(bufb,              Ahi, m0, ka, lda, tid);
    stage_async(bufb + TILE_B,     Alo, m0, ka, lda, tid);
    stage_async(bufb + 2 * TILE_B, Bhi, n0, kb, ldb, tid);
    stage_async(bufb + 3 * TILE_B, Blo, n0, kb, ldb, tid);
    CP_COMMIT();
}

__global__ __launch_bounds__(512, 1)
void gemm_tc(const __nv_bfloat16* __restrict__ Ahi, const __nv_bfloat16* __restrict__ Alo, int lda, int aK0z,
             const __nv_bfloat16* __restrict__ Bhi, const __nv_bfloat16* __restrict__ Blo, int ldb,
             float* __restrict__ C, int ldc, int cZoff,
             const float* __restrict__ bias, int nChunks,
             __nv_bfloat16* __restrict__ outH, __nv_bfloat16* __restrict__ outL)
{
    extern __shared__ __align__(16) char smem[];
    __nv_bfloat16* s16 = reinterpret_cast<__nv_bfloat16*>(smem);
    const uint32_t sb = smem_u32(smem);
    const int tid = threadIdx.x, wid = tid >> 5;
    const int wy = wid >> 2, wx = wid & 3;
    const long long m0 = (long long)blockIdx.y * 128;
    const int n0 = blockIdx.x * 128;
    const int aK0 = blockIdx.z * aK0z;
    const int cOff = n0 + blockIdx.z * cZoff;

    wmma::fragment<wmma::accumulator, 16, 16, 16, float> acc[2][2];
#pragma unroll
    for (int i = 0; i < 2; i++)
#pragma unroll
        for (int j = 0; j < 2; j++) wmma::fill_fragment(acc[i][j], 0.0f);

    stage4(sb, Ahi, Alo, Bhi, Blo, m0, n0, aK0, 0, lda, ldb, tid);

    for (int c = 0; c < nChunks; c++) {
        if (c + 1 < nChunks) {
            stage4(sb + ((c + 1) & 1) * BUF_B, Ahi, Alo, Bhi, Blo, m0, n0,
                   aK0 + (c + 1) * BKT, (c + 1) * BKT, lda, ldb, tid);
            CP_WAIT1();
        } else {
            CP_WAIT0();
        }
        __syncthreads();
        const __nv_bfloat16* base = s16 + (c & 1) * E_BUF;
#pragma unroll
        for (int ks = 0; ks < BKT; ks += 16) {
            wmma::fragment<wmma::matrix_b, 16, 16, 16, __nv_bfloat16, wmma::col_major> bh[2], bl[2];
            wmma::fragment<wmma::matrix_a, 16, 16, 16, __nv_bfloat16, wmma::row_major> ah[2], al[2];
#pragma unroll
            for (int fn = 0; fn < 2; fn++) {
                const int nb = wx * 32 + fn * 16;
                wmma::load_matrix_sync(bh[fn], base + E_BHI + nb * LDSK + ks, LDSK);
                wmma::load_matrix_sync(bl[fn], base + E_BLO + nb * LDSK + ks, LDSK);
            }
#pragma unroll
            for (int fm = 0; fm < 2; fm++) {
                const int mb = wy * 32 + fm * 16;
                wmma::load_matrix_sync(ah[fm], base + mb * LDSK + ks, LDSK);
                wmma::load_matrix_sync(al[fm], base + E_ALO + mb * LDSK + ks, LDSK);
            }
#pragma unroll
            for (int fm = 0; fm < 2; fm++)
#pragma unroll
                for (int fn = 0; fn < 2; fn++)
                    wmma::mma_sync(acc[fm][fn], ah[fm], bh[fn], acc[fm][fn]);
#pragma unroll
            for (int fm = 0; fm < 2; fm++)
#pragma unroll
                for (int fn = 0; fn < 2; fn++)
                    wmma::mma_sync(acc[fm][fn], ah[fm], bl[fn], acc[fm][fn]);
#pragma unroll
            for (int fm = 0; fm < 2; fm++)
#pragma unroll
                for (int fn = 0; fn < 2; fn++)
                    wmma::mma_sync(acc[fm][fn], al[fm], bh[fn], acc[fm][fn]);
        }
        __syncthreads();
    }

    float* Cs = reinterpret_cast<float*>(smem);
#pragma unroll
    for (int fm = 0; fm < 2; fm++)
#pragma unroll
        for (int fn = 0; fn < 2; fn++)
            wmma::store_matrix_sync(Cs + (wy * 32 + fm * 16) * 128 + wx * 32 + fn * 16,
                                    acc[fm][fn], 128, wmma::mem_row_major);
    __syncthreads();
#pragma unroll
    for (int it = 0; it < 8; it++) {
        int flat = it * 512 + tid;
        int row = flat >> 5, q = flat & 31;
        float4 v = *reinterpret_cast<const float4*>(Cs + row * 128 + q * 4);
        if (bias) {
            const float4 bv = *reinterpret_cast<const float4*>(bias + n0 + q * 4);
            v.x += bv.x; v.y += bv.y; v.z += bv.z; v.w += bv.w;
        }
        size_t co = (size_t)(m0 + row) * ldc + cOff + q * 4;
        if (C) *reinterpret_cast<float4*>(C + co) = v;
        if (outH) {
            __nv_bfloat16 h0,l0,h1,l1,h2,l2,h3,l3;
            hilo(v.x,h0,l0); hilo(v.y,h1,l1); hilo(v.z,h2,l2); hilo(v.w,h3,l3);
            __nv_bfloat162 ph0 = {h0,h1}, ph1 = {h2,h3}, pl0 = {l0,l1}, pl1 = {l2,l3};
            *reinterpret_cast<__nv_bfloat162*>(outH + co)     = ph0;
            *reinterpret_cast<__nv_bfloat162*>(outH + co + 2) = ph1;
            *reinterpret_cast<__nv_bfloat162*>(outL + co)     = pl0;
            *reinterpret_cast<__nv_bfloat162*>(outL + co + 2) = pl1;
        }
    }
}

// ---------------------------------------------------------------------------
// Heads GEMM (K=128) with fused GELU . W2 epilogue
// ---------------------------------------------------------------------------
__device__ __forceinline__ float gelu_exact(float x) {
    return 0.5f * x * (1.0f + erff(x * 0.70710678118654752f));
}

__global__ __launch_bounds__(512, 1)
void gemm_heads(const __nv_bfloat16* __restrict__ Ahi, const __nv_bfloat16* __restrict__ Alo,
                const __nv_bfloat16* __restrict__ Bhi, const __nv_bfloat16* __restrict__ Blo,
                const float* __restrict__ b1cat, const float* __restrict__ W2cat,
                const float* __restrict__ bh2, const float* __restrict__ bt2, const float* __restrict__ bv2,
                float* __restrict__ oH, float* __restrict__ oT, float* __restrict__ oV)
{
    extern __shared__ __align__(16) char smem[];
    __nv_bfloat16* s16 = reinterpret_cast<__nv_bfloat16*>(smem);
    const uint32_t sb = smem_u32(smem);
    const int tid = threadIdx.x, wid = tid >> 5;
    const int wy = wid >> 2, wx = wid & 3;
    const long long m0 = (long long)blockIdx.y * 128;
    const int n0 = blockIdx.x * 128;
    const int nChunks = 2;

    wmma::fragment<wmma::accumulator, 16, 16, 16, float> acc[2][2];
#pragma unroll
    for (int i = 0; i < 2; i++)
#pragma unroll
        for (int j = 0; j < 2; j++) wmma::fill_fragment(acc[i][j], 0.0f);

    stage4(sb, Ahi, Alo, Bhi, Blo, m0, n0, 0, 0, DSq, DSq, tid);

    for (int c = 0; c < nChunks; c++) {
        if (c + 1 < nChunks) {
            stage4(sb + ((c + 1) & 1) * BUF_B, Ahi, Alo, Bhi, Blo, m0, n0,
                   (c + 1) * BKT, (c + 1) * BKT, DSq, DSq, tid);
            CP_WAIT1();
        } else {
            CP_WAIT0();
        }
        __syncthreads();
        const __nv_bfloat16* base = s16 + (c & 1) * E_BUF;
#pragma unroll
        for (int ks = 0; ks < BKT; ks += 16) {
            wmma::fragment<wmma::matrix_b, 16, 16, 16, __nv_bfloat16, wmma::col_major> bh[2], bl[2];
            wmma::fragment<wmma::matrix_a, 16, 16, 16, __nv_bfloat16, wmma::row_major> ah[2], al[2];
#pragma unroll
            for (int fn = 0; fn < 2; fn++) {
                const int nb = wx * 32 + fn * 16;
                wmma::load_matrix_sync(bh[fn], base + E_BHI + nb * LDSK + ks, LDSK);
                wmma::load_matrix_sync(bl[fn], base + E_BLO + nb * LDSK + ks, LDSK);
            }
#pragma unroll
            for (int fm = 0; fm < 2; fm++) {
                const int mb = wy * 32 + fm * 16;
                wmma::load_matrix_sync(ah[fm], base + mb * LDSK + ks, LDSK);
                wmma::load_matrix_sync(al[fm], base + E_ALO + mb * LDSK + ks, LDSK);
            }
#pragma unroll
            for (int fm = 0; fm < 2; fm++)
#pragma unroll
                for (int fn = 0; fn < 2; fn++)
                    wmma::mma_sync(acc[fm][fn], ah[fm], bh[fn], acc[fm][fn]);
#pragma unroll
            for (int fm = 0; fm < 2; fm++)
#pragma unroll
                for (int fn = 0; fn < 2; fn++)
                    wmma::mma_sync(acc[fm][fn], ah[fm], bl[fn], acc[fm][fn]);
#pragma unroll
            for (int fm = 0; fm < 2; fm++)
#pragma unroll
                for (int fn = 0; fn < 2; fn++)
                    wmma::mma_sync(acc[fm][fn], al[fm], bh[fn], acc[fm][fn]);
        }
        __syncthreads();
    }

    float* Cs = reinterpret_cast<float*>(smem);
#pragma unroll
    for (int fm = 0; fm < 2; fm++)
#pragma unroll
        for (int fn = 0; fn < 2; fn++)
            wmma::store_matrix_sync(Cs + (wy * 32 + fm * 16) * 128 + wx * 32 + fn * 16,
                                    acc[fm][fn], 128, wmma::mem_row_major);
    __syncthreads();

    if (tid < 256) {
        const int row = tid >> 1, half = tid & 1;
        const int headIdx = blockIdx.x * 2 + half;
        if (headIdx < 3) {
            float dot = 0.f;
#pragma unroll
            for (int q = 0; q < 16; q++) {
                int qq = (q + row) & 15;
                float4 v = *reinterpret_cast<const float4*>(Cs + row * 128 + half * 64 + qq * 4);
                int col = n0 + half * 64 + qq * 4;
                dot = fmaf(gelu_exact(v.x + __ldg(b1cat + col + 0)), __ldg(W2cat + col + 0), dot);
                dot = fmaf(gelu_exact(v.y + __ldg(b1cat + col + 1)), __ldg(W2cat + col + 1), dot);
                dot = fmaf(gelu_exact(v.z + __ldg(b1cat + col + 2)), __ldg(W2cat + col + 2), dot);
                dot = fmaf(gelu_exact(v.w + __ldg(b1cat + col + 3)), __ldg(W2cat + col + 3), dot);
            }
            float* op = (headIdx == 0) ? oH : (headIdx == 1) ? oT : oV;
            float b2 = (headIdx == 0) ? __ldg(bh2) : (headIdx == 1) ? __ldg(bt2) : __ldg(bv2);
            op[m0 + row] = dot + b2;
        }
    }
}

// ---------------------------------------------------------------------------
// FUSED scan + {memory, pooled} GEMM persistent kernel (384 threads).
// Blocks 0..63: scan chains; publish g_prog[b*16+k] per 64-step chunk.
// Consumer blocks: g = bid-64, r = g/9, s = g%9.
//   s<8 : memory tile  (A = state [65536,128], K=128, tile 128x96)
//   s==8: pooled tile  (A = state_flat [8192,1024], K=1024, tile 128x96)
// ---------------------------------------------------------------------------
#define F_EALO  9216
#define F_EBHI  18432
#define F_EBLO  25344
#define F_EBUF  32256
#define F_TA_B  18432
#define F_BUF_B 64512
#define F_SM    129024

__device__ __forceinline__ void f_stageA(uint32_t sdst, const __nv_bfloat16* __restrict__ g,
                                         long long row0, int k0, int ld, int tid)
{
#pragma unroll
    for (int it = 0; it < 3; it++) {
        int u = it * 384 + tid;
        if (u < 1024) {
            int row = u >> 3, q = u & 7;
            cp16(sdst + row * (LDSK * 2) + q * 16, g + (row0 + row) * (long long)ld + k0 + q * 8);
        }
    }
}
__device__ __forceinline__ void f_stageB(uint32_t sdst, const __nv_bfloat16* __restrict__ g,
                                         int n0, int k0, int ld, int tid)
{
#pragma unroll
    for (int it = 0; it < 2; it++) {
        int u = it * 384 + tid;
        int row = u >> 3, q = u & 7;
        cp16(sdst + row * (LDSK * 2) + q * 16, g + (size_t)(n0 + row) * ld + k0 + q * 8);
    }
}

__device__ __forceinline__ void f_stage_all(uint32_t bufb,
                                            const __nv_bfloat16* Ahi, const __nv_bfloat16* Alo, long long row0, int lda,
                                            const __nv_bfloat16* Bhi, const __nv_bfloat16* Blo, int n0, int ldb,
                                            int k0, int tid)
{
    f_stageA(bufb,              Ahi, row0, k0, lda, tid);
    f_stageA(bufb + F_TA_B,     Alo, row0, k0, lda, tid);
    f_stageB(bufb + F_EBHI * 2, Bhi, n0, k0, ldb, tid);
    f_stageB(bufb + F_EBLO * 2, Blo, n0, k0, ldb, tid);
    CP_COMMIT();
}

__global__ __launch_bounds__(384, 1)
void fused_scan_mem(const float* __restrict__ Q, const float* __restrict__ rw,
                    const float* __restrict__ state0, const float* __restrict__ W_hh,
                    const float* __restrict__ b_ih, const float* __restrict__ b_hh,
                    float* __restrict__ state_out,
                    __nv_bfloat16* __restrict__ sth, __nv_bfloat16* __restrict__ stl,
                    const __nv_bfloat16* __restrict__ Wmh, const __nv_bfloat16* __restrict__ Wml,
                    const float* __restrict__ bm, float* __restrict__ Cmem,
                    const __nv_bfloat16* __restrict__ Mch, const __nv_bfloat16* __restrict__ Mcl,
                    const float* __restrict__ pbias, float* __restrict__ Cpool)
{
    extern __shared__ __align__(16) char smem[];
    const int tid = threadIdx.x;

    if (blockIdx.x < 64) {
        // ================= SCAN ROLE =================
        float* hbuf = reinterpret_cast<float*>(smem);
        float* gh   = hbuf + 128;
        const int b = blockIdx.x >> 3;
        const int e = blockIdx.x & 7;
        const int j = tid;

        unsigned long long w2r[64];
        {
            const unsigned long long* wr = reinterpret_cast<const unsigned long long*>(W_hh + (size_t)j * DSq);
#pragma unroll
            for (int i = 0; i < 64; i++) w2r[i] = wr[i];
        }
        if (j < 32) reinterpret_cast<float4*>(hbuf)[j] = reinterpret_cast<const float4*>(state0 + e * DSq)[j];
        const float bhh = b_hh[j];
        float bir = 0.f, biz = 0.f, bin = 0.f;
        if (j < DSq) { bir = b_ih[j]; biz = b_ih[DSq + j]; bin = b_ih[2 * DSq + j]; }
        __syncthreads();

        const ulonglong2* hs2 = reinterpret_cast<const ulonglong2*>(hbuf);

        float qr = 0.f, qz = 0.f, qn = 0.f, rwv = 0.f;
        if (j < DSq) {
            const float* qp = Q + (size_t)(b * Tq) * (3 * DSq);
            qr = qp[j]; qz = qp[DSq + j]; qn = qp[2 * DSq + j];
            rwv = rw[(size_t)(b * Tq) * NEq + e];
        }

        for (int t = 0; t < Tq; t++) {
            const int row = b * Tq + t;
            float nqr = 0.f, nqz = 0.f, nqn = 0.f, nrw = 0.f;
            if (t + 1 < Tq && j < DSq) {
                const float* qp = Q + (size_t)(row + 1) * (3 * DSq);
                nqr = __ldg(qp + j); nqz = __ldg(qp + DSq + j); nqn = __ldg(qp + 2 * DSq + j);
                nrw = __ldg(rw + (size_t)(row + 1) * NEq + e);
            }
            unsigned long long a0 = 0, a1 = 0, a2 = 0, a3 = 0;
#pragma unroll
            for (int i = 0; i < 32; i += 2) {
                ulonglong2 h0 = hs2[i];
                ulonglong2 h1 = hs2[i + 1];
                a0 = fma_f32x2(w2r[i * 2 + 0], h0.x, a0);
                a1 = fma_f32x2(w2r[i * 2 + 1], h0.y, a1);
                a2 = fma_f32x2(w2r[i * 2 + 2], h1.x, a2);
                a3 = fma_f32x2(w2r[i * 2 + 3], h1.y, a3);
            }
            float acc = ((lo_f(a0) + hi_f(a0)) + (lo_f(a1) + hi_f(a1)))
                      + ((lo_f(a2) + hi_f(a2)) + (lo_f(a3) + hi_f(a3)));
            gh[j] = acc + bhh;
            __syncthreads();
            if (j < DSq) {
                float gir = fmaf(rwv, qr, bir);
                float giz = fmaf(rwv, qz, biz);
                float gin = fmaf(rwv, qn, bin);
                float r = __fdividef(1.f, 1.f + __expf(-(gir + gh[j])));
                float z = __fdividef(1.f, 1.f + __expf(-(giz + gh[DSq + j])));
                float xn = fmaf(r, gh[2 * DSq + j], gin);
                float ex = __expf(-2.f * xn);
                float n = __fdividef(1.f - ex, 1.f + ex);
                float hnew = fmaf(z, hbuf[j] - n, n);
                hbuf[j] = hnew;
                size_t idx = (((size_t)row) * NEq + e) * DSq + j;
                state_out[idx] = hnew;
                __nv_bfloat16 hh = __float2bfloat16(hnew);
                sth[idx] = hh;
                stl[idx] = __float2bfloat16(hnew - __bfloat162float(hh));
            }
            __syncthreads();
            if ((t & 63) == 63 && j == 0) {
                __threadfence();
                atomicAdd(&g_prog[b * 16 + (t >> 6)], 1);
            }
            qr = nqr; qz = nqz; qn = nqn; rwv = nrw;
        }
    } else {
        // ================= CONSUMER GEMM ROLE =================
        __nv_bfloat16* s16 = reinterpret_cast<__nv_bfloat16*>(smem);
        const uint32_t sb = smem_u32(smem);
        const int g = blockIdx.x - 64;
        const int r = g / 9;
        const int s = g - r * 9;

        const __nv_bfloat16 *Ahi, *Alo, *Bhi, *Blo;
        const float* biasv;
        float* Cp;
        long long row0;
        int lda, ldb, n0, nCh, kflag;
        long long crow0;

        if (s < 8) {
            // memory tile: C[65536,768], A=state[65536,128], B=Wm[768,128]
            // 128 rows = 16 timesteps -> needs chunk tb16>>2
            const int b = r & 7, tb16 = r >> 3;
            row0 = (long long)b * 8192 + (long long)tb16 * 128;
            lda = DSq; ldb = DSq; nCh = 2;
            Ahi = sth; Alo = stl; Bhi = Wmh; Blo = Wml;
            n0 = s * 96; biasv = bm; Cp = Cmem;
            crow0 = row0;
            kflag = b * 16 + (tb16 >> 2);
        } else {
            // pooled tile: C[8192,768], A=state_flat[8192,1024], B=Mc[768,1024]
            // 128 t-rows = timesteps [tb16*128, tb16*128+128) -> needs chunk 2*tb16+1
            const int rowtile = r >> 3;            // 0..63, ascending t
            const int tb16 = rowtile >> 3, b = rowtile & 7;
            row0 = (long long)b * 1024 + (long long)tb16 * 128;
            lda = NEq * DSq; ldb = NEq * DSq; nCh = 16;
            Ahi = sth; Alo = stl; Bhi = Mch; Blo = Mcl;
            n0 = (r & 7) * 96; biasv = pbias; Cp = Cpool;
            crow0 = row0;
            kflag = b * 16 + 2 * tb16 + 1;         // FIXED: full 128-step coverage
        }

        if (tid == 0) {
            while (atomicAdd(&g_prog[kflag], 0) < 8) { }
        }
        __syncthreads();
        __threadfence();

        const int wid = tid >> 5;
        const int wy = wid & 3;
        const int wx = wid >> 2;

        wmma::fragment<wmma::accumulator, 16, 16, 16, float> acc[2][2];
#pragma unroll
        for (int i = 0; i < 2; i++)
#pragma unroll
            for (int jj = 0; jj < 2; jj++) wmma::fill_fragment(acc[i][jj], 0.0f);

        f_stage_all(sb, Ahi, Alo, row0, lda, Bhi, Blo, n0, ldb, 0, tid);

        for (int c = 0; c < nCh; c++) {
            if (c + 1 < nCh) {
                f_stage_all(sb + ((c + 1) & 1) * F_BUF_B, Ahi, Alo, row0, lda,
                            Bhi, Blo, n0, ldb, (c + 1) * BKT, tid);
                CP_WAIT1();
            } else {
                CP_WAIT0();
            }
            __syncthreads();
            const __nv_bfloat16* base = s16 + (c & 1) * F_EBUF;
#pragma unroll
            for (int ks = 0; ks < BKT; ks += 16) {
                wmma::fragment<wmma::matrix_b, 16, 16, 16, __nv_bfloat16, wmma::col_major> bh[2], bl[2];
                wmma::fragment<wmma::matrix_a, 16, 16, 16, __nv_bfloat16, wmma::row_major> ah[2], al[2];
#pragma unroll
                for (int fn = 0; fn < 2; fn++) {
                    const int nb = wx * 32 + fn * 16;
                    wmma::load_matrix_sync(bh[fn], base + F_EBHI + nb * LDSK + ks, LDSK);
                    wmma::load_matrix_sync(bl[fn], base + F_EBLO + nb * LDSK + ks, LDSK);
                }
#pragma unroll
                for (int fm = 0; fm < 2; fm++) {
                    const int mb = wy * 32 + fm * 16;
                    wmma::load_matrix_sync(ah[fm], base + mb * LDSK + ks, LDSK);
                    wmma::load_matrix_sync(al[fm], base + F_EALO + mb * LDSK + ks, LDSK);
                }
#pragma unroll
                for (int fm = 0; fm < 2; fm++)
#pragma unroll
                    for (int fn = 0; fn < 2; fn++)
                        wmma::mma_sync(acc[fm][fn], ah[fm], bh[fn], acc[fm][fn]);
#pragma unroll
                for (int fm = 0; fm < 2; fm++)
#pragma unroll
                    for (int fn = 0; fn < 2; fn++)
                        wmma::mma_sync(acc[fm][fn], ah[fm], bl[fn], acc[fm][fn]);
#pragma unroll
                for (int fm = 0; fm < 2; fm++)
#pragma unroll
                    for (int fn = 0; fn < 2; fn++)
                        wmma::mma_sync(acc[fm][fn], al[fm], bh[fn], acc[fm][fn]);
            }
            __syncthreads();
        }

        float* Cs = reinterpret_cast<float*>(smem);
#pragma unroll
        for (int fm = 0; fm < 2; fm++)
#pragma unroll
            for (int fn = 0; fn < 2; fn++)
                wmma::store_matrix_sync(Cs + (wy * 32 + fm * 16) * 96 + wx * 32 + fn * 16,
                                        acc[fm][fn], 96, wmma::mem_row_major);
        __syncthreads();
#pragma unroll
        for (int it = 0; it < 8; it++) {
            int flat = it * 384 + tid;
            int row = flat / 24, q = flat % 24;
            float4 v = *reinterpret_cast<const float4*>(Cs + row * 96 + q * 4);
            const float4 bv = *reinterpret_cast<const float4*>(biasv + n0 + q * 4);
            v.x += bv.x; v.y += bv.y; v.z += bv.z; v.w += bv.w;
            *reinterpret_cast<float4*>(Cp + (size_t)(crow0 + row) * Dq + n0 + q * 4) = v;
        }
    }
}

// ---------------------------------------------------------------------------
// Weight prep (+ progress flag reset each launch)
// ---------------------------------------------------------------------------
__global__ void prep_weights(const float* __restrict__ Wi, const float* __restrict__ W_ih,
                             const float* __restrict__ Wm, const float* __restrict__ Ws,
                             const float* __restrict__ Wh1, const float* __restrict__ Wt1,
                             const float* __restrict__ Wv1,
                             const float* __restrict__ bh1, const float* __restrict__ bt1,
                             const float* __restrict__ bv1,
                             const float* __restrict__ Wh2, const float* __restrict__ Wt2,
                             const float* __restrict__ Wv2)
{
    if (blockIdx.x == 0 && threadIdx.x < 128) g_prog[threadIdx.x] = 0;

    const int N_Wi = DSq * Dq, N_Wih = 3 * DSq * DSq, N_Wm = Dq * DSq;
    const int N_W1 = 256 * DSq;
    const long long N_Ws = (long long)Dq * NEq * Dq;
    long long idx = (long long)blockIdx.x * 256 + threadIdx.x;
    __nv_bfloat16 h, l;
    if (idx < N_Wi)  { hilo(Wi[idx], h, l);   g_Wi_hi[idx] = h;  g_Wi_lo[idx] = l;  return; }
    idx -= N_Wi;
    if (idx < N_Wih) { hilo(W_ih[idx], h, l); g_Wih_hi[idx] = h; g_Wih_lo[idx] = l; return; }
    idx -= N_Wih;
    if (idx < N_Wm)  { hilo(Wm[idx], h, l);   g_Wm_hi[idx] = h;  g_Wm_lo[idx] = l;  return; }
    idx -= N_Wm;
    if (idx < N_Wm) {
        int j = (int)(idx / DSq), k = (int)(idx % DSq);
        hilo(Wm[idx], h, l);
        g_WmT_hi[(size_t)k * Dq + j] = h; g_WmT_lo[(size_t)k * Dq + j] = l; return;
    }
    idx -= N_Wm;
    if (idx < N_W1) {
        int r = (int)(idx / DSq), c = (int)(idx % DSq);
        float v = (r < 64) ? Wh1[r * DSq + c] : (r < 128) ? Wt1[(r - 64) * DSq + c]
                : (r < 192) ? Wv1[(r - 128) * DSq + c] : 0.f;
        hilo(v, h, l); g_W1_hi[idx] = h; g_W1_lo[idx] = l; return;
    }
    idx -= N_W1;
    if (idx < 256) {
        int i = (int)idx;
        g_b1cat[i] = (i < 64) ? bh1[i] : (i < 128) ? bt1[i - 64] : (i < 192) ? bv1[i - 128] : 0.f;
        g_W2cat[i] = (i < 64) ? Wh2[i] : (i < 128) ? Wt2[i - 64] : (i < 192) ? Wv2[i - 128] : 0.f;
        return;
    }
    idx -= 256;
    if (idx < N_Ws) { hilo(Ws[idx], h, l); g_Ws_hi[idx] = h; g_Ws_lo[idx] = l; }
}
#define PREP_TOTAL (DSq*Dq + 3*DSq*DSq + Dq*DSq + Dq*DSq + 256*DSq + 256 + Dq*NEq*Dq)

// ---------------------------------------------------------------------------
// Route softmax + fused h_seq hi/lo conversion
// ---------------------------------------------------------------------------
__global__ __launch_bounds__(256)
void route_cvt(const float* __restrict__ h_seq, const float* __restrict__ ek,
               float* __restrict__ rw,
               __nv_bfloat16* __restrict__ hi, __nv_bfloat16* __restrict__ lo)
{
    const int row = blockIdx.x;
    const int w = threadIdx.x >> 5, lane = threadIdx.x & 31;
    const float* hr = h_seq + (size_t)row * Dq;
    const float* er = ek + (size_t)w * Dq;
    float s = 0.f;
#pragma unroll 4
    for (int k = lane; k < Dq; k += 32) s = fmaf(hr[k], er[k], s);
#pragma unroll
    for (int o = 16; o; o >>= 1) s += __shfl_xor_sync(0xffffffffu, s, o);
    __shared__ float lg[NEq];
    if (lane == 0) lg[w] = s;

#pragma unroll
    for (int i = threadIdx.x; i < Dq; i += 256) {
        __nv_bfloat16 h, l; hilo(hr[i], h, l);
        hi[(size_t)row * Dq + i] = h;
        lo[(size_t)row * Dq + i] = l;
    }
    __syncthreads();
    if (threadIdx.x == 0) {
        const float inv = 0.036084391824351615f;
        float v[NEq], m = -1e30f;
#pragma unroll
        for (int e = 0; e < NEq; e++) { v[e] = lg[e] * inv; m = fmaxf(m, v[e]); }
        float den = 0.f;
#pragma unroll
        for (int e = 0; e < NEq; e++) { v[e] = __expf(v[e] - m); den += v[e]; }
        float id = 1.f / den;
#pragma unroll
        for (int e = 0; e < NEq; e++) rw[(size_t)row * NEq + e] = v[e] * id;
    }
}

__global__ __launch_bounds__(256)
void pbias_kernel(const float* __restrict__ Ws, const float* __restrict__ bm,
                  const float* __restrict__ bs, float* __restrict__ pb)
{
    int d = blockIdx.x, tid = threadIdx.x;
    float s = 0.f;
    for (int j = tid; j < NEq * Dq; j += 256) s = fmaf(bm[j % Dq], Ws[(size_t)d * (NEq * Dq) + j], s);
    __shared__ float red[256];
    red[tid] = s; __syncthreads();
    for (int o = 128; o; o >>= 1) { if (tid < o) red[tid] += red[tid + o]; __syncthreads(); }
    if (tid == 0) pb[d] = red[0] + bs[d];
}

// ---------------------------------------------------------------------------
// Launch
// ---------------------------------------------------------------------------
extern "C" void kernel_launch(void* const* d_in, const int* in_sizes, int n_in,
                              void* d_out, int out_size)
{
    const float* h_seq = (const float*)d_in[0];
    const float* ek    = (const float*)d_in[1];
    const float* state0= (const float*)d_in[2];
    const float* Wi    = (const float*)d_in[3];
    const float* bi    = (const float*)d_in[4];
    const float* W_ih  = (const float*)d_in[5];
    const float* W_hh  = (const float*)d_in[6];
    const float* b_ih  = (const float*)d_in[7];
    const float* b_hh  = (const float*)d_in[8];
    const float* Wm    = (const float*)d_in[9];
    const float* bm    = (const float*)d_in[10];
    const float* Ws    = (const float*)d_in[11];
    const float* bs    = (const float*)d_in[12];
    const float* Wh1   = (const float*)d_in[13];
    const float* bh1   = (const float*)d_in[14];
    const float* Wh2   = (const float*)d_in[15];
    const float* bh2   = (const float*)d_in[16];
    const float* Wt1   = (const float*)d_in[17];
    const float* bt1   = (const float*)d_in[18];
    const float* Wt2   = (const float*)d_in[19];
    const float* bt2   = (const float*)d_in[20];
    const float* Wv1   = (const float*)d_in[21];
    const float* bv1   = (const float*)d_in[22];
    const float* Wv2   = (const float*)d_in[23];
    const float* bv2   = (const float*)d_in[24];
    float* out = (float*)d_out;

    cudaFuncSetAttribute(gemm_tc, cudaFuncAttributeMaxDynamicSharedMemorySize, SM_BYTES);
    cudaFuncSetAttribute(gemm_heads, cudaFuncAttributeMaxDynamicSharedMemorySize, SM_BYTES);
    cudaFuncSetAttribute(fused_scan_mem, cudaFuncAttributeMaxDynamicSharedMemorySize, F_SM);

#define SYMF(p, s) float* p; cudaGetSymbolAddress((void**)&p, s)
#define SYMB(p, s) __nv_bfloat16* p; cudaGetSymbolAddress((void**)&p, s)
    SYMB(p_hsh, g_hseq_hi);  SYMB(p_hsl, g_hseq_lo);
    SYMB(p_sth, g_state_hi); SYMB(p_stl, g_state_lo);
    SYMB(p_prh, g_projh);    SYMB(p_prl, g_projl);
    SYMB(p_wsh, g_Ws_hi);    SYMB(p_wsl, g_Ws_lo);
    SYMB(p_wih, g_Wi_hi);    SYMB(p_wil, g_Wi_lo);
    SYMB(p_whh, g_Wih_hi);   SYMB(p_whl, g_Wih_lo);
    SYMB(p_wmh, g_Wm_hi);    SYMB(p_wml, g_Wm_lo);
    SYMB(p_wth, g_WmT_hi);   SYMB(p_wtl, g_WmT_lo);
    SYMB(p_mch, g_Mc_hi);    SYMB(p_mcl, g_Mc_lo);
    SYMB(p_w1h, g_W1_hi);    SYMB(p_w1l, g_W1_lo);
    SYMF(p_Q, g_Q); SYMF(p_pb, g_pbias);
    SYMF(p_b1, g_b1cat);  SYMF(p_w2, g_W2cat);

    // 1) prep (+flag reset) + route(+cvt)
    prep_weights<<<(PREP_TOTAL + 255) / 256, 256>>>(Wi, W_ih, Wm, Ws, Wh1, Wt1, Wv1,
                                                    bh1, bt1, bv1, Wh2, Wt2, Wv2);
    route_cvt<<<ROWS, 256>>>(h_seq, ek, out + RW_OFF, p_hsh, p_hsl);

    // 2) proj = h_seq @ Wi^T + bi  (bf16 hi/lo only)
    gemm_tc<<<dim3(1, ROWS / 128, 1), 512, SM_BYTES>>>(p_hsh, p_hsl, Dq, 0,
                                                       p_wih, p_wil, Dq,
                                                       nullptr, DSq, 0, bi, Dq / BKT,
                                                       p_prh, p_prl);

    // 3) Q = proj @ W_ih^T
    gemm_tc<<<dim3(3, ROWS / 128, 1), 512, SM_BYTES>>>(p_prh, p_prl, DSq, 0,
                                                       p_whh, p_whl, DSq,
                                                       p_Q, 3 * DSq, 0, nullptr, DSq / BKT,
                                                       nullptr, nullptr);

    // 4) Mc = per-entity Ws_e @ Wm (bf16 hi/lo only) + pbias  (pooled operands)
    gemm_tc<<<dim3(1, Dq / 128, NEq), 512, SM_BYTES>>>(p_wsh, p_wsl, NEq * Dq, Dq,
                                                       p_wth, p_wtl, Dq,
                                                       nullptr, NEq * DSq, DSq, nullptr, Dq / BKT,
                                                       p_mch, p_mcl);
    pbias_kernel<<<Dq, 256>>>(Ws, bm, bs, p_pb);

    // 5) FUSED: scan (64 blocks) + memory & pooled gemm tiles (flag-gated)
    fused_scan_mem<<<64 + 512 * 9, 384, F_SM>>>(p_Q, out + RW_OFF, state0, W_hh, b_ih, b_hh,
                                                out + STATE_OFF, p_sth, p_stl,
                                                p_wmh, p_wml, bm, out + MEM_OFF,
                                                p_mch, p_mcl, p_pb, out + POOLED_OFF);

    // 6) heads fused -> holder/tagged/visible
    gemm_heads<<<dim3(2, SROWS / 128, 1), 512, SM_BYTES>>>(p_sth, p_stl, p_w1h, p_w1l,
                                                           p_b1, p_w2, bh2, bt2, bv2,
                                                           out + HOLDER_OFF, out + TAGGED_OFF, out + VISIBLE_OFF);

    (void)in_sizes; (void)n_in; (void)out_size;
}